// round 3
// baseline (speedup 1.0000x reference)
#include <cuda_runtime.h>
#include <cuda_fp16.h>
#include <cstdint>

// ---------------- problem constants ----------------
#define TT   8192      // tokens (B*S)
#define DD   1024      // model dim
#define II   4096      // ffn dim
#define EE   8         // experts
#define CAPACITY 2560  // int(1.25 * T*TOP_K/E)
#define RR   (EE*CAPACITY)

// ---------------- device scratch (allocation-free rule: __device__ globals) ----------------
__device__ __half g_W1h[(size_t)EE*DD*II];
__device__ __half g_W2h[(size_t)EE*II*DD];
__device__ __half g_fw1h[(size_t)DD*II];
__device__ __half g_fw2h[(size_t)II*DD];
__device__ __half g_Xg [(size_t)RR*DD];
__device__ __half g_Xfb[(size_t)TT*DD];
__device__ __half g_H  [(size_t)RR*II];
__device__ __half g_Hfb[(size_t)TT*II];
__device__ float  g_Ye [(size_t)RR*DD];
__device__ float  g_Yfb[(size_t)TT*DD];
__device__ int    g_top2e[TT*2];
__device__ float  g_top2w[TT*2];
__device__ int    g_slot [TT*2];
__device__ int    g_fbslot[TT];
__device__ int    g_fbidx [TT];
__device__ unsigned char g_fbflag[TT];
__device__ int    g_counts[EE];
__device__ int    g_fbcount;
__device__ int    g_idx[RR];

// ---------------- helpers ----------------
__device__ __forceinline__ float gelu_exact(float v) {
    return 0.5f * v * (1.0f + erff(v * 0.7071067811865475f));
}

__device__ __forceinline__ void cpasync16(uint32_t dst, const void* src) {
    asm volatile("cp.async.cg.shared.global [%0], [%1], 16;\n" :: "r"(dst), "l"(src));
}
__device__ __forceinline__ void cpasync_commit() { asm volatile("cp.async.commit_group;\n"); }
__device__ __forceinline__ void cpasync_waitall() { asm volatile("cp.async.wait_group 0;\n"); }

__device__ __forceinline__ void ldmatrix_x4(uint32_t* r, uint32_t addr) {
    asm volatile("ldmatrix.sync.aligned.m8n8.x4.shared.b16 {%0,%1,%2,%3}, [%4];"
                 : "=r"(r[0]), "=r"(r[1]), "=r"(r[2]), "=r"(r[3]) : "r"(addr));
}
__device__ __forceinline__ void ldmatrix_x4_trans(uint32_t* r, uint32_t addr) {
    asm volatile("ldmatrix.sync.aligned.m8n8.x4.trans.shared.b16 {%0,%1,%2,%3}, [%4];"
                 : "=r"(r[0]), "=r"(r[1]), "=r"(r[2]), "=r"(r[3]) : "r"(addr));
}
__device__ __forceinline__ void mma16816(float* c, const uint32_t* a, const uint32_t* b) {
    asm volatile("mma.sync.aligned.m16n8k16.row.col.f32.f16.f16.f32 "
                 "{%0,%1,%2,%3},{%4,%5,%6,%7},{%8,%9},{%0,%1,%2,%3};"
                 : "+f"(c[0]), "+f"(c[1]), "+f"(c[2]), "+f"(c[3])
                 : "r"(a[0]), "r"(a[1]), "r"(a[2]), "r"(a[3]), "r"(b[0]), "r"(b[1]));
}

// ---------------- fp32 -> fp16 convert ----------------
__global__ void convert_kernel(const float* __restrict__ src, __half* __restrict__ dst, int n4) {
    int i = blockIdx.x * blockDim.x + threadIdx.x;
    if (i < n4) {
        float4 v = reinterpret_cast<const float4*>(src)[i];
        reinterpret_cast<__half2*>(dst)[2*i]   = __floats2half2_rn(v.x, v.y);
        reinterpret_cast<__half2*>(dst)[2*i+1] = __floats2half2_rn(v.z, v.w);
    }
}

// ---------------- router: logits -> softmax -> top2 -> normalized weights ----------------
__global__ void router_kernel(const float* __restrict__ x, const float* __restrict__ Wr) {
    __shared__ float sWr[EE*DD];  // 32KB
    int tid = threadIdx.x;
    for (int i = tid; i < EE*DD; i += 256) sWr[i] = Wr[i];
    __syncthreads();
    int w = tid >> 5, lane = tid & 31;
    int t = blockIdx.x * 8 + w;
    const float* xr = x + (size_t)t * DD;
    float acc[EE];
    #pragma unroll
    for (int e = 0; e < EE; e++) acc[e] = 0.f;
    for (int d = lane; d < DD; d += 32) {
        float xv = xr[d];
        #pragma unroll
        for (int e = 0; e < EE; e++) acc[e] += xv * sWr[e*DD + d];
    }
    #pragma unroll
    for (int e = 0; e < EE; e++)
        #pragma unroll
        for (int o = 16; o > 0; o >>= 1) acc[e] += __shfl_xor_sync(0xffffffffu, acc[e], o);
    if (lane == 0) {
        float m = acc[0];
        #pragma unroll
        for (int e = 1; e < EE; e++) m = fmaxf(m, acc[e]);
        float p[EE], s = 0.f;
        #pragma unroll
        for (int e = 0; e < EE; e++) { p[e] = expf(acc[e] - m); s += p[e]; }
        #pragma unroll
        for (int e = 0; e < EE; e++) p[e] /= s;
        int i1 = 0;
        #pragma unroll
        for (int e = 1; e < EE; e++) if (p[e] > p[i1]) i1 = e;
        int i2 = -1;
        #pragma unroll
        for (int e = 0; e < EE; e++) if (e != i1 && (i2 < 0 || p[e] > p[i2])) i2 = e;
        float ssum = p[i1] + p[i2];
        if (ssum < 1e-9f) ssum = 1e-9f;
        g_top2e[2*t] = i1; g_top2e[2*t+1] = i2;
        g_top2w[2*t] = p[i1] / ssum; g_top2w[2*t+1] = p[i2] / ssum;
    }
}

// ---------------- sequential capacity assignment (exact reference semantics) ----------------
// 1024 threads, each owns 8 consecutive tokens; per-expert block-wide exclusive scan
// reproduces the reference's cumsum-ordered slot assignment and overflow -> fallback.
__global__ void assign_kernel() {
    int tid = threadIdx.x, lane = tid & 31, wid = tid >> 5;
    __shared__ int wsum[32];
    int e0[8], e1[8];
    bool fb[8];
    #pragma unroll
    for (int i = 0; i < 8; i++) {
        int t = tid * 8 + i;
        e0[i] = g_top2e[2*t]; e1[i] = g_top2e[2*t+1];
        fb[i] = false;
    }
    for (int e = 0; e < EE; e++) {
        bool elig[8]; int cnt = 0;
        #pragma unroll
        for (int i = 0; i < 8; i++) {
            elig[i] = (!fb[i]) && (e0[i] == e || e1[i] == e);
            cnt += elig[i] ? 1 : 0;
        }
        // block-wide inclusive scan of per-thread counts
        int inc = cnt;
        #pragma unroll
        for (int o = 1; o < 32; o <<= 1) { int v = __shfl_up_sync(0xffffffffu, inc, o); if (lane >= o) inc += v; }
        if (lane == 31) wsum[wid] = inc;
        __syncthreads();
        if (wid == 0) {
            int v = wsum[lane];
            int inc2 = v;
            #pragma unroll
            for (int o = 1; o < 32; o <<= 1) { int u = __shfl_up_sync(0xffffffffu, inc2, o); if (lane >= o) inc2 += u; }
            wsum[lane] = inc2;
        }
        __syncthreads();
        int pos = inc - cnt + (wid ? wsum[wid-1] : 0);   // exclusive prefix for this thread
        int total = wsum[31];
        if (tid == 0) g_counts[e] = (total < CAPACITY) ? total : CAPACITY;
        #pragma unroll
        for (int i = 0; i < 8; i++) {
            if (elig[i]) {
                int t = tid * 8 + i;
                if (pos < CAPACITY) {
                    int k = (e0[i] == e) ? 0 : 1;
                    g_slot[2*t + k] = pos;
                    g_idx[e*CAPACITY + pos] = t;
                } else {
                    fb[i] = true;
                }
                pos++;
            }
        }
        __syncthreads();   // protect wsum reuse next iteration
    }
    // fallback compaction
    int cnt = 0;
    #pragma unroll
    for (int i = 0; i < 8; i++) cnt += fb[i] ? 1 : 0;
    int inc = cnt;
    #pragma unroll
    for (int o = 1; o < 32; o <<= 1) { int v = __shfl_up_sync(0xffffffffu, inc, o); if (lane >= o) inc += v; }
    if (lane == 31) wsum[wid] = inc;
    __syncthreads();
    if (wid == 0) {
        int v = wsum[lane];
        int inc2 = v;
        #pragma unroll
        for (int o = 1; o < 32; o <<= 1) { int u = __shfl_up_sync(0xffffffffu, inc2, o); if (lane >= o) inc2 += u; }
        wsum[lane] = inc2;
    }
    __syncthreads();
    int pos = inc - cnt + (wid ? wsum[wid-1] : 0);
    #pragma unroll
    for (int i = 0; i < 8; i++) {
        int t = tid * 8 + i;
        g_fbflag[t] = fb[i] ? 1 : 0;
        if (fb[i]) { g_fbidx[pos] = t; g_fbslot[t] = pos; pos++; }
    }
    if (tid == 0) g_fbcount = wsum[31];
}

// ---------------- gathers (fp32 -> fp16 row copies) ----------------
__global__ void gather_expert(const float* __restrict__ x) {
    int r = blockIdx.x;
    int e = r / CAPACITY;
    if (r - e*CAPACITY >= g_counts[e]) return;
    int t = g_idx[r];
    const float4* src = reinterpret_cast<const float4*>(x + (size_t)t * DD);
    __half2* dst = reinterpret_cast<__half2*>(g_Xg + (size_t)r * DD);
    int i = threadIdx.x; // 256 threads * 4 floats = 1024
    float4 v = src[i];
    dst[2*i]   = __floats2half2_rn(v.x, v.y);
    dst[2*i+1] = __floats2half2_rn(v.z, v.w);
}

__global__ void gather_fb(const float* __restrict__ x) {
    int r = blockIdx.x;
    if (r >= g_fbcount) return;
    int t = g_fbidx[r];
    const float4* src = reinterpret_cast<const float4*>(x + (size_t)t * DD);
    __half2* dst = reinterpret_cast<__half2*>(g_Xfb + (size_t)r * DD);
    int i = threadIdx.x;
    float4 v = src[i];
    dst[2*i]   = __floats2half2_rn(v.x, v.y);
    dst[2*i+1] = __floats2half2_rn(v.z, v.w);
}

// ---------------- tensor-core GEMM ----------------
// MODE: 0 = gemm1 expert (Xg @ W1 -> gelu -> H, fp16 out)
//       1 = gemm1 fb     (Xfb @ fw1 -> gelu -> Hfb)
//       2 = gemm2 expert (H @ W2 + b2 -> Ye, fp32 out)
//       3 = gemm2 fb     (Hfb @ fw2 + fb2 -> Yfb)
#define BM 128
#define BN 128
#define BKH 64

template<int MODE>
__global__ void gemm_kernel(const float* __restrict__ bias) {
    constexpr bool G1 = (MODE < 2);
    constexpr bool FB = (MODE & 1);
    constexpr int K = G1 ? DD : II;
    constexpr int N = G1 ? II : DD;
    constexpr int KT = K / BKH;

    const int e = blockIdx.z;
    const int count = FB ? g_fbcount : g_counts[e];
    const int m0 = blockIdx.y * BM;
    if (m0 >= count) return;
    const int n0 = blockIdx.x * BN;

    const __half* __restrict__ Aexp;
    const __half* __restrict__ Bexp;
    if constexpr (MODE == 0) { Aexp = g_Xg  + (size_t)e*CAPACITY*K; Bexp = g_W1h + (size_t)e*K*II; }
    if constexpr (MODE == 1) { Aexp = g_Xfb;                        Bexp = g_fw1h; }
    if constexpr (MODE == 2) { Aexp = g_H   + (size_t)e*CAPACITY*K; Bexp = g_W2h + (size_t)e*K*DD; }
    if constexpr (MODE == 3) { Aexp = g_Hfb;                        Bexp = g_fw2h; }
    const float* biasp = bias + (FB ? 0 : (size_t)e*N);

    extern __shared__ __half smem[];
    const uint32_t sbase = (uint32_t)__cvta_generic_to_shared(smem);
    const int tid = threadIdx.x, lane = tid & 31, wid = tid >> 5;
    const int wm = wid & 1, wn = wid >> 1;
    const int g = lane >> 3, rin = lane & 7;

    float acc[4][4][4];
    #pragma unroll
    for (int a = 0; a < 4; a++)
        #pragma unroll
        for (int b = 0; b < 4; b++)
            #pragma unroll
            for (int c = 0; c < 4; c++) acc[a][b][c] = 0.f;

    auto loadStage = [&](int kt, int st) {
        uint32_t aB = sbase + st * 32768;
        uint32_t bB = aB + 16384;
        // A tile: 128 rows x 64 cols fp16. 8 chunks of 8 halves per row.
        #pragma unroll
        for (int j = 0; j < 4; j++) {
            int id = j * 256 + tid;
            int r = id >> 3, c = id & 7;
            const __half* src = Aexp + (size_t)(m0 + r) * K + kt * BKH + c * 8;
            uint32_t dst = aB + (uint32_t)(r * 64 + ((c ^ (r & 7)) << 3)) * 2;
            cpasync16(dst, src);
        }
        // B tile: 64 rows x 128 cols fp16. 16 chunks of 8 halves per row.
        #pragma unroll
        for (int j = 0; j < 4; j++) {
            int id = j * 256 + tid;
            int r = id >> 4, c = id & 15;
            const __half* src = Bexp + (size_t)(kt * BKH + r) * N + n0 + c * 8;
            uint32_t dst = bB + (uint32_t)(r * 128 + (((c & 8) | ((c ^ r) & 7)) << 3)) * 2;
            cpasync16(dst, src);
        }
        cpasync_commit();
    };

    loadStage(0, 0);
    #pragma unroll 1
    for (int kt = 0; kt < KT; kt++) {
        cpasync_waitall();
        __syncthreads();
        if (kt + 1 < KT) loadStage(kt + 1, (kt + 1) & 1);
        const int st = kt & 1;
        uint32_t aB = sbase + st * 32768;
        uint32_t bB = aB + 16384;
        #pragma unroll
        for (int ks = 0; ks < 4; ks++) {
            uint32_t afr[4][4];
            #pragma unroll
            for (int mt = 0; mt < 4; mt++) {
                int row = wm * 64 + mt * 16 + (g & 1) * 8 + rin;
                int ch = (ks * 2 + (g >> 1)) ^ rin;
                ldmatrix_x4(afr[mt], aB + (uint32_t)(row * 64 + ch * 8) * 2);
            }
            uint32_t bfr[4][2];
            #pragma unroll
            for (int ht = 0; ht < 2; ht++) {
                int row = ks * 16 + (g & 1) * 8 + rin;
                int c = wn * 4 + ht * 2 + (g >> 1);
                int ph = (c & 8) | ((c & 7) ^ rin);
                uint32_t r4[4];
                ldmatrix_x4_trans(r4, bB + (uint32_t)(row * 128 + ph * 8) * 2);
                bfr[ht*2][0] = r4[0]; bfr[ht*2][1] = r4[1];
                bfr[ht*2+1][0] = r4[2]; bfr[ht*2+1][1] = r4[3];
            }
            #pragma unroll
            for (int mt = 0; mt < 4; mt++)
                #pragma unroll
                for (int nt = 0; nt < 4; nt++)
                    mma16816(acc[mt][nt], afr[mt], bfr[nt]);
        }
        __syncthreads();
    }

    // epilogue
    const int growb = m0 + wm * 64;
    const int gcolb = n0 + wn * 32;
    #pragma unroll
    for (int mt = 0; mt < 4; mt++) {
        #pragma unroll
        for (int nt = 0; nt < 4; nt++) {
            int r0 = growb + mt * 16 + (lane >> 2);
            int c0 = gcolb + nt * 8 + (lane & 3) * 2;
            float b0f = biasp[c0], b1f = biasp[c0 + 1];
            float x0 = acc[mt][nt][0] + b0f, x1 = acc[mt][nt][1] + b1f;
            float x2 = acc[mt][nt][2] + b0f, x3 = acc[mt][nt][3] + b1f;
            if constexpr (G1) {
                __half* Hout = FB ? g_Hfb : (g_H + (size_t)e*CAPACITY*N);
                float v0 = gelu_exact(x0), v1 = gelu_exact(x1);
                float v2 = gelu_exact(x2), v3 = gelu_exact(x3);
                *reinterpret_cast<__half2*>(Hout + (size_t)r0 * N + c0)       = __floats2half2_rn(v0, v1);
                *reinterpret_cast<__half2*>(Hout + (size_t)(r0 + 8) * N + c0) = __floats2half2_rn(v2, v3);
            } else {
                float* Yout = FB ? g_Yfb : (g_Ye + (size_t)e*CAPACITY*N);
                float2 lo; lo.x = x0; lo.y = x1;
                float2 hi; hi.x = x2; hi.y = x3;
                *reinterpret_cast<float2*>(Yout + (size_t)r0 * N + c0)       = lo;
                *reinterpret_cast<float2*>(Yout + (size_t)(r0 + 8) * N + c0) = hi;
            }
        }
    }
}

// ---------------- final combine ----------------
__global__ void combine_kernel(float* __restrict__ out) {
    int t = blockIdx.x;
    int i = threadIdx.x; // 256 threads * float4
    float4* o = reinterpret_cast<float4*>(out + (size_t)t * DD);
    if (g_fbflag[t]) {
        const float4* src = reinterpret_cast<const float4*>(g_Yfb + (size_t)g_fbslot[t] * DD);
        o[i] = src[i];
    } else {
        int e0 = g_top2e[2*t], e1 = g_top2e[2*t+1];
        float w0 = g_top2w[2*t], w1 = g_top2w[2*t+1];
        size_t r0 = (size_t)(e0 * CAPACITY + g_slot[2*t]) * DD;
        size_t r1 = (size_t)(e1 * CAPACITY + g_slot[2*t+1]) * DD;
        float4 a = reinterpret_cast<const float4*>(g_Ye + r0)[i];
        float4 b = reinterpret_cast<const float4*>(g_Ye + r1)[i];
        float4 v;
        v.x = w0 * a.x + w1 * b.x;
        v.y = w0 * a.y + w1 * b.y;
        v.z = w0 * a.z + w1 * b.z;
        v.w = w0 * a.w + w1 * b.w;
        o[i] = v;
    }
}

// ---------------- launch ----------------
extern "C" void kernel_launch(void* const* d_in, const int* in_sizes, int n_in,
                              void* d_out, int out_size) {
    const float* x   = (const float*)d_in[0];
    const float* Wr  = (const float*)d_in[1];
    const float* W1  = (const float*)d_in[2];
    const float* b1  = (const float*)d_in[3];
    const float* W2  = (const float*)d_in[4];
    const float* b2  = (const float*)d_in[5];
    const float* fw1 = (const float*)d_in[6];
    const float* fb1 = (const float*)d_in[7];
    const float* fw2 = (const float*)d_in[8];
    const float* fb2 = (const float*)d_in[9];
    float* out = (float*)d_out;

    cudaFuncSetAttribute(gemm_kernel<0>, cudaFuncAttributeMaxDynamicSharedMemorySize, 65536);
    cudaFuncSetAttribute(gemm_kernel<1>, cudaFuncAttributeMaxDynamicSharedMemorySize, 65536);
    cudaFuncSetAttribute(gemm_kernel<2>, cudaFuncAttributeMaxDynamicSharedMemorySize, 65536);
    cudaFuncSetAttribute(gemm_kernel<3>, cudaFuncAttributeMaxDynamicSharedMemorySize, 65536);

    // weight conversions (fp32 -> fp16), every call (determinism)
    __half* dW1h;  cudaGetSymbolAddress((void**)&dW1h,  g_W1h);
    __half* dW2h;  cudaGetSymbolAddress((void**)&dW2h,  g_W2h);
    __half* dfw1h; cudaGetSymbolAddress((void**)&dfw1h, g_fw1h);
    __half* dfw2h; cudaGetSymbolAddress((void**)&dfw2h, g_fw2h);
    convert_kernel<<<(EE*DD*II/4 + 255)/256, 256>>>(W1,  dW1h,  EE*DD*II/4);
    convert_kernel<<<(EE*II*DD/4 + 255)/256, 256>>>(W2,  dW2h,  EE*II*DD/4);
    convert_kernel<<<(DD*II/4   + 255)/256, 256>>>(fw1, dfw1h, DD*II/4);
    convert_kernel<<<(II*DD/4   + 255)/256, 256>>>(fw2, dfw2h, II*DD/4);

    router_kernel<<<TT/8, 256>>>(x, Wr);
    assign_kernel<<<1, 1024>>>();
    gather_expert<<<RR, 256>>>(x);
    gather_fb<<<TT, 256>>>(x);

    gemm_kernel<0><<<dim3(II/BN, CAPACITY/BM, EE), 256, 65536>>>(b1);
    gemm_kernel<1><<<dim3(II/BN, TT/BM, 1),        256, 65536>>>(fb1);
    gemm_kernel<2><<<dim3(DD/BN, CAPACITY/BM, EE), 256, 65536>>>(b2);
    gemm_kernel<3><<<dim3(DD/BN, TT/BM, 1),        256, 65536>>>(fb2);

    combine_kernel<<<TT, 256>>>(out);
}

// round 4
// speedup vs baseline: 1.0256x; 1.0256x over previous
#include <cuda_runtime.h>
#include <cuda_fp16.h>
#include <cstdint>

// ---------------- problem constants ----------------
#define TT   8192      // tokens (B*S)
#define DD   1024      // model dim
#define II   4096      // ffn dim
#define EE   8         // experts
#define CAPACITY 2560  // int(1.25 * T*TOP_K/E)
#define RR   (EE*CAPACITY)

// ---------------- device scratch ----------------
__device__ __half g_W1h[(size_t)EE*DD*II];
__device__ __half g_W2h[(size_t)EE*II*DD];
__device__ __half g_fw1h[(size_t)DD*II];
__device__ __half g_fw2h[(size_t)II*DD];
__device__ __half g_Xg [(size_t)RR*DD];
__device__ __half g_Xfb[(size_t)TT*DD];
__device__ __half g_H  [(size_t)RR*II];
__device__ __half g_Hfb[(size_t)TT*II];
__device__ float  g_Ye [(size_t)RR*DD];
__device__ float  g_Yfb[(size_t)TT*DD];
__device__ int    g_top2e[TT*2];
__device__ float  g_top2w[TT*2];
__device__ int    g_slot [TT*2];
__device__ int    g_fbslot[TT];
__device__ int    g_fbidx [TT];
__device__ unsigned char g_fbflag[TT];
__device__ int    g_counts[EE];
__device__ int    g_fbcount;
__device__ int    g_idx[RR];

// ---------------- helpers ----------------
__device__ __forceinline__ float gelu_exact(float v) {
    return 0.5f * v * (1.0f + erff(v * 0.7071067811865475f));
}
__device__ __forceinline__ void cpasync16(uint32_t dst, const void* src) {
    asm volatile("cp.async.cg.shared.global [%0], [%1], 16;\n" :: "r"(dst), "l"(src));
}
__device__ __forceinline__ void cpasync_commit() { asm volatile("cp.async.commit_group;\n"); }
__device__ __forceinline__ void cpasync_wait1()  { asm volatile("cp.async.wait_group 1;\n"); }

__device__ __forceinline__ void ldmatrix_x4(uint32_t* r, uint32_t addr) {
    asm volatile("ldmatrix.sync.aligned.m8n8.x4.shared.b16 {%0,%1,%2,%3}, [%4];"
                 : "=r"(r[0]), "=r"(r[1]), "=r"(r[2]), "=r"(r[3]) : "r"(addr));
}
__device__ __forceinline__ void ldmatrix_x4_trans(uint32_t* r, uint32_t addr) {
    asm volatile("ldmatrix.sync.aligned.m8n8.x4.trans.shared.b16 {%0,%1,%2,%3}, [%4];"
                 : "=r"(r[0]), "=r"(r[1]), "=r"(r[2]), "=r"(r[3]) : "r"(addr));
}
__device__ __forceinline__ void mma16816(float* c, const uint32_t* a, const uint32_t* b) {
    asm volatile("mma.sync.aligned.m16n8k16.row.col.f32.f16.f16.f32 "
                 "{%0,%1,%2,%3},{%4,%5,%6,%7},{%8,%9},{%0,%1,%2,%3};"
                 : "+f"(c[0]), "+f"(c[1]), "+f"(c[2]), "+f"(c[3])
                 : "r"(a[0]), "r"(a[1]), "r"(a[2]), "r"(a[3]), "r"(b[0]), "r"(b[1]));
}

// ---------------- fp32 -> fp16 convert (8 floats/thread, 16B store) ----------------
__global__ void convert_kernel(const float* __restrict__ src, __half* __restrict__ dst, int n8) {
    int i = blockIdx.x * blockDim.x + threadIdx.x;
    if (i < n8) {
        float4 a = reinterpret_cast<const float4*>(src)[2*i];
        float4 b = reinterpret_cast<const float4*>(src)[2*i+1];
        union { __half2 h[4]; uint4 u; } o;
        o.h[0] = __floats2half2_rn(a.x, a.y);
        o.h[1] = __floats2half2_rn(a.z, a.w);
        o.h[2] = __floats2half2_rn(b.x, b.y);
        o.h[3] = __floats2half2_rn(b.z, b.w);
        reinterpret_cast<uint4*>(dst)[i] = o.u;
    }
}

// ---------------- router ----------------
__global__ void router_kernel(const float* __restrict__ x, const float* __restrict__ Wr) {
    __shared__ float sWr[EE*DD];
    int tid = threadIdx.x;
    for (int i = tid; i < EE*DD; i += 256) sWr[i] = Wr[i];
    __syncthreads();
    int w = tid >> 5, lane = tid & 31;
    int t = blockIdx.x * 8 + w;
    const float* xr = x + (size_t)t * DD;
    float acc[EE];
    #pragma unroll
    for (int e = 0; e < EE; e++) acc[e] = 0.f;
    for (int d = lane; d < DD; d += 32) {
        float xv = xr[d];
        #pragma unroll
        for (int e = 0; e < EE; e++) acc[e] += xv * sWr[e*DD + d];
    }
    #pragma unroll
    for (int e = 0; e < EE; e++)
        #pragma unroll
        for (int o = 16; o > 0; o >>= 1) acc[e] += __shfl_xor_sync(0xffffffffu, acc[e], o);
    if (lane == 0) {
        float m = acc[0];
        #pragma unroll
        for (int e = 1; e < EE; e++) m = fmaxf(m, acc[e]);
        float p[EE], s = 0.f;
        #pragma unroll
        for (int e = 0; e < EE; e++) { p[e] = expf(acc[e] - m); s += p[e]; }
        #pragma unroll
        for (int e = 0; e < EE; e++) p[e] /= s;
        int i1 = 0;
        #pragma unroll
        for (int e = 1; e < EE; e++) if (p[e] > p[i1]) i1 = e;
        int i2 = -1;
        #pragma unroll
        for (int e = 0; e < EE; e++) if (e != i1 && (i2 < 0 || p[e] > p[i2])) i2 = e;
        float ssum = p[i1] + p[i2];
        if (ssum < 1e-9f) ssum = 1e-9f;
        g_top2e[2*t] = i1; g_top2e[2*t+1] = i2;
        g_top2w[2*t] = p[i1] / ssum; g_top2w[2*t+1] = p[i2] / ssum;
    }
}

// ---------------- sequential capacity assignment ----------------
__global__ void assign_kernel() {
    int tid = threadIdx.x, lane = tid & 31, wid = tid >> 5;
    __shared__ int wsum[32];
    int e0[8], e1[8];
    bool fb[8];
    #pragma unroll
    for (int i = 0; i < 8; i++) {
        int t = tid * 8 + i;
        e0[i] = g_top2e[2*t]; e1[i] = g_top2e[2*t+1];
        fb[i] = false;
    }
    for (int e = 0; e < EE; e++) {
        bool elig[8]; int cnt = 0;
        #pragma unroll
        for (int i = 0; i < 8; i++) {
            elig[i] = (!fb[i]) && (e0[i] == e || e1[i] == e);
            cnt += elig[i] ? 1 : 0;
        }
        int inc = cnt;
        #pragma unroll
        for (int o = 1; o < 32; o <<= 1) { int v = __shfl_up_sync(0xffffffffu, inc, o); if (lane >= o) inc += v; }
        if (lane == 31) wsum[wid] = inc;
        __syncthreads();
        if (wid == 0) {
            int v = wsum[lane];
            int inc2 = v;
            #pragma unroll
            for (int o = 1; o < 32; o <<= 1) { int u = __shfl_up_sync(0xffffffffu, inc2, o); if (lane >= o) inc2 += u; }
            wsum[lane] = inc2;
        }
        __syncthreads();
        int pos = inc - cnt + (wid ? wsum[wid-1] : 0);
        int total = wsum[31];
        if (tid == 0) g_counts[e] = (total < CAPACITY) ? total : CAPACITY;
        #pragma unroll
        for (int i = 0; i < 8; i++) {
            if (elig[i]) {
                int t = tid * 8 + i;
                if (pos < CAPACITY) {
                    int k = (e0[i] == e) ? 0 : 1;
                    g_slot[2*t + k] = pos;
                    g_idx[e*CAPACITY + pos] = t;
                } else {
                    fb[i] = true;
                }
                pos++;
            }
        }
        __syncthreads();
    }
    int cnt = 0;
    #pragma unroll
    for (int i = 0; i < 8; i++) cnt += fb[i] ? 1 : 0;
    int inc = cnt;
    #pragma unroll
    for (int o = 1; o < 32; o <<= 1) { int v = __shfl_up_sync(0xffffffffu, inc, o); if (lane >= o) inc += v; }
    if (lane == 31) wsum[wid] = inc;
    __syncthreads();
    if (wid == 0) {
        int v = wsum[lane];
        int inc2 = v;
        #pragma unroll
        for (int o = 1; o < 32; o <<= 1) { int u = __shfl_up_sync(0xffffffffu, inc2, o); if (lane >= o) inc2 += u; }
        wsum[lane] = inc2;
    }
    __syncthreads();
    int pos = inc - cnt + (wid ? wsum[wid-1] : 0);
    #pragma unroll
    for (int i = 0; i < 8; i++) {
        int t = tid * 8 + i;
        g_fbflag[t] = fb[i] ? 1 : 0;
        if (fb[i]) { g_fbidx[pos] = t; g_fbslot[t] = pos; pos++; }
    }
    if (tid == 0) g_fbcount = wsum[31];
}

// ---------------- fused gather (expert rows + fallback rows) ----------------
__global__ void gather_all(const float* __restrict__ x) {
    int r = blockIdx.x;
    int t;
    __half* dstrow;
    if (r < RR) {
        int e = r / CAPACITY;
        if (r - e*CAPACITY >= g_counts[e]) return;
        t = g_idx[r];
        dstrow = g_Xg + (size_t)r * DD;
    } else {
        int rr = r - RR;
        if (rr >= g_fbcount) return;
        t = g_fbidx[rr];
        dstrow = g_Xfb + (size_t)rr * DD;
    }
    const float4* src = reinterpret_cast<const float4*>(x + (size_t)t * DD);
    __half2* dst = reinterpret_cast<__half2*>(dstrow);
    int i = threadIdx.x;
    float4 v = src[i];
    dst[2*i]   = __floats2half2_rn(v.x, v.y);
    dst[2*i+1] = __floats2half2_rn(v.z, v.w);
}

// ---------------- tensor-core GEMM, 3-stage cp.async pipeline ----------------
#define BM 128
#define BN 128
#define BKH 64
#define STAGE_BYTES 32768

template<int MODE>
__global__ void gemm_kernel(const float* __restrict__ bias) {
    constexpr bool G1 = (MODE < 2);
    constexpr bool FB = (MODE & 1);
    constexpr int K = G1 ? DD : II;
    constexpr int N = G1 ? II : DD;
    constexpr int KT = K / BKH;

    const int e = blockIdx.z;
    const int count = FB ? g_fbcount : g_counts[e];
    const int m0 = blockIdx.y * BM;
    if (m0 >= count) return;
    const int n0 = blockIdx.x * BN;

    const __half* __restrict__ Aexp;
    const __half* __restrict__ Bexp;
    if constexpr (MODE == 0) { Aexp = g_Xg  + (size_t)e*CAPACITY*K; Bexp = g_W1h + (size_t)e*K*II; }
    if constexpr (MODE == 1) { Aexp = g_Xfb;                        Bexp = g_fw1h; }
    if constexpr (MODE == 2) { Aexp = g_H   + (size_t)e*CAPACITY*K; Bexp = g_W2h + (size_t)e*K*DD; }
    if constexpr (MODE == 3) { Aexp = g_Hfb;                        Bexp = g_fw2h; }
    const float* biasp = bias + (FB ? 0 : (size_t)e*N);

    extern __shared__ __half smem[];
    const uint32_t sbase = (uint32_t)__cvta_generic_to_shared(smem);
    const int tid = threadIdx.x, lane = tid & 31, wid = tid >> 5;
    const int wm = wid & 1, wn = wid >> 1;
    const int g = lane >> 3, rin = lane & 7;

    float acc[4][4][4];
    #pragma unroll
    for (int a = 0; a < 4; a++)
        #pragma unroll
        for (int b = 0; b < 4; b++)
            #pragma unroll
            for (int c = 0; c < 4; c++) acc[a][b][c] = 0.f;

    // load k-tile kt into stage st; always commits a (possibly empty) group
    auto loadStage = [&](int kt, int st) {
        if (kt < KT) {
            uint32_t aB = sbase + st * STAGE_BYTES;
            uint32_t bB = aB + 16384;
            #pragma unroll
            for (int j = 0; j < 4; j++) {
                int id = j * 256 + tid;
                int r = id >> 3, c = id & 7;
                const __half* src = Aexp + (size_t)(m0 + r) * K + kt * BKH + c * 8;
                uint32_t dst = aB + (uint32_t)(r * 64 + ((c ^ (r & 7)) << 3)) * 2;
                cpasync16(dst, src);
            }
            #pragma unroll
            for (int j = 0; j < 4; j++) {
                int id = j * 256 + tid;
                int r = id >> 4, c = id & 15;
                const __half* src = Bexp + (size_t)(kt * BKH + r) * N + n0 + c * 8;
                uint32_t dst = bB + (uint32_t)(r * 128 + (((c & 8) | ((c ^ r) & 7)) << 3)) * 2;
                cpasync16(dst, src);
            }
        }
        cpasync_commit();
    };

    loadStage(0, 0);
    loadStage(1, 1);
    int st = 0;
    #pragma unroll 1
    for (int kt = 0; kt < KT; kt++) {
        cpasync_wait1();        // group kt complete (<=1 outstanding)
        __syncthreads();
        loadStage(kt + 2, (st + 2) % 3);
        uint32_t aB = sbase + st * STAGE_BYTES;
        uint32_t bB = aB + 16384;
        #pragma unroll
        for (int ks = 0; ks < 4; ks++) {
            uint32_t afr[4][4];
            #pragma unroll
            for (int mt = 0; mt < 4; mt++) {
                int row = wm * 64 + mt * 16 + (g & 1) * 8 + rin;
                int ch = (ks * 2 + (g >> 1)) ^ rin;
                ldmatrix_x4(afr[mt], aB + (uint32_t)(row * 64 + ch * 8) * 2);
            }
            uint32_t bfr[4][2];
            #pragma unroll
            for (int ht = 0; ht < 2; ht++) {
                int row = ks * 16 + (g & 1) * 8 + rin;
                int c = wn * 4 + ht * 2 + (g >> 1);
                int ph = (c & 8) | ((c & 7) ^ rin);
                uint32_t r4[4];
                ldmatrix_x4_trans(r4, bB + (uint32_t)(row * 128 + ph * 8) * 2);
                bfr[ht*2][0] = r4[0]; bfr[ht*2][1] = r4[1];
                bfr[ht*2+1][0] = r4[2]; bfr[ht*2+1][1] = r4[3];
            }
            #pragma unroll
            for (int mt = 0; mt < 4; mt++)
                #pragma unroll
                for (int nt = 0; nt < 4; nt++)
                    mma16816(acc[mt][nt], afr[mt], bfr[nt]);
        }
        st = (st + 1) % 3;
    }

    // epilogue
    const int growb = m0 + wm * 64;
    const int gcolb = n0 + wn * 32;
    #pragma unroll
    for (int mt = 0; mt < 4; mt++) {
        #pragma unroll
        for (int nt = 0; nt < 4; nt++) {
            int r0 = growb + mt * 16 + (lane >> 2);
            int c0 = gcolb + nt * 8 + (lane & 3) * 2;
            float b0f = biasp[c0], b1f = biasp[c0 + 1];
            float x0 = acc[mt][nt][0] + b0f, x1 = acc[mt][nt][1] + b1f;
            float x2 = acc[mt][nt][2] + b0f, x3 = acc[mt][nt][3] + b1f;
            if constexpr (G1) {
                __half* Hout = FB ? g_Hfb : (g_H + (size_t)e*CAPACITY*N);
                float v0 = gelu_exact(x0), v1 = gelu_exact(x1);
                float v2 = gelu_exact(x2), v3 = gelu_exact(x3);
                *reinterpret_cast<__half2*>(Hout + (size_t)r0 * N + c0)       = __floats2half2_rn(v0, v1);
                *reinterpret_cast<__half2*>(Hout + (size_t)(r0 + 8) * N + c0) = __floats2half2_rn(v2, v3);
            } else {
                float* Yout = FB ? g_Yfb : (g_Ye + (size_t)e*CAPACITY*N);
                float2 lo; lo.x = x0; lo.y = x1;
                float2 hi; hi.x = x2; hi.y = x3;
                *reinterpret_cast<float2*>(Yout + (size_t)r0 * N + c0)       = lo;
                *reinterpret_cast<float2*>(Yout + (size_t)(r0 + 8) * N + c0) = hi;
            }
        }
    }
}

// ---------------- final combine ----------------
__global__ void combine_kernel(float* __restrict__ out) {
    int t = blockIdx.x;
    int i = threadIdx.x;
    float4* o = reinterpret_cast<float4*>(out + (size_t)t * DD);
    if (g_fbflag[t]) {
        const float4* src = reinterpret_cast<const float4*>(g_Yfb + (size_t)g_fbslot[t] * DD);
        o[i] = src[i];
    } else {
        int e0 = g_top2e[2*t], e1 = g_top2e[2*t+1];
        float w0 = g_top2w[2*t], w1 = g_top2w[2*t+1];
        size_t r0 = (size_t)(e0 * CAPACITY + g_slot[2*t]) * DD;
        size_t r1 = (size_t)(e1 * CAPACITY + g_slot[2*t+1]) * DD;
        float4 a = reinterpret_cast<const float4*>(g_Ye + r0)[i];
        float4 b = reinterpret_cast<const float4*>(g_Ye + r1)[i];
        float4 v;
        v.x = w0 * a.x + w1 * b.x;
        v.y = w0 * a.y + w1 * b.y;
        v.z = w0 * a.z + w1 * b.z;
        v.w = w0 * a.w + w1 * b.w;
        o[i] = v;
    }
}

// ---------------- launch ----------------
extern "C" void kernel_launch(void* const* d_in, const int* in_sizes, int n_in,
                              void* d_out, int out_size) {
    const float* x   = (const float*)d_in[0];
    const float* Wr  = (const float*)d_in[1];
    const float* W1  = (const float*)d_in[2];
    const float* b1  = (const float*)d_in[3];
    const float* W2  = (const float*)d_in[4];
    const float* b2  = (const float*)d_in[5];
    const float* fw1 = (const float*)d_in[6];
    const float* fb1 = (const float*)d_in[7];
    const float* fw2 = (const float*)d_in[8];
    const float* fb2 = (const float*)d_in[9];
    float* out = (float*)d_out;

    cudaFuncSetAttribute(gemm_kernel<0>, cudaFuncAttributeMaxDynamicSharedMemorySize, 3*STAGE_BYTES);
    cudaFuncSetAttribute(gemm_kernel<1>, cudaFuncAttributeMaxDynamicSharedMemorySize, 3*STAGE_BYTES);
    cudaFuncSetAttribute(gemm_kernel<2>, cudaFuncAttributeMaxDynamicSharedMemorySize, 3*STAGE_BYTES);
    cudaFuncSetAttribute(gemm_kernel<3>, cudaFuncAttributeMaxDynamicSharedMemorySize, 3*STAGE_BYTES);

    __half* dW1h;  cudaGetSymbolAddress((void**)&dW1h,  g_W1h);
    __half* dW2h;  cudaGetSymbolAddress((void**)&dW2h,  g_W2h);
    __half* dfw1h; cudaGetSymbolAddress((void**)&dfw1h, g_fw1h);
    __half* dfw2h; cudaGetSymbolAddress((void**)&dfw2h, g_fw2h);

    // launch order arranged so gemm_kernel<0> is launch index 5 (ncu -s 5 -c 1)
    router_kernel <<<TT/8, 256>>>(x, Wr);                                  // 0
    convert_kernel<<<(EE*DD*II/8 + 255)/256, 256>>>(W1,  dW1h,  EE*DD*II/8); // 1
    convert_kernel<<<(EE*II*DD/8 + 255)/256, 256>>>(W2,  dW2h,  EE*II*DD/8); // 2
    assign_kernel <<<1, 1024>>>();                                         // 3
    gather_all    <<<RR + TT, 256>>>(x);                                   // 4
    gemm_kernel<0><<<dim3(II/BN, CAPACITY/BM, EE), 256, 3*STAGE_BYTES>>>(b1); // 5  <- profiled
    gemm_kernel<2><<<dim3(DD/BN, CAPACITY/BM, EE), 256, 3*STAGE_BYTES>>>(b2); // 6
    convert_kernel<<<(DD*II/8 + 255)/256, 256>>>(fw1, dfw1h, DD*II/8);     // 7
    gemm_kernel<1><<<dim3(II/BN, TT/BM, 1), 256, 3*STAGE_BYTES>>>(fb1);    // 8
    convert_kernel<<<(II*DD/8 + 255)/256, 256>>>(fw2, dfw2h, II*DD/8);     // 9
    gemm_kernel<3><<<dim3(DD/BN, TT/BM, 1), 256, 3*STAGE_BYTES>>>(fb2);    // 10
    combine_kernel<<<TT, 256>>>(out);                                      // 11
}

// round 6
// speedup vs baseline: 1.1596x; 1.1306x over previous
#include <cuda_runtime.h>
#include <cuda_fp16.h>
#include <cstdint>

// ---------------- problem constants ----------------
#define TT   8192
#define DD   1024
#define II   4096
#define EE   8
#define CAPACITY 2560
#define RR   (EE*CAPACITY)

// arch-specific (sm_103a/sm_100a) feature gate for tcgen05
#if defined(__CUDA_ARCH__) && (defined(__CUDA_ARCH_FEAT_SM103_ALL) || defined(__CUDA_ARCH_FEAT_SM100_ALL) || defined(__CUDA_ARCH_SPECIFIC__) || defined(__CUDA_ARCH_FAMILY_SPECIFIC__))
#define TC_PATH 1
#else
#define TC_PATH 0
#endif

// ---------------- device scratch ----------------
// K-major fp16 weights: W1t [E][II][DD], W2t [E][DD][II], fw1t [II][DD], fw2t [DD][II]
__device__ __half g_W1t[(size_t)EE*DD*II];
__device__ __half g_W2t[(size_t)EE*II*DD];
__device__ __half g_fw1t[(size_t)DD*II];
__device__ __half g_fw2t[(size_t)II*DD];
__device__ __half g_Xg [(size_t)RR*DD];
__device__ __half g_Xfb[(size_t)TT*DD];
__device__ __half g_H  [(size_t)RR*II];
__device__ __half g_Hfb[(size_t)TT*II];
__device__ float  g_Ye [(size_t)RR*DD];
__device__ float  g_Yfb[(size_t)TT*DD];
__device__ int    g_top2e[TT*2];
__device__ float  g_top2w[TT*2];
__device__ int    g_slot [TT*2];
__device__ int    g_fbslot[TT];
__device__ int    g_fbidx [TT];
__device__ unsigned char g_fbflag[TT];
__device__ int    g_counts[EE];
__device__ int    g_fbcount;
__device__ int    g_idx[RR];

// ---------------- generic helpers ----------------
__device__ __forceinline__ float gelu_exact(float v) {
    return 0.5f * v * (1.0f + erff(v * 0.7071067811865475f));
}
__device__ __forceinline__ void cpasync16(uint32_t dst, const void* src) {
    asm volatile("cp.async.cg.shared.global [%0], [%1], 16;\n" :: "r"(dst), "l"(src));
}
__device__ __forceinline__ void cpasync_commit() { asm volatile("cp.async.commit_group;\n"); }
__device__ __forceinline__ void cpasync_wait0() { asm volatile("cp.async.wait_group 0;\n"); }
__device__ __forceinline__ void cpasync_wait1() { asm volatile("cp.async.wait_group 1;\n"); }

__device__ __forceinline__ uint32_t smem_u32(const void* p) {
    uint32_t a;
    asm("{ .reg .u64 t; cvta.to.shared.u64 t, %1; cvt.u32.u64 %0, t; }" : "=r"(a) : "l"(p));
    return a;
}
__device__ __forceinline__ void ldmatrix_x4(uint32_t* r, uint32_t addr) {
    asm volatile("ldmatrix.sync.aligned.m8n8.x4.shared.b16 {%0,%1,%2,%3}, [%4];"
                 : "=r"(r[0]), "=r"(r[1]), "=r"(r[2]), "=r"(r[3]) : "r"(addr));
}
__device__ __forceinline__ void mma16816(float* c, const uint32_t* a, const uint32_t* b) {
    asm volatile("mma.sync.aligned.m16n8k16.row.col.f32.f16.f16.f32 "
                 "{%0,%1,%2,%3},{%4,%5,%6,%7},{%8,%9},{%0,%1,%2,%3};"
                 : "+f"(c[0]), "+f"(c[1]), "+f"(c[2]), "+f"(c[3])
                 : "r"(a[0]), "r"(a[1]), "r"(a[2]), "r"(a[3]), "r"(b[0]), "r"(b[1]));
}

// ---------------- mbarrier helpers ----------------
__device__ __forceinline__ void mbar_init(uint32_t a, uint32_t cnt) {
    asm volatile("mbarrier.init.shared.b64 [%0], %1;" :: "r"(a), "r"(cnt) : "memory");
}
__device__ __forceinline__ void mbar_arrive(uint32_t a) {
    asm volatile("mbarrier.arrive.shared.b64 _, [%0];" :: "r"(a) : "memory");
}
__device__ __forceinline__ void mbar_wait(uint32_t a, uint32_t parity) {
    asm volatile(
        "{\n\t"
        ".reg .pred P1;\n\t"
        "WAIT_LOOP_%=:\n\t"
        "mbarrier.try_wait.parity.acquire.cta.shared::cta.b64 P1, [%0], %1, 0x989680;\n\t"
        "@P1 bra.uni WAIT_DONE_%=;\n\t"
        "bra.uni WAIT_LOOP_%=;\n\t"
        "WAIT_DONE_%=:\n\t"
        "}"
        :: "r"(a), "r"(parity) : "memory");
}
__device__ __forceinline__ void fence_proxy_async_shared() {
    asm volatile("fence.proxy.async.shared::cta;" ::: "memory");
}

// ---------------- fp32 -> fp16 transpose-convert ----------------
// src: [Kdim, Ndim] fp32 row-major; dst: [Ndim, Kdim] fp16 row-major (K-major weights)
__global__ void transpose_convert(const float* __restrict__ src, __half* __restrict__ dst,
                                  int Kdim, int Ndim) {
    __shared__ float tile[64][65];
    const size_t zoff = (size_t)blockIdx.z * Kdim * Ndim;
    src += zoff; dst += zoff;
    int kb = blockIdx.x * 64, nb = blockIdx.y * 64;
    int tid = threadIdx.x;
    #pragma unroll
    for (int p = 0; p < 4; p++) {
        int i = p * 256 + tid;
        int r = i >> 4, c4 = i & 15;
        float4 v = *reinterpret_cast<const float4*>(src + (size_t)(kb + r) * Ndim + nb + c4 * 4);
        tile[r][c4*4+0] = v.x; tile[r][c4*4+1] = v.y;
        tile[r][c4*4+2] = v.z; tile[r][c4*4+3] = v.w;
    }
    __syncthreads();
    #pragma unroll
    for (int p = 0; p < 8; p++) {
        int i = p * 256 + tid;
        int r2 = i >> 5, c2 = i & 31;
        __half2 h = __floats2half2_rn(tile[c2*2][r2], tile[c2*2+1][r2]);
        *reinterpret_cast<__half2*>(dst + (size_t)(nb + r2) * Kdim + kb + c2 * 2) = h;
    }
}

// ---------------- router ----------------
__global__ void router_kernel(const float* __restrict__ x, const float* __restrict__ Wr) {
    __shared__ float sWr[EE*DD];
    int tid = threadIdx.x;
    for (int i = tid; i < EE*DD; i += 256) sWr[i] = Wr[i];
    __syncthreads();
    int w = tid >> 5, lane = tid & 31;
    int t = blockIdx.x * 8 + w;
    const float* xr = x + (size_t)t * DD;
    float acc[EE];
    #pragma unroll
    for (int e = 0; e < EE; e++) acc[e] = 0.f;
    for (int d = lane; d < DD; d += 32) {
        float xv = xr[d];
        #pragma unroll
        for (int e = 0; e < EE; e++) acc[e] += xv * sWr[e*DD + d];
    }
    #pragma unroll
    for (int e = 0; e < EE; e++)
        #pragma unroll
        for (int o = 16; o > 0; o >>= 1) acc[e] += __shfl_xor_sync(0xffffffffu, acc[e], o);
    if (lane == 0) {
        float m = acc[0];
        #pragma unroll
        for (int e = 1; e < EE; e++) m = fmaxf(m, acc[e]);
        float p[EE], s = 0.f;
        #pragma unroll
        for (int e = 0; e < EE; e++) { p[e] = expf(acc[e] - m); s += p[e]; }
        #pragma unroll
        for (int e = 0; e < EE; e++) p[e] /= s;
        int i1 = 0;
        #pragma unroll
        for (int e = 1; e < EE; e++) if (p[e] > p[i1]) i1 = e;
        int i2 = -1;
        #pragma unroll
        for (int e = 0; e < EE; e++) if (e != i1 && (i2 < 0 || p[e] > p[i2])) i2 = e;
        float ssum = p[i1] + p[i2];
        if (ssum < 1e-9f) ssum = 1e-9f;
        g_top2e[2*t] = i1; g_top2e[2*t+1] = i2;
        g_top2w[2*t] = p[i1] / ssum; g_top2w[2*t+1] = p[i2] / ssum;
    }
}

// ---------------- sequential capacity assignment ----------------
__global__ void assign_kernel() {
    int tid = threadIdx.x, lane = tid & 31, wid = tid >> 5;
    __shared__ int wsum[32];
    int e0[8], e1[8];
    bool fb[8];
    #pragma unroll
    for (int i = 0; i < 8; i++) {
        int t = tid * 8 + i;
        e0[i] = g_top2e[2*t]; e1[i] = g_top2e[2*t+1];
        fb[i] = false;
    }
    for (int e = 0; e < EE; e++) {
        bool elig[8]; int cnt = 0;
        #pragma unroll
        for (int i = 0; i < 8; i++) {
            elig[i] = (!fb[i]) && (e0[i] == e || e1[i] == e);
            cnt += elig[i] ? 1 : 0;
        }
        int inc = cnt;
        #pragma unroll
        for (int o = 1; o < 32; o <<= 1) { int v = __shfl_up_sync(0xffffffffu, inc, o); if (lane >= o) inc += v; }
        if (lane == 31) wsum[wid] = inc;
        __syncthreads();
        if (wid == 0) {
            int v = wsum[lane];
            int inc2 = v;
            #pragma unroll
            for (int o = 1; o < 32; o <<= 1) { int u = __shfl_up_sync(0xffffffffu, inc2, o); if (lane >= o) inc2 += u; }
            wsum[lane] = inc2;
        }
        __syncthreads();
        int pos = inc - cnt + (wid ? wsum[wid-1] : 0);
        int total = wsum[31];
        if (tid == 0) g_counts[e] = (total < CAPACITY) ? total : CAPACITY;
        #pragma unroll
        for (int i = 0; i < 8; i++) {
            if (elig[i]) {
                int t = tid * 8 + i;
                if (pos < CAPACITY) {
                    int k = (e0[i] == e) ? 0 : 1;
                    g_slot[2*t + k] = pos;
                    g_idx[e*CAPACITY + pos] = t;
                } else {
                    fb[i] = true;
                }
                pos++;
            }
        }
        __syncthreads();
    }
    int cnt = 0;
    #pragma unroll
    for (int i = 0; i < 8; i++) cnt += fb[i] ? 1 : 0;
    int inc = cnt;
    #pragma unroll
    for (int o = 1; o < 32; o <<= 1) { int v = __shfl_up_sync(0xffffffffu, inc, o); if (lane >= o) inc += v; }
    if (lane == 31) wsum[wid] = inc;
    __syncthreads();
    if (wid == 0) {
        int v = wsum[lane];
        int inc2 = v;
        #pragma unroll
        for (int o = 1; o < 32; o <<= 1) { int u = __shfl_up_sync(0xffffffffu, inc2, o); if (lane >= o) inc2 += u; }
        wsum[lane] = inc2;
    }
    __syncthreads();
    int pos = inc - cnt + (wid ? wsum[wid-1] : 0);
    #pragma unroll
    for (int i = 0; i < 8; i++) {
        int t = tid * 8 + i;
        g_fbflag[t] = fb[i] ? 1 : 0;
        if (fb[i]) { g_fbidx[pos] = t; g_fbslot[t] = pos; pos++; }
    }
    if (tid == 0) g_fbcount = wsum[31];
}

// ---------------- fused gather ----------------
__global__ void gather_all(const float* __restrict__ x) {
    int r = blockIdx.x;
    int t;
    __half* dstrow;
    if (r < RR) {
        int e = r / CAPACITY;
        if (r - e*CAPACITY >= g_counts[e]) return;
        t = g_idx[r];
        dstrow = g_Xg + (size_t)r * DD;
    } else {
        int rr = r - RR;
        if (rr >= g_fbcount) return;
        t = g_fbidx[rr];
        dstrow = g_Xfb + (size_t)rr * DD;
    }
    const float4* src = reinterpret_cast<const float4*>(x + (size_t)t * DD);
    __half2* dst = reinterpret_cast<__half2*>(dstrow);
    int i = threadIdx.x;
    float4 v = src[i];
    dst[2*i]   = __floats2half2_rn(v.x, v.y);
    dst[2*i+1] = __floats2half2_rn(v.z, v.w);
}

// ---------------- GEMM (dual path: tcgen05 on arch-specific, HMMA otherwise) ----------------
// C[M x N] = A[M x K] @ B[N x K]^T   A: activations [row, K], B: K-major weights [N, K]
// MODE: 0 = X@W1->gelu->H (expert)  1 = fb  2 = H@W2+b->Ye  3 = fb
#define TBM 128
#define TBN 256
#define BKH 64                 // halves per k-chunk (128B rows)
#define NSTG 3
// tcgen05 stage: A 128x64h (16KB) + B 256x64h (32KB) = 48KB
#define TC_ASTG 16384
#define TC_STGB 49152
#define SM_TILE0 1024
#define GEMM_SMEM (SM_TILE0 + NSTG*TC_STGB)   // 148480
// HMMA stage: A 128x64h + B 128x64h = 32KB (fits inside the same allocation)
#define HM_STGB 32768

// idesc kind::f16: dtype F32 (1<<4), a/b F16 (0), N=256 -> 32<<17, M=128 -> 8<<24
#define IDESC_F16_128x256 ((1u<<4) | (32u<<17) | (8u<<24))

#if TC_PATH
// SW128 K-major smem descriptor: layout=2, version=1, SBO=64, LBO=1
static __device__ __forceinline__ uint64_t make_desc(uint32_t addr) {
    const uint64_t base =
        (uint64_t(2)  << 61) | (uint64_t(1) << 46) | (uint64_t(64) << 32) | (uint64_t(1) << 16);
    return base | ((uint64_t)(addr >> 4) & 0x3FFF);
}
__device__ __forceinline__ void mma_f16_ss(uint32_t d_tmem, uint64_t adesc, uint64_t bdesc,
                                           uint32_t idesc, bool accum) {
    uint32_t en = accum ? 1u : 0u;
    asm volatile(
        "{\n\t"
        ".reg .pred p;\n\t"
        "setp.ne.u32 p, %5, 0;\n\t"
        "tcgen05.mma.cta_group::1.kind::f16 [%0], %1, %2, %3, {%4, %4, %4, %4}, p;\n\t"
        "}"
        :: "r"(d_tmem), "l"(adesc), "l"(bdesc), "r"(idesc), "r"(0u), "r"(en)
        : "memory");
}
#define TC_LD32(r, addr) \
    asm volatile( \
        "tcgen05.ld.sync.aligned.32x32b.x32.b32 " \
        "{%0, %1, %2, %3, %4, %5, %6, %7, " \
        " %8, %9, %10, %11, %12, %13, %14, %15, " \
        " %16, %17, %18, %19, %20, %21, %22, %23, " \
        " %24, %25, %26, %27, %28, %29, %30, %31}, [%32];" \
        : "=r"((r)[0]),  "=r"((r)[1]),  "=r"((r)[2]),  "=r"((r)[3]), \
          "=r"((r)[4]),  "=r"((r)[5]),  "=r"((r)[6]),  "=r"((r)[7]), \
          "=r"((r)[8]),  "=r"((r)[9]),  "=r"((r)[10]), "=r"((r)[11]), \
          "=r"((r)[12]), "=r"((r)[13]), "=r"((r)[14]), "=r"((r)[15]), \
          "=r"((r)[16]), "=r"((r)[17]), "=r"((r)[18]), "=r"((r)[19]), \
          "=r"((r)[20]), "=r"((r)[21]), "=r"((r)[22]), "=r"((r)[23]), \
          "=r"((r)[24]), "=r"((r)[25]), "=r"((r)[26]), "=r"((r)[27]), \
          "=r"((r)[28]), "=r"((r)[29]), "=r"((r)[30]), "=r"((r)[31]) \
        : "r"(addr))
#endif

template<int MODE>
__global__ void __launch_bounds__(256, 1) gemm_tc(const float* __restrict__ bias) {
    constexpr bool G1 = (MODE < 2);
    constexpr bool FB = (MODE & 1);
    constexpr int K = G1 ? DD : II;
    constexpr int N = G1 ? II : DD;
    constexpr int KT = K / BKH;

    const int e = blockIdx.z;
    const int count = FB ? g_fbcount : g_counts[e];
    const int m0 = blockIdx.y * TBM;
    if (m0 >= count) return;
    const int n0 = blockIdx.x * TBN;

    const __half* __restrict__ A;
    const __half* __restrict__ B;
    if constexpr (MODE == 0) { A = g_Xg  + (size_t)e*CAPACITY*DD; B = g_W1t + (size_t)e*DD*II; }
    if constexpr (MODE == 1) { A = g_Xfb;                         B = g_fw1t; }
    if constexpr (MODE == 2) { A = g_H   + (size_t)e*CAPACITY*II; B = g_W2t + (size_t)e*II*DD; }
    if constexpr (MODE == 3) { A = g_Hfb;                         B = g_fw2t; }
    const float* biasp = bias + (FB ? 0 : (size_t)e*N);

    extern __shared__ char smem[];
    const uint32_t sb = smem_u32(smem);
    const int tid = threadIdx.x, lane = tid & 31, wid = tid >> 5;

#if TC_PATH
    // ---------------- tcgen05 path ----------------
    const uint32_t mb_full0 = sb + 64, mb_empty0 = sb + 96, mb_done = sb + 120;
    if (tid == 0) {
        #pragma unroll
        for (int s = 0; s < NSTG; s++) {
            mbar_init(mb_full0 + 8*s, 224);
            mbar_init(mb_empty0 + 8*s, 1);
        }
        mbar_init(mb_done, 1);
    }
    if (wid == 0) {
        asm volatile("tcgen05.alloc.cta_group::1.sync.aligned.shared::cta.b32 [%0], %1;"
                     :: "r"(sb), "r"(256) : "memory");
    }
    __syncthreads();
    uint32_t tb;
    asm volatile("ld.shared.b32 %0, [%1];" : "=r"(tb) : "r"(sb));

    if (wid == 0) {
        if (lane == 0) {
            uint64_t ad[NSTG], bd[NSTG];
            #pragma unroll
            for (int s = 0; s < NSTG; s++) {
                ad[s] = make_desc(sb + SM_TILE0 + s*TC_STGB);
                bd[s] = make_desc(sb + SM_TILE0 + s*TC_STGB + TC_ASTG);
            }
            #pragma unroll 1
            for (int kt = 0; kt < KT; kt++) {
                int st = kt % NSTG;
                uint32_t ph = (kt / NSTG) & 1;
                mbar_wait(mb_full0 + 8*st, ph);
                asm volatile("tcgen05.fence::after_thread_sync;" ::: "memory");
                #pragma unroll
                for (int k = 0; k < 4; k++)
                    mma_f16_ss(tb, ad[st] + k*2, bd[st] + k*2, IDESC_F16_128x256, (kt > 0) || (k > 0));
                asm volatile("tcgen05.commit.cta_group::1.mbarrier::arrive::one.shared::cluster.b64 [%0];"
                             :: "r"(mb_empty0 + 8*st) : "memory");
            }
            asm volatile("tcgen05.commit.cta_group::1.mbarrier::arrive::one.shared::cluster.b64 [%0];"
                         :: "r"(mb_done) : "memory");
        }
    } else {
        const int ptid = tid - 32;
        #pragma unroll 1
        for (int kt = 0; kt < KT; kt++) {
            int st = kt % NSTG;
            uint32_t eph = ((kt / NSTG) & 1) ^ 1u;
            mbar_wait(mb_empty0 + 8*st, eph);
            uint32_t aB = sb + SM_TILE0 + st*TC_STGB;
            uint32_t bB = aB + TC_ASTG;
            const __half* Ak = A + (size_t)m0 * K + kt * BKH;
            const __half* Bk = B + (size_t)n0 * K + kt * BKH;
            #pragma unroll 1
            for (int i = ptid; i < 3072; i += 224) {
                if (i < 1024) {
                    int r = i >> 3, c = i & 7;
                    cpasync16(aB + (uint32_t)(r*128 + ((c ^ (r & 7)) << 4)), Ak + (size_t)r*K + c*8);
                } else {
                    int j = i - 1024;
                    int r = j >> 3, c = j & 7;
                    cpasync16(bB + (uint32_t)(r*128 + ((c ^ (r & 7)) << 4)), Bk + (size_t)r*K + c*8);
                }
            }
            cpasync_commit();
            if (kt > 0) {
                cpasync_wait1();
                fence_proxy_async_shared();
                mbar_arrive(mb_full0 + 8*((kt-1) % NSTG));
            }
        }
        cpasync_wait0();
        fence_proxy_async_shared();
        mbar_arrive(mb_full0 + 8*((KT-1) % NSTG));
    }

    mbar_wait(mb_done, 0);
    asm volatile("tcgen05.fence::after_thread_sync;" ::: "memory");

    if (wid < 4) {
        const int row = m0 + wid*32 + lane;
        if constexpr (G1) {
            __half* outp = (FB ? g_Hfb : g_H + (size_t)e*CAPACITY*II) + (size_t)row * II;
            #pragma unroll 1
            for (int cb = 0; cb < 8; cb++) {
                uint32_t r[32];
                TC_LD32(r, tb + cb*32);
                asm volatile("tcgen05.wait::ld.sync.aligned;" ::: "memory");
                int c0 = n0 + cb*32;
                union { __half2 h[16]; uint4 u[4]; } o;
                #pragma unroll
                for (int j = 0; j < 16; j++) {
                    float v0 = __uint_as_float(r[2*j])   + __ldg(biasp + c0 + 2*j);
                    float v1 = __uint_as_float(r[2*j+1]) + __ldg(biasp + c0 + 2*j + 1);
                    o.h[j] = __floats2half2_rn(gelu_exact(v0), gelu_exact(v1));
                }
                uint4* dst = reinterpret_cast<uint4*>(outp + c0);
                dst[0] = o.u[0]; dst[1] = o.u[1]; dst[2] = o.u[2]; dst[3] = o.u[3];
            }
        } else {
            float* outp = (FB ? g_Yfb : g_Ye + (size_t)e*CAPACITY*DD) + (size_t)row * DD;
            #pragma unroll 1
            for (int cb = 0; cb < 8; cb++) {
                uint32_t r[32];
                TC_LD32(r, tb + cb*32);
                asm volatile("tcgen05.wait::ld.sync.aligned;" ::: "memory");
                int c0 = n0 + cb*32;
                #pragma unroll
                for (int q = 0; q < 8; q++) {
                    float4 v;
                    v.x = __uint_as_float(r[4*q+0]) + __ldg(biasp + c0 + 4*q + 0);
                    v.y = __uint_as_float(r[4*q+1]) + __ldg(biasp + c0 + 4*q + 1);
                    v.z = __uint_as_float(r[4*q+2]) + __ldg(biasp + c0 + 4*q + 2);
                    v.w = __uint_as_float(r[4*q+3]) + __ldg(biasp + c0 + 4*q + 3);
                    *reinterpret_cast<float4*>(outp + c0 + 4*q) = v;
                }
            }
        }
    }
    __syncthreads();
    if (wid == 0) {
        asm volatile("tcgen05.relinquish_alloc_permit.cta_group::1.sync.aligned;");
        asm volatile("tcgen05.dealloc.cta_group::1.sync.aligned.b32 %0, %1;" :: "r"(tb), "r"(256));
    }
#else
    // ---------------- HMMA fallback: two 128-wide halves of the 256 tile ----------------
    const int wm = wid & 1, wn = wid >> 1;
    const int g = lane >> 3, rin = lane & 7;

    #pragma unroll 1
    for (int half = 0; half < 2; half++) {
        const int n0h = n0 + half * 128;
        float acc[4][4][4];
        #pragma unroll
        for (int a = 0; a < 4; a++)
            #pragma unroll
            for (int b = 0; b < 4; b++)
                #pragma unroll
                for (int c = 0; c < 4; c++) acc[a][b][c] = 0.f;

        auto loadStage = [&](int kt, int st) {
            if (kt < KT) {
                uint32_t aB = sb + st * HM_STGB;
                uint32_t bB = aB + 16384;
                #pragma unroll
                for (int j = 0; j < 4; j++) {
                    int id = j * 256 + tid;
                    int r = id >> 3, c = id & 7;
                    cpasync16(aB + (uint32_t)(r*128 + ((c ^ (r & 7)) << 4)),
                              A + (size_t)(m0 + r) * K + kt * BKH + c * 8);
                }
                #pragma unroll
                for (int j = 0; j < 4; j++) {
                    int id = j * 256 + tid;
                    int r = id >> 3, c = id & 7;
                    cpasync16(bB + (uint32_t)(r*128 + ((c ^ (r & 7)) << 4)),
                              B + (size_t)(n0h + r) * K + kt * BKH + c * 8);
                }
            }
            cpasync_commit();
        };

        loadStage(0, 0);
        loadStage(1, 1);
        int st = 0;
        #pragma unroll 1
        for (int kt = 0; kt < KT; kt++) {
            cpasync_wait1();
            __syncthreads();
            loadStage(kt + 2, (st + 2) % 3);
            uint32_t aB = sb + st * HM_STGB;
            uint32_t bB = aB + 16384;
            #pragma unroll
            for (int ks = 0; ks < 4; ks++) {
                uint32_t afr[4][4];
                #pragma unroll
                for (int mt = 0; mt < 4; mt++) {
                    int row = wm * 64 + mt * 16 + (g & 1) * 8 + rin;
                    int ch = (ks * 2 + (g >> 1)) ^ rin;
                    ldmatrix_x4(afr[mt], aB + (uint32_t)(row * 128 + ch * 16));
                }
                uint32_t bfr[4][2];
                #pragma unroll
                for (int q = 0; q < 2; q++) {
                    int nrow = wn * 32 + q * 16 + (g & 1) * 8 + rin;
                    int ch = (ks * 2 + (g >> 1)) ^ rin;
                    uint32_t r4[4];
                    ldmatrix_x4(r4, bB + (uint32_t)(nrow * 128 + ch * 16));
                    bfr[q*2][0]   = r4[0]; bfr[q*2][1]   = r4[2];
                    bfr[q*2+1][0] = r4[1]; bfr[q*2+1][1] = r4[3];
                }
                #pragma unroll
                for (int mt = 0; mt < 4; mt++)
                    #pragma unroll
                    for (int nt = 0; nt < 4; nt++)
                        mma16816(acc[mt][nt], afr[mt], bfr[nt]);
            }
            st = (st + 1) % 3;
        }

        // epilogue for this half
        const int growb = m0 + wm * 64;
        const int gcolb = n0h + wn * 32;
        #pragma unroll
        for (int mt = 0; mt < 4; mt++) {
            #pragma unroll
            for (int nt = 0; nt < 4; nt++) {
                int r0 = growb + mt * 16 + (lane >> 2);
                int c0 = gcolb + nt * 8 + (lane & 3) * 2;
                float b0f = biasp[c0], b1f = biasp[c0 + 1];
                float x0 = acc[mt][nt][0] + b0f, x1 = acc[mt][nt][1] + b1f;
                float x2 = acc[mt][nt][2] + b0f, x3 = acc[mt][nt][3] + b1f;
                if constexpr (G1) {
                    __half* Hout = FB ? g_Hfb : (g_H + (size_t)e*CAPACITY*II);
                    *reinterpret_cast<__half2*>(Hout + (size_t)r0 * N + c0) =
                        __floats2half2_rn(gelu_exact(x0), gelu_exact(x1));
                    *reinterpret_cast<__half2*>(Hout + (size_t)(r0 + 8) * N + c0) =
                        __floats2half2_rn(gelu_exact(x2), gelu_exact(x3));
                } else {
                    float* Yout = FB ? g_Yfb : (g_Ye + (size_t)e*CAPACITY*DD);
                    float2 lo; lo.x = x0; lo.y = x1;
                    float2 hi; hi.x = x2; hi.y = x3;
                    *reinterpret_cast<float2*>(Yout + (size_t)r0 * N + c0)       = lo;
                    *reinterpret_cast<float2*>(Yout + (size_t)(r0 + 8) * N + c0) = hi;
                }
            }
        }
        cpasync_wait0();
        __syncthreads();
    }
#endif
}

// ---------------- final combine ----------------
__global__ void combine_kernel(float* __restrict__ out) {
    int t = blockIdx.x;
    int i = threadIdx.x;
    float4* o = reinterpret_cast<float4*>(out + (size_t)t * DD);
    if (g_fbflag[t]) {
        const float4* src = reinterpret_cast<const float4*>(g_Yfb + (size_t)g_fbslot[t] * DD);
        o[i] = src[i];
    } else {
        int e0 = g_top2e[2*t], e1 = g_top2e[2*t+1];
        float w0 = g_top2w[2*t], w1 = g_top2w[2*t+1];
        size_t r0 = (size_t)(e0 * CAPACITY + g_slot[2*t]) * DD;
        size_t r1 = (size_t)(e1 * CAPACITY + g_slot[2*t+1]) * DD;
        float4 a = reinterpret_cast<const float4*>(g_Ye + r0)[i];
        float4 b = reinterpret_cast<const float4*>(g_Ye + r1)[i];
        float4 v;
        v.x = w0 * a.x + w1 * b.x;
        v.y = w0 * a.y + w1 * b.y;
        v.z = w0 * a.z + w1 * b.z;
        v.w = w0 * a.w + w1 * b.w;
        o[i] = v;
    }
}

// ---------------- launch ----------------
extern "C" void kernel_launch(void* const* d_in, const int* in_sizes, int n_in,
                              void* d_out, int out_size) {
    const float* x   = (const float*)d_in[0];
    const float* Wr  = (const float*)d_in[1];
    const float* W1  = (const float*)d_in[2];
    const float* b1  = (const float*)d_in[3];
    const float* W2  = (const float*)d_in[4];
    const float* b2  = (const float*)d_in[5];
    const float* fw1 = (const float*)d_in[6];
    const float* fb1 = (const float*)d_in[7];
    const float* fw2 = (const float*)d_in[8];
    const float* fb2 = (const float*)d_in[9];
    float* out = (float*)d_out;

    cudaFuncSetAttribute(gemm_tc<0>, cudaFuncAttributeMaxDynamicSharedMemorySize, GEMM_SMEM);
    cudaFuncSetAttribute(gemm_tc<1>, cudaFuncAttributeMaxDynamicSharedMemorySize, GEMM_SMEM);
    cudaFuncSetAttribute(gemm_tc<2>, cudaFuncAttributeMaxDynamicSharedMemorySize, GEMM_SMEM);
    cudaFuncSetAttribute(gemm_tc<3>, cudaFuncAttributeMaxDynamicSharedMemorySize, GEMM_SMEM);

    __half* dW1t;  cudaGetSymbolAddress((void**)&dW1t,  g_W1t);
    __half* dW2t;  cudaGetSymbolAddress((void**)&dW2t,  g_W2t);
    __half* dfw1t; cudaGetSymbolAddress((void**)&dfw1t, g_fw1t);
    __half* dfw2t; cudaGetSymbolAddress((void**)&dfw2t, g_fw2t);

    // gemm_tc<0> kept at launch index 5 for ncu (-s 5 -c 1)
    router_kernel<<<TT/8, 256>>>(x, Wr);                                   // 0
    transpose_convert<<<dim3(DD/64, II/64, EE), 256>>>(W1, dW1t, DD, II);  // 1
    transpose_convert<<<dim3(II/64, DD/64, EE), 256>>>(W2, dW2t, II, DD);  // 2
    assign_kernel<<<1, 1024>>>();                                          // 3
    gather_all<<<RR + TT, 256>>>(x);                                       // 4
    gemm_tc<0><<<dim3(II/TBN, CAPACITY/TBM, EE), 256, GEMM_SMEM>>>(b1);    // 5 <- profiled
    gemm_tc<2><<<dim3(DD/TBN, CAPACITY/TBM, EE), 256, GEMM_SMEM>>>(b2);    // 6
    transpose_convert<<<dim3(DD/64, II/64, 1), 256>>>(fw1, dfw1t, DD, II); // 7
    gemm_tc<1><<<dim3(II/TBN, TT/TBM, 1), 256, GEMM_SMEM>>>(fb1);          // 8
    transpose_convert<<<dim3(II/64, DD/64, 1), 256>>>(fw2, dfw2t, II, DD); // 9
    gemm_tc<3><<<dim3(DD/TBN, TT/TBM, 1), 256, GEMM_SMEM>>>(fb2);          // 10
    combine_kernel<<<TT, 256>>>(out);                                      // 11
}

// round 7
// speedup vs baseline: 1.4292x; 1.2326x over previous
#include <cuda_runtime.h>
#include <cuda_fp16.h>
#include <cstdint>

// ---------------- problem constants ----------------
#define TT   8192
#define DD   1024
#define II   4096
#define EE   8
#define CAPACITY 2560
#define RR   (EE*CAPACITY)

// arch-specific (sm_103a/sm_100a) feature gate for tcgen05
#if defined(__CUDA_ARCH__) && (defined(__CUDA_ARCH_FEAT_SM103_ALL) || defined(__CUDA_ARCH_FEAT_SM100_ALL) || defined(__CUDA_ARCH_SPECIFIC__) || defined(__CUDA_ARCH_FAMILY_SPECIFIC__))
#define TC_PATH 1
#else
#define TC_PATH 0
#endif

// ---------------- device scratch ----------------
// Weight buffers are layout-polymorphic: TC path stores K-major [N,K] fp16,
// HMMA path stores [K,N] fp16. Only one layout is ever written+read per binary.
__device__ __half g_W1f[(size_t)EE*DD*II];
__device__ __half g_W2f[(size_t)EE*II*DD];
__device__ __half g_fw1f[(size_t)DD*II];
__device__ __half g_fw2f[(size_t)II*DD];
__device__ __half g_Xg [(size_t)RR*DD];
__device__ __half g_Xfb[(size_t)TT*DD];
__device__ __half g_H  [(size_t)RR*II];
__device__ __half g_Hfb[(size_t)TT*II];
__device__ float  g_Ye [(size_t)RR*DD];
__device__ float  g_Yfb[(size_t)TT*DD];
__device__ int    g_top2e[TT*2];
__device__ float  g_top2w[TT*2];
__device__ int    g_slot [TT*2];
__device__ int    g_fbslot[TT];
__device__ int    g_fbidx [TT];
__device__ unsigned char g_fbflag[TT];
__device__ int    g_counts[EE];
__device__ int    g_fbcount;
__device__ int    g_idx[RR];

// ---------------- generic helpers ----------------
__device__ __forceinline__ float gelu_exact(float v) {
    return 0.5f * v * (1.0f + erff(v * 0.7071067811865475f));
}
__device__ __forceinline__ void cpasync16(uint32_t dst, const void* src) {
    asm volatile("cp.async.cg.shared.global [%0], [%1], 16;\n" :: "r"(dst), "l"(src));
}
__device__ __forceinline__ void cpasync_commit() { asm volatile("cp.async.commit_group;\n"); }
__device__ __forceinline__ void cpasync_wait0() { asm volatile("cp.async.wait_group 0;\n"); }
__device__ __forceinline__ void cpasync_wait1() { asm volatile("cp.async.wait_group 1;\n"); }

__device__ __forceinline__ uint32_t smem_u32(const void* p) {
    uint32_t a;
    asm("{ .reg .u64 t; cvta.to.shared.u64 t, %1; cvt.u32.u64 %0, t; }" : "=r"(a) : "l"(p));
    return a;
}
__device__ __forceinline__ void ldmatrix_x4(uint32_t* r, uint32_t addr) {
    asm volatile("ldmatrix.sync.aligned.m8n8.x4.shared.b16 {%0,%1,%2,%3}, [%4];"
                 : "=r"(r[0]), "=r"(r[1]), "=r"(r[2]), "=r"(r[3]) : "r"(addr));
}
__device__ __forceinline__ void ldmatrix_x4_trans(uint32_t* r, uint32_t addr) {
    asm volatile("ldmatrix.sync.aligned.m8n8.x4.trans.shared.b16 {%0,%1,%2,%3}, [%4];"
                 : "=r"(r[0]), "=r"(r[1]), "=r"(r[2]), "=r"(r[3]) : "r"(addr));
}
__device__ __forceinline__ void mma16816(float* c, const uint32_t* a, const uint32_t* b) {
    asm volatile("mma.sync.aligned.m16n8k16.row.col.f32.f16.f16.f32 "
                 "{%0,%1,%2,%3},{%4,%5,%6,%7},{%8,%9},{%0,%1,%2,%3};"
                 : "+f"(c[0]), "+f"(c[1]), "+f"(c[2]), "+f"(c[3])
                 : "r"(a[0]), "r"(a[1]), "r"(a[2]), "r"(a[3]), "r"(b[0]), "r"(b[1]));
}

// ---------------- mbarrier helpers ----------------
__device__ __forceinline__ void mbar_init(uint32_t a, uint32_t cnt) {
    asm volatile("mbarrier.init.shared.b64 [%0], %1;" :: "r"(a), "r"(cnt) : "memory");
}
__device__ __forceinline__ void mbar_arrive(uint32_t a) {
    asm volatile("mbarrier.arrive.shared.b64 _, [%0];" :: "r"(a) : "memory");
}
__device__ __forceinline__ void mbar_wait(uint32_t a, uint32_t parity) {
    asm volatile(
        "{\n\t"
        ".reg .pred P1;\n\t"
        "WAIT_LOOP_%=:\n\t"
        "mbarrier.try_wait.parity.acquire.cta.shared::cta.b64 P1, [%0], %1, 0x989680;\n\t"
        "@P1 bra.uni WAIT_DONE_%=;\n\t"
        "bra.uni WAIT_LOOP_%=;\n\t"
        "WAIT_DONE_%=:\n\t"
        "}"
        :: "r"(a), "r"(parity) : "memory");
}
__device__ __forceinline__ void fence_proxy_async_shared() {
    asm volatile("fence.proxy.async.shared::cta;" ::: "memory");
}

// ---------------- fp32 -> fp16 plain convert (HMMA layout [K,N]) ----------------
__global__ void convert_kernel(const float* __restrict__ src, __half* __restrict__ dst, int n8) {
    int i = blockIdx.x * blockDim.x + threadIdx.x;
    if (i < n8) {
        float4 a = reinterpret_cast<const float4*>(src)[2*i];
        float4 b = reinterpret_cast<const float4*>(src)[2*i+1];
        union { __half2 h[4]; uint4 u; } o;
        o.h[0] = __floats2half2_rn(a.x, a.y);
        o.h[1] = __floats2half2_rn(a.z, a.w);
        o.h[2] = __floats2half2_rn(b.x, b.y);
        o.h[3] = __floats2half2_rn(b.z, b.w);
        reinterpret_cast<uint4*>(dst)[i] = o.u;
    }
}

// ---------------- fp32 -> fp16 transpose-convert (TC layout [N,K]) ----------------
__global__ void transpose_convert(const float* __restrict__ src, __half* __restrict__ dst,
                                  int Kdim, int Ndim) {
    __shared__ float tile[64][65];
    const size_t zoff = (size_t)blockIdx.z * Kdim * Ndim;
    src += zoff; dst += zoff;
    int kb = blockIdx.x * 64, nb = blockIdx.y * 64;
    int tid = threadIdx.x;
    #pragma unroll
    for (int p = 0; p < 4; p++) {
        int i = p * 256 + tid;
        int r = i >> 4, c4 = i & 15;
        float4 v = *reinterpret_cast<const float4*>(src + (size_t)(kb + r) * Ndim + nb + c4 * 4);
        tile[r][c4*4+0] = v.x; tile[r][c4*4+1] = v.y;
        tile[r][c4*4+2] = v.z; tile[r][c4*4+3] = v.w;
    }
    __syncthreads();
    // 16B stores: dst[n][k] = src[k][n]
    #pragma unroll
    for (int p = 0; p < 2; p++) {
        int i = p * 256 + tid;      // 0..511
        int r = i >> 3;             // n in 0..63
        int c = i & 7;              // k-group of 8
        union { __half2 h[4]; uint4 u; } o;
        #pragma unroll
        for (int j = 0; j < 4; j++)
            o.h[j] = __floats2half2_rn(tile[c*8 + 2*j][r], tile[c*8 + 2*j + 1][r]);
        *reinterpret_cast<uint4*>(dst + (size_t)(nb + r) * Kdim + kb + c * 8) = o.u;
    }
}

// ---------------- router ----------------
__global__ void router_kernel(const float* __restrict__ x, const float* __restrict__ Wr) {
    __shared__ float sWr[EE*DD];
    int tid = threadIdx.x;
    for (int i = tid; i < EE*DD; i += 256) sWr[i] = Wr[i];
    __syncthreads();
    int w = tid >> 5, lane = tid & 31;
    int t = blockIdx.x * 8 + w;
    const float* xr = x + (size_t)t * DD;
    float acc[EE];
    #pragma unroll
    for (int e = 0; e < EE; e++) acc[e] = 0.f;
    for (int d = lane; d < DD; d += 32) {
        float xv = xr[d];
        #pragma unroll
        for (int e = 0; e < EE; e++) acc[e] += xv * sWr[e*DD + d];
    }
    #pragma unroll
    for (int e = 0; e < EE; e++)
        #pragma unroll
        for (int o = 16; o > 0; o >>= 1) acc[e] += __shfl_xor_sync(0xffffffffu, acc[e], o);
    if (lane == 0) {
        float m = acc[0];
        #pragma unroll
        for (int e = 1; e < EE; e++) m = fmaxf(m, acc[e]);
        float p[EE], s = 0.f;
        #pragma unroll
        for (int e = 0; e < EE; e++) { p[e] = expf(acc[e] - m); s += p[e]; }
        #pragma unroll
        for (int e = 0; e < EE; e++) p[e] /= s;
        int i1 = 0;
        #pragma unroll
        for (int e = 1; e < EE; e++) if (p[e] > p[i1]) i1 = e;
        int i2 = -1;
        #pragma unroll
        for (int e = 0; e < EE; e++) if (e != i1 && (i2 < 0 || p[e] > p[i2])) i2 = e;
        float ssum = p[i1] + p[i2];
        if (ssum < 1e-9f) ssum = 1e-9f;
        g_top2e[2*t] = i1; g_top2e[2*t+1] = i2;
        g_top2w[2*t] = p[i1] / ssum; g_top2w[2*t+1] = p[i2] / ssum;
    }
}

// ---------------- sequential capacity assignment ----------------
__global__ void assign_kernel() {
    int tid = threadIdx.x, lane = tid & 31, wid = tid >> 5;
    __shared__ int wsum[32];
    int e0[8], e1[8];
    bool fb[8];
    #pragma unroll
    for (int i = 0; i < 8; i++) {
        int t = tid * 8 + i;
        e0[i] = g_top2e[2*t]; e1[i] = g_top2e[2*t+1];
        fb[i] = false;
    }
    for (int e = 0; e < EE; e++) {
        bool elig[8]; int cnt = 0;
        #pragma unroll
        for (int i = 0; i < 8; i++) {
            elig[i] = (!fb[i]) && (e0[i] == e || e1[i] == e);
            cnt += elig[i] ? 1 : 0;
        }
        int inc = cnt;
        #pragma unroll
        for (int o = 1; o < 32; o <<= 1) { int v = __shfl_up_sync(0xffffffffu, inc, o); if (lane >= o) inc += v; }
        if (lane == 31) wsum[wid] = inc;
        __syncthreads();
        if (wid == 0) {
            int v = wsum[lane];
            int inc2 = v;
            #pragma unroll
            for (int o = 1; o < 32; o <<= 1) { int u = __shfl_up_sync(0xffffffffu, inc2, o); if (lane >= o) inc2 += u; }
            wsum[lane] = inc2;
        }
        __syncthreads();
        int pos = inc - cnt + (wid ? wsum[wid-1] : 0);
        int total = wsum[31];
        if (tid == 0) g_counts[e] = (total < CAPACITY) ? total : CAPACITY;
        #pragma unroll
        for (int i = 0; i < 8; i++) {
            if (elig[i]) {
                int t = tid * 8 + i;
                if (pos < CAPACITY) {
                    int k = (e0[i] == e) ? 0 : 1;
                    g_slot[2*t + k] = pos;
                    g_idx[e*CAPACITY + pos] = t;
                } else {
                    fb[i] = true;
                }
                pos++;
            }
        }
        __syncthreads();
    }
    int cnt = 0;
    #pragma unroll
    for (int i = 0; i < 8; i++) cnt += fb[i] ? 1 : 0;
    int inc = cnt;
    #pragma unroll
    for (int o = 1; o < 32; o <<= 1) { int v = __shfl_up_sync(0xffffffffu, inc, o); if (lane >= o) inc += v; }
    if (lane == 31) wsum[wid] = inc;
    __syncthreads();
    if (wid == 0) {
        int v = wsum[lane];
        int inc2 = v;
        #pragma unroll
        for (int o = 1; o < 32; o <<= 1) { int u = __shfl_up_sync(0xffffffffu, inc2, o); if (lane >= o) inc2 += u; }
        wsum[lane] = inc2;
    }
    __syncthreads();
    int pos = inc - cnt + (wid ? wsum[wid-1] : 0);
    #pragma unroll
    for (int i = 0; i < 8; i++) {
        int t = tid * 8 + i;
        g_fbflag[t] = fb[i] ? 1 : 0;
        if (fb[i]) { g_fbidx[pos] = t; g_fbslot[t] = pos; pos++; }
    }
    if (tid == 0) g_fbcount = wsum[31];
}

// ---------------- fused gather ----------------
__global__ void gather_all(const float* __restrict__ x) {
    int r = blockIdx.x;
    int t;
    __half* dstrow;
    if (r < RR) {
        int e = r / CAPACITY;
        if (r - e*CAPACITY >= g_counts[e]) return;
        t = g_idx[r];
        dstrow = g_Xg + (size_t)r * DD;
    } else {
        int rr = r - RR;
        if (rr >= g_fbcount) return;
        t = g_fbidx[rr];
        dstrow = g_Xfb + (size_t)rr * DD;
    }
    const float4* src = reinterpret_cast<const float4*>(x + (size_t)t * DD);
    __half2* dst = reinterpret_cast<__half2*>(dstrow);
    int i = threadIdx.x;
    float4 v = src[i];
    dst[2*i]   = __floats2half2_rn(v.x, v.y);
    dst[2*i+1] = __floats2half2_rn(v.z, v.w);
}

// ============================================================================
// Path A: tcgen05 GEMM, M=256 per CTA (two m-tiles share each B stage)
// C[256 x 256] per CTA;  A: [row,K] act rows; B: K-major weights [N,K]
// MODE: 0 = X@W1->gelu->H (expert)  1 = fb  2 = H@W2+b->Ye  3 = fb
// ============================================================================
#define TCBM 256
#define TCBN 256
#define BKH 64
#define NSTG 3
#define TC_A2 32768          // A: 256 rows x 128B
#define TC_STGB 65536        // A(32K) + B(32K)
#define SM_TILE0 1024
#define TC_SMEM (SM_TILE0 + NSTG*TC_STGB)   // 197632

// idesc kind::f16: dtype F32 (1<<4), a/b F16, N=256 -> 32<<17, M=128 -> 8<<24
#define IDESC_F16_128x256 ((1u<<4) | (32u<<17) | (8u<<24))

#if TC_PATH
static __device__ __forceinline__ uint64_t make_desc(uint32_t addr) {
    const uint64_t base =
        (uint64_t(2)  << 61) | (uint64_t(1) << 46) | (uint64_t(64) << 32) | (uint64_t(1) << 16);
    return base | ((uint64_t)(addr >> 4) & 0x3FFF);
}
__device__ __forceinline__ void mma_f16_ss(uint32_t d_tmem, uint64_t adesc, uint64_t bdesc,
                                           uint32_t idesc, bool accum) {
    uint32_t en = accum ? 1u : 0u;
    asm volatile(
        "{\n\t"
        ".reg .pred p;\n\t"
        "setp.ne.u32 p, %5, 0;\n\t"
        "tcgen05.mma.cta_group::1.kind::f16 [%0], %1, %2, %3, {%4, %4, %4, %4}, p;\n\t"
        "}"
        :: "r"(d_tmem), "l"(adesc), "l"(bdesc), "r"(idesc), "r"(0u), "r"(en)
        : "memory");
}
#define TC_LD32(r, addr) \
    asm volatile( \
        "tcgen05.ld.sync.aligned.32x32b.x32.b32 " \
        "{%0, %1, %2, %3, %4, %5, %6, %7, " \
        " %8, %9, %10, %11, %12, %13, %14, %15, " \
        " %16, %17, %18, %19, %20, %21, %22, %23, " \
        " %24, %25, %26, %27, %28, %29, %30, %31}, [%32];" \
        : "=r"((r)[0]),  "=r"((r)[1]),  "=r"((r)[2]),  "=r"((r)[3]), \
          "=r"((r)[4]),  "=r"((r)[5]),  "=r"((r)[6]),  "=r"((r)[7]), \
          "=r"((r)[8]),  "=r"((r)[9]),  "=r"((r)[10]), "=r"((r)[11]), \
          "=r"((r)[12]), "=r"((r)[13]), "=r"((r)[14]), "=r"((r)[15]), \
          "=r"((r)[16]), "=r"((r)[17]), "=r"((r)[18]), "=r"((r)[19]), \
          "=r"((r)[20]), "=r"((r)[21]), "=r"((r)[22]), "=r"((r)[23]), \
          "=r"((r)[24]), "=r"((r)[25]), "=r"((r)[26]), "=r"((r)[27]), \
          "=r"((r)[28]), "=r"((r)[29]), "=r"((r)[30]), "=r"((r)[31]) \
        : "r"(addr))
#endif

template<int MODE>
__global__ void __launch_bounds__(256, 1) gemm_tc5(const float* __restrict__ bias) {
#if TC_PATH
    constexpr bool G1 = (MODE < 2);
    constexpr bool FB = (MODE & 1);
    constexpr int K = G1 ? DD : II;
    constexpr int N = G1 ? II : DD;
    constexpr int KT = K / BKH;

    const int e = blockIdx.z;
    const int count = FB ? g_fbcount : g_counts[e];
    const int m0 = blockIdx.y * TCBM;
    if (m0 >= count) return;
    const int n0 = blockIdx.x * TCBN;

    const __half* __restrict__ A;
    const __half* __restrict__ B;
    if constexpr (MODE == 0) { A = g_Xg  + (size_t)e*CAPACITY*DD; B = g_W1f + (size_t)e*DD*II; }
    if constexpr (MODE == 1) { A = g_Xfb;                         B = g_fw1f; }
    if constexpr (MODE == 2) { A = g_H   + (size_t)e*CAPACITY*II; B = g_W2f + (size_t)e*II*DD; }
    if constexpr (MODE == 3) { A = g_Hfb;                         B = g_fw2f; }
    const float* biasp = bias + (FB ? 0 : (size_t)e*N);

    extern __shared__ char smem[];
    const uint32_t sb = smem_u32(smem);
    const int tid = threadIdx.x, lane = tid & 31, wid = tid >> 5;

    const uint32_t mb_full0 = sb + 64, mb_empty0 = sb + 96, mb_done = sb + 120;
    if (tid == 0) {
        #pragma unroll
        for (int s = 0; s < NSTG; s++) {
            mbar_init(mb_full0 + 8*s, 224);
            mbar_init(mb_empty0 + 8*s, 1);
        }
        mbar_init(mb_done, 1);
    }
    if (wid == 0) {
        asm volatile("tcgen05.alloc.cta_group::1.sync.aligned.shared::cta.b32 [%0], %1;"
                     :: "r"(sb), "r"(512) : "memory");
    }
    __syncthreads();
    uint32_t tb;
    asm volatile("ld.shared.b32 %0, [%1];" : "=r"(tb) : "r"(sb));

    if (wid == 0) {
        if (lane == 0) {
            uint64_t ad0[NSTG], ad1[NSTG], bd[NSTG];
            #pragma unroll
            for (int s = 0; s < NSTG; s++) {
                uint32_t base = sb + SM_TILE0 + s*TC_STGB;
                ad0[s] = make_desc(base);
                ad1[s] = make_desc(base + 16384);
                bd[s]  = make_desc(base + TC_A2);
            }
            #pragma unroll 1
            for (int kt = 0; kt < KT; kt++) {
                int st = kt % NSTG;
                uint32_t ph = (kt / NSTG) & 1;
                mbar_wait(mb_full0 + 8*st, ph);
                asm volatile("tcgen05.fence::after_thread_sync;" ::: "memory");
                #pragma unroll
                for (int k = 0; k < 4; k++) {
                    bool acc = (kt > 0) || (k > 0);
                    mma_f16_ss(tb,       ad0[st] + k*2, bd[st] + k*2, IDESC_F16_128x256, acc);
                    mma_f16_ss(tb + 256, ad1[st] + k*2, bd[st] + k*2, IDESC_F16_128x256, acc);
                }
                asm volatile("tcgen05.commit.cta_group::1.mbarrier::arrive::one.shared::cluster.b64 [%0];"
                             :: "r"(mb_empty0 + 8*st) : "memory");
            }
            asm volatile("tcgen05.commit.cta_group::1.mbarrier::arrive::one.shared::cluster.b64 [%0];"
                         :: "r"(mb_done) : "memory");
        }
    } else {
        const int ptid = tid - 32;
        #pragma unroll 1
        for (int kt = 0; kt < KT; kt++) {
            int st = kt % NSTG;
            uint32_t eph = ((kt / NSTG) & 1) ^ 1u;
            mbar_wait(mb_empty0 + 8*st, eph);
            uint32_t aB = sb + SM_TILE0 + st*TC_STGB;
            uint32_t bB = aB + TC_A2;
            const __half* Ak = A + (size_t)m0 * K + kt * BKH;
            const __half* Bk = B + (size_t)n0 * K + kt * BKH;
            #pragma unroll 1
            for (int i = ptid; i < 4096; i += 224) {
                if (i < 2048) {
                    int r = i >> 3, c = i & 7;
                    cpasync16(aB + (uint32_t)(r*128 + ((c ^ (r & 7)) << 4)), Ak + (size_t)r*K + c*8);
                } else {
                    int j = i - 2048;
                    int r = j >> 3, c = j & 7;
                    cpasync16(bB + (uint32_t)(r*128 + ((c ^ (r & 7)) << 4)), Bk + (size_t)r*K + c*8);
                }
            }
            cpasync_commit();
            if (kt > 0) {
                cpasync_wait1();
                fence_proxy_async_shared();
                mbar_arrive(mb_full0 + 8*((kt-1) % NSTG));
            }
        }
        cpasync_wait0();
        fence_proxy_async_shared();
        mbar_arrive(mb_full0 + 8*((KT-1) % NSTG));
    }

    mbar_wait(mb_done, 0);
    asm volatile("tcgen05.fence::after_thread_sync;" ::: "memory");

    // parallel epilogue: warps 0-3 -> m-tile 0 (TMEM cols 0-255),
    //                    warps 4-7 -> m-tile 1 (TMEM cols 256-511)
    {
        const int mtile = wid >> 2;
        const int lw = wid & 3;
        const int row = m0 + mtile*128 + lw*32 + lane;
        const uint32_t coff = (uint32_t)mtile * 256;
        if constexpr (G1) {
            __half* outp = (FB ? g_Hfb : g_H + (size_t)e*CAPACITY*II) + (size_t)row * II;
            #pragma unroll 1
            for (int cb = 0; cb < 8; cb++) {
                uint32_t r[32];
                TC_LD32(r, tb + coff + cb*32);
                asm volatile("tcgen05.wait::ld.sync.aligned;" ::: "memory");
                int c0 = n0 + cb*32;
                union { __half2 h[16]; uint4 u[4]; } o;
                #pragma unroll
                for (int j = 0; j < 16; j++) {
                    float v0 = __uint_as_float(r[2*j])   + __ldg(biasp + c0 + 2*j);
                    float v1 = __uint_as_float(r[2*j+1]) + __ldg(biasp + c0 + 2*j + 1);
                    o.h[j] = __floats2half2_rn(gelu_exact(v0), gelu_exact(v1));
                }
                uint4* dst = reinterpret_cast<uint4*>(outp + c0);
                dst[0] = o.u[0]; dst[1] = o.u[1]; dst[2] = o.u[2]; dst[3] = o.u[3];
            }
        } else {
            float* outp = (FB ? g_Yfb : g_Ye + (size_t)e*CAPACITY*DD) + (size_t)row * DD;
            #pragma unroll 1
            for (int cb = 0; cb < 8; cb++) {
                uint32_t r[32];
                TC_LD32(r, tb + coff + cb*32);
                asm volatile("tcgen05.wait::ld.sync.aligned;" ::: "memory");
                int c0 = n0 + cb*32;
                #pragma unroll
                for (int q = 0; q < 8; q++) {
                    float4 v;
                    v.x = __uint_as_float(r[4*q+0]) + __ldg(biasp + c0 + 4*q + 0);
                    v.y = __uint_as_float(r[4*q+1]) + __ldg(biasp + c0 + 4*q + 1);
                    v.z = __uint_as_float(r[4*q+2]) + __ldg(biasp + c0 + 4*q + 2);
                    v.w = __uint_as_float(r[4*q+3]) + __ldg(biasp + c0 + 4*q + 3);
                    *reinterpret_cast<float4*>(outp + c0 + 4*q) = v;
                }
            }
        }
    }
    __syncthreads();
    if (wid == 0) {
        asm volatile("tcgen05.relinquish_alloc_permit.cta_group::1.sync.aligned;");
        asm volatile("tcgen05.dealloc.cta_group::1.sync.aligned.b32 %0, %1;" :: "r"(tb), "r"(512));
    }
#endif
}

// ============================================================================
// Path B: HMMA GEMM (R4-proven, [K,N] weights), 128x128 tiles, 3-stage, 96KB
// ============================================================================
#define BM 128
#define BN 128
#define HM_STGB 32768
#define HM_SMEM (3*HM_STGB)

template<int MODE>
__global__ void gemm_hmma(const float* __restrict__ bias) {
    constexpr bool G1 = (MODE < 2);
    constexpr bool FB = (MODE & 1);
    constexpr int K = G1 ? DD : II;
    constexpr int N = G1 ? II : DD;
    constexpr int KT = K / BKH;

    const int e = blockIdx.z;
    const int count = FB ? g_fbcount : g_counts[e];
    const int m0 = blockIdx.y * BM;
    if (m0 >= count) return;
    const int n0 = blockIdx.x * BN;

    const __half* __restrict__ Aexp;
    const __half* __restrict__ Bexp;
    if constexpr (MODE == 0) { Aexp = g_Xg  + (size_t)e*CAPACITY*K; Bexp = g_W1f + (size_t)e*K*II; }
    if constexpr (MODE == 1) { Aexp = g_Xfb;                        Bexp = g_fw1f; }
    if constexpr (MODE == 2) { Aexp = g_H   + (size_t)e*CAPACITY*K; Bexp = g_W2f + (size_t)e*K*DD; }
    if constexpr (MODE == 3) { Aexp = g_Hfb;                        Bexp = g_fw2f; }
    const float* biasp = bias + (FB ? 0 : (size_t)e*N);

    extern __shared__ __half smemh[];
    const uint32_t sbase = smem_u32(smemh);
    const int tid = threadIdx.x, lane = tid & 31, wid = tid >> 5;
    const int wm = wid & 1, wn = wid >> 1;
    const int g = lane >> 3, rin = lane & 7;

    float acc[4][4][4];
    #pragma unroll
    for (int a = 0; a < 4; a++)
        #pragma unroll
        for (int b = 0; b < 4; b++)
            #pragma unroll
            for (int c = 0; c < 4; c++) acc[a][b][c] = 0.f;

    auto loadStage = [&](int kt, int st) {
        if (kt < KT) {
            uint32_t aB = sbase + st * HM_STGB;
            uint32_t bB = aB + 16384;
            #pragma unroll
            for (int j = 0; j < 4; j++) {
                int id = j * 256 + tid;
                int r = id >> 3, c = id & 7;
                const __half* src = Aexp + (size_t)(m0 + r) * K + kt * BKH + c * 8;
                uint32_t dst = aB + (uint32_t)(r * 64 + ((c ^ (r & 7)) << 3)) * 2;
                cpasync16(dst, src);
            }
            #pragma unroll
            for (int j = 0; j < 4; j++) {
                int id = j * 256 + tid;
                int r = id >> 4, c = id & 15;
                const __half* src = Bexp + (size_t)(kt * BKH + r) * N + n0 + c * 8;
                uint32_t dst = bB + (uint32_t)(r * 128 + (((c & 8) | ((c ^ r) & 7)) << 3)) * 2;
                cpasync16(dst, src);
            }
        }
        cpasync_commit();
    };

    loadStage(0, 0);
    loadStage(1, 1);
    int st = 0;
    #pragma unroll 1
    for (int kt = 0; kt < KT; kt++) {
        cpasync_wait1();
        __syncthreads();
        loadStage(kt + 2, (st + 2) % 3);
        uint32_t aB = sbase + st * HM_STGB;
        uint32_t bB = aB + 16384;
        #pragma unroll
        for (int ks = 0; ks < 4; ks++) {
            uint32_t afr[4][4];
            #pragma unroll
            for (int mt = 0; mt < 4; mt++) {
                int row = wm * 64 + mt * 16 + (g & 1) * 8 + rin;
                int ch = (ks * 2 + (g >> 1)) ^ rin;
                ldmatrix_x4(afr[mt], aB + (uint32_t)(row * 64 + ch * 8) * 2);
            }
            uint32_t bfr[4][2];
            #pragma unroll
            for (int ht = 0; ht < 2; ht++) {
                int row = ks * 16 + (g & 1) * 8 + rin;
                int c = wn * 4 + ht * 2 + (g >> 1);
                int ph = (c & 8) | ((c & 7) ^ rin);
                uint32_t r4[4];
                ldmatrix_x4_trans(r4, bB + (uint32_t)(row * 128 + ph * 8) * 2);
                bfr[ht*2][0] = r4[0]; bfr[ht*2][1] = r4[1];
                bfr[ht*2+1][0] = r4[2]; bfr[ht*2+1][1] = r4[3];
            }
            #pragma unroll
            for (int mt = 0; mt < 4; mt++)
                #pragma unroll
                for (int nt = 0; nt < 4; nt++)
                    mma16816(acc[mt][nt], afr[mt], bfr[nt]);
        }
        st = (st + 1) % 3;
    }

    const int growb = m0 + wm * 64;
    const int gcolb = n0 + wn * 32;
    #pragma unroll
    for (int mt = 0; mt < 4; mt++) {
        #pragma unroll
        for (int nt = 0; nt < 4; nt++) {
            int r0 = growb + mt * 16 + (lane >> 2);
            int c0 = gcolb + nt * 8 + (lane & 3) * 2;
            float b0f = biasp[c0], b1f = biasp[c0 + 1];
            float x0 = acc[mt][nt][0] + b0f, x1 = acc[mt][nt][1] + b1f;
            float x2 = acc[mt][nt][2] + b0f, x3 = acc[mt][nt][3] + b1f;
            if constexpr (G1) {
                __half* Hout = FB ? g_Hfb : (g_H + (size_t)e*CAPACITY*N);
                *reinterpret_cast<__half2*>(Hout + (size_t)r0 * N + c0) =
                    __floats2half2_rn(gelu_exact(x0), gelu_exact(x1));
                *reinterpret_cast<__half2*>(Hout + (size_t)(r0 + 8) * N + c0) =
                    __floats2half2_rn(gelu_exact(x2), gelu_exact(x3));
            } else {
                float* Yout = FB ? g_Yfb : (g_Ye + (size_t)e*CAPACITY*N);
                float2 lo; lo.x = x0; lo.y = x1;
                float2 hi; hi.x = x2; hi.y = x3;
                *reinterpret_cast<float2*>(Yout + (size_t)r0 * N + c0)       = lo;
                *reinterpret_cast<float2*>(Yout + (size_t)(r0 + 8) * N + c0) = hi;
            }
        }
    }
}

// ---------------- final combine ----------------
__global__ void combine_kernel(float* __restrict__ out) {
    int t = blockIdx.x;
    int i = threadIdx.x;
    float4* o = reinterpret_cast<float4*>(out + (size_t)t * DD);
    if (g_fbflag[t]) {
        const float4* src = reinterpret_cast<const float4*>(g_Yfb + (size_t)g_fbslot[t] * DD);
        o[i] = src[i];
    } else {
        int e0 = g_top2e[2*t], e1 = g_top2e[2*t+1];
        float w0 = g_top2w[2*t], w1 = g_top2w[2*t+1];
        size_t r0 = (size_t)(e0 * CAPACITY + g_slot[2*t]) * DD;
        size_t r1 = (size_t)(e1 * CAPACITY + g_slot[2*t+1]) * DD;
        float4 a = reinterpret_cast<const float4*>(g_Ye + r0)[i];
        float4 b = reinterpret_cast<const float4*>(g_Ye + r1)[i];
        float4 v;
        v.x = w0 * a.x + w1 * b.x;
        v.y = w0 * a.y + w1 * b.y;
        v.z = w0 * a.z + w1 * b.z;
        v.w = w0 * a.w + w1 * b.w;
        o[i] = v;
    }
}

// ---------------- launch ----------------
extern "C" void kernel_launch(void* const* d_in, const int* in_sizes, int n_in,
                              void* d_out, int out_size) {
    const float* x   = (const float*)d_in[0];
    const float* Wr  = (const float*)d_in[1];
    const float* W1  = (const float*)d_in[2];
    const float* b1  = (const float*)d_in[3];
    const float* W2  = (const float*)d_in[4];
    const float* b2  = (const float*)d_in[5];
    const float* fw1 = (const float*)d_in[6];
    const float* fb1 = (const float*)d_in[7];
    const float* fw2 = (const float*)d_in[8];
    const float* fb2 = (const float*)d_in[9];
    float* out = (float*)d_out;

    __half* dW1;  cudaGetSymbolAddress((void**)&dW1,  g_W1f);
    __half* dW2;  cudaGetSymbolAddress((void**)&dW2,  g_W2f);
    __half* dfw1; cudaGetSymbolAddress((void**)&dfw1, g_fw1f);
    __half* dfw2; cudaGetSymbolAddress((void**)&dfw2, g_fw2f);

    // Runtime path probe: under an arch-specific compile the tcgen05 kernel has a
    // real body (>=40 regs); under a generic pass it compiles empty (<16 regs).
    cudaFuncAttributes fa{};
    cudaFuncGetAttributes(&fa, (const void*)gemm_tc5<0>);
    const bool use_tc = (fa.numRegs >= 24);

    router_kernel<<<TT/8, 256>>>(x, Wr);                                    // 0

    if (use_tc) {
        cudaFuncSetAttribute(gemm_tc5<0>, cudaFuncAttributeMaxDynamicSharedMemorySize, TC_SMEM);
        cudaFuncSetAttribute(gemm_tc5<1>, cudaFuncAttributeMaxDynamicSharedMemorySize, TC_SMEM);
        cudaFuncSetAttribute(gemm_tc5<2>, cudaFuncAttributeMaxDynamicSharedMemorySize, TC_SMEM);
        cudaFuncSetAttribute(gemm_tc5<3>, cudaFuncAttributeMaxDynamicSharedMemorySize, TC_SMEM);
        // K-major [N,K] weights
        transpose_convert<<<dim3(DD/64, II/64, EE), 256>>>(W1, dW1, DD, II); // 1
        transpose_convert<<<dim3(II/64, DD/64, EE), 256>>>(W2, dW2, II, DD); // 2
        assign_kernel<<<1, 1024>>>();                                        // 3
        gather_all<<<RR + TT, 256>>>(x);                                     // 4
        gemm_tc5<0><<<dim3(II/TCBN, CAPACITY/TCBM, EE), 256, TC_SMEM>>>(b1); // 5 <- profiled
        gemm_tc5<2><<<dim3(DD/TCBN, CAPACITY/TCBM, EE), 256, TC_SMEM>>>(b2); // 6
        transpose_convert<<<dim3(DD/64, II/64, 1), 256>>>(fw1, dfw1, DD, II);
        gemm_tc5<1><<<dim3(II/TCBN, TT/TCBM, 1), 256, TC_SMEM>>>(fb1);
        transpose_convert<<<dim3(II/64, DD/64, 1), 256>>>(fw2, dfw2, II, DD);
        gemm_tc5<3><<<dim3(DD/TCBN, TT/TCBM, 1), 256, TC_SMEM>>>(fb2);
    } else {
        cudaFuncSetAttribute(gemm_hmma<0>, cudaFuncAttributeMaxDynamicSharedMemorySize, HM_SMEM);
        cudaFuncSetAttribute(gemm_hmma<1>, cudaFuncAttributeMaxDynamicSharedMemorySize, HM_SMEM);
        cudaFuncSetAttribute(gemm_hmma<2>, cudaFuncAttributeMaxDynamicSharedMemorySize, HM_SMEM);
        cudaFuncSetAttribute(gemm_hmma<3>, cudaFuncAttributeMaxDynamicSharedMemorySize, HM_SMEM);
        // [K,N] weights (R4 layout)
        convert_kernel<<<(EE*DD*II/8 + 255)/256, 256>>>(W1, dW1, EE*DD*II/8);
        convert_kernel<<<(EE*II*DD/8 + 255)/256, 256>>>(W2, dW2, EE*II*DD/8);
        assign_kernel<<<1, 1024>>>();
        gather_all<<<RR + TT, 256>>>(x);
        gemm_hmma<0><<<dim3(II/BN, CAPACITY/BM, EE), 256, HM_SMEM>>>(b1);
        gemm_hmma<2><<<dim3(DD/BN, CAPACITY/BM, EE), 256, HM_SMEM>>>(b2);
        convert_kernel<<<(DD*II/8 + 255)/256, 256>>>(fw1, dfw1, DD*II/8);
        gemm_hmma<1><<<dim3(II/BN, TT/BM, 1), 256, HM_SMEM>>>(fb1);
        convert_kernel<<<(II*DD/8 + 255)/256, 256>>>(fw2, dfw2, II*DD/8);
        gemm_hmma<3><<<dim3(DD/BN, TT/BM, 1), 256, HM_SMEM>>>(fb2);
    }

    combine_kernel<<<TT, 256>>>(out);
}

// round 8
// speedup vs baseline: 1.4786x; 1.0345x over previous
#include <cuda_runtime.h>
#include <cuda_fp16.h>
#include <cstdint>

// ---------------- problem constants ----------------
#define TT   8192
#define DD   1024
#define II   4096
#define EE   8
#define CAPACITY 2560
#define RR   (EE*CAPACITY)

// arch-specific (sm_103a/sm_100a) feature gate for tcgen05
#if defined(__CUDA_ARCH__) && (defined(__CUDA_ARCH_FEAT_SM103_ALL) || defined(__CUDA_ARCH_FEAT_SM100_ALL) || defined(__CUDA_ARCH_SPECIFIC__) || defined(__CUDA_ARCH_FAMILY_SPECIFIC__))
#define TC_PATH 1
#else
#define TC_PATH 0
#endif

// ---------------- device scratch ----------------
// Weights: TC path -> K-major [N,K] fp16; HMMA path -> [K,N] fp16.
__device__ __half g_W1f[(size_t)EE*DD*II];
__device__ __half g_W2f[(size_t)EE*II*DD];
__device__ __half g_fw1f[(size_t)DD*II];
__device__ __half g_fw2f[(size_t)II*DD];
__device__ __half g_Xg [(size_t)RR*DD];
__device__ __half g_Xfb[(size_t)TT*DD];
__device__ __half g_H  [(size_t)RR*II];
__device__ __half g_Hfb[(size_t)TT*II];
__device__ __half g_Yeh [(size_t)RR*DD];
__device__ __half g_Yfbh[(size_t)TT*DD];
__device__ int    g_top2e[TT*2];
__device__ float  g_top2w[TT*2];
__device__ int    g_slot [TT*2];
__device__ int    g_fbslot[TT];
__device__ int    g_fbidx [TT];
__device__ unsigned char g_fbflag[TT];
__device__ int    g_counts[EE];
__device__ int    g_fbcount;
__device__ int    g_idx[RR];

// ---------------- generic helpers ----------------
__device__ __forceinline__ float gelu_exact(float v) {
    return 0.5f * v * (1.0f + erff(v * 0.7071067811865475f));
}
__device__ __forceinline__ void cpasync16(uint32_t dst, const void* src) {
    asm volatile("cp.async.cg.shared.global [%0], [%1], 16;\n" :: "r"(dst), "l"(src));
}
__device__ __forceinline__ void cpasync_commit() { asm volatile("cp.async.commit_group;\n"); }
__device__ __forceinline__ void cpasync_wait0() { asm volatile("cp.async.wait_group 0;\n"); }
__device__ __forceinline__ void cpasync_wait1() { asm volatile("cp.async.wait_group 1;\n"); }

__device__ __forceinline__ uint32_t smem_u32(const void* p) {
    uint32_t a;
    asm("{ .reg .u64 t; cvta.to.shared.u64 t, %1; cvt.u32.u64 %0, t; }" : "=r"(a) : "l"(p));
    return a;
}
__device__ __forceinline__ void ldmatrix_x4(uint32_t* r, uint32_t addr) {
    asm volatile("ldmatrix.sync.aligned.m8n8.x4.shared.b16 {%0,%1,%2,%3}, [%4];"
                 : "=r"(r[0]), "=r"(r[1]), "=r"(r[2]), "=r"(r[3]) : "r"(addr));
}
__device__ __forceinline__ void ldmatrix_x4_trans(uint32_t* r, uint32_t addr) {
    asm volatile("ldmatrix.sync.aligned.m8n8.x4.trans.shared.b16 {%0,%1,%2,%3}, [%4];"
                 : "=r"(r[0]), "=r"(r[1]), "=r"(r[2]), "=r"(r[3]) : "r"(addr));
}
__device__ __forceinline__ void mma16816(float* c, const uint32_t* a, const uint32_t* b) {
    asm volatile("mma.sync.aligned.m16n8k16.row.col.f32.f16.f16.f32 "
                 "{%0,%1,%2,%3},{%4,%5,%6,%7},{%8,%9},{%0,%1,%2,%3};"
                 : "+f"(c[0]), "+f"(c[1]), "+f"(c[2]), "+f"(c[3])
                 : "r"(a[0]), "r"(a[1]), "r"(a[2]), "r"(a[3]), "r"(b[0]), "r"(b[1]));
}

// ---------------- mbarrier helpers ----------------
__device__ __forceinline__ void mbar_init(uint32_t a, uint32_t cnt) {
    asm volatile("mbarrier.init.shared.b64 [%0], %1;" :: "r"(a), "r"(cnt) : "memory");
}
__device__ __forceinline__ void mbar_arrive(uint32_t a) {
    asm volatile("mbarrier.arrive.shared.b64 _, [%0];" :: "r"(a) : "memory");
}
__device__ __forceinline__ void mbar_wait(uint32_t a, uint32_t parity) {
    asm volatile(
        "{\n\t"
        ".reg .pred P1;\n\t"
        "WAIT_LOOP_%=:\n\t"
        "mbarrier.try_wait.parity.acquire.cta.shared::cta.b64 P1, [%0], %1, 0x989680;\n\t"
        "@P1 bra.uni WAIT_DONE_%=;\n\t"
        "bra.uni WAIT_LOOP_%=;\n\t"
        "WAIT_DONE_%=:\n\t"
        "}"
        :: "r"(a), "r"(parity) : "memory");
}
__device__ __forceinline__ void fence_proxy_async_shared() {
    asm volatile("fence.proxy.async.shared::cta;" ::: "memory");
}

// ---------------- fp32 -> fp16 plain convert (HMMA layout [K,N]) ----------------
__global__ void convert_kernel(const float* __restrict__ src, __half* __restrict__ dst, int n8) {
    int i = blockIdx.x * blockDim.x + threadIdx.x;
    if (i < n8) {
        float4 a = reinterpret_cast<const float4*>(src)[2*i];
        float4 b = reinterpret_cast<const float4*>(src)[2*i+1];
        union { __half2 h[4]; uint4 u; } o;
        o.h[0] = __floats2half2_rn(a.x, a.y);
        o.h[1] = __floats2half2_rn(a.z, a.w);
        o.h[2] = __floats2half2_rn(b.x, b.y);
        o.h[3] = __floats2half2_rn(b.z, b.w);
        reinterpret_cast<uint4*>(dst)[i] = o.u;
    }
}

// ---------------- transpose-convert tile body (TC layout [N,K]) ----------------
__device__ __forceinline__ void tconv_tile(const float* __restrict__ src, __half* __restrict__ dst,
                                           int Kdim, int Ndim, int kb, int nb,
                                           float (*tile)[65], int tid) {
    #pragma unroll
    for (int p = 0; p < 4; p++) {
        int i = p * 256 + tid;
        int r = i >> 4, c4 = i & 15;
        float4 v = *reinterpret_cast<const float4*>(src + (size_t)(kb + r) * Ndim + nb + c4 * 4);
        tile[r][c4*4+0] = v.x; tile[r][c4*4+1] = v.y;
        tile[r][c4*4+2] = v.z; tile[r][c4*4+3] = v.w;
    }
    __syncthreads();
    #pragma unroll
    for (int p = 0; p < 2; p++) {
        int i = p * 256 + tid;
        int r = i >> 3, c = i & 7;
        union { __half2 h[4]; uint4 u; } o;
        #pragma unroll
        for (int j = 0; j < 4; j++)
            o.h[j] = __floats2half2_rn(tile[c*8 + 2*j][r], tile[c*8 + 2*j + 1][r]);
        *reinterpret_cast<uint4*>(dst + (size_t)(nb + r) * Kdim + kb + c * 8) = o.u;
    }
}

// standalone transpose (unused in TC branch; kept for parity/testing)
__global__ void transpose_convert(const float* __restrict__ src, __half* __restrict__ dst,
                                  int Kdim, int Ndim) {
    __shared__ float tile[64][65];
    const size_t zoff = (size_t)blockIdx.z * Kdim * Ndim;
    tconv_tile(src + zoff, dst + zoff, Kdim, Ndim, blockIdx.x * 64, blockIdx.y * 64,
               tile, threadIdx.x);
}

// ---------------- router ----------------
__global__ void router_kernel(const float* __restrict__ x, const float* __restrict__ Wr) {
    __shared__ float sWr[EE*DD];
    int tid = threadIdx.x;
    for (int i = tid; i < EE*DD; i += 256) sWr[i] = Wr[i];
    __syncthreads();
    int w = tid >> 5, lane = tid & 31;
    int t = blockIdx.x * 8 + w;
    const float* xr = x + (size_t)t * DD;
    float acc[EE];
    #pragma unroll
    for (int e = 0; e < EE; e++) acc[e] = 0.f;
    for (int d = lane; d < DD; d += 32) {
        float xv = xr[d];
        #pragma unroll
        for (int e = 0; e < EE; e++) acc[e] += xv * sWr[e*DD + d];
    }
    #pragma unroll
    for (int e = 0; e < EE; e++)
        #pragma unroll
        for (int o = 16; o > 0; o >>= 1) acc[e] += __shfl_xor_sync(0xffffffffu, acc[e], o);
    if (lane == 0) {
        float m = acc[0];
        #pragma unroll
        for (int e = 1; e < EE; e++) m = fmaxf(m, acc[e]);
        float p[EE], s = 0.f;
        #pragma unroll
        for (int e = 0; e < EE; e++) { p[e] = expf(acc[e] - m); s += p[e]; }
        #pragma unroll
        for (int e = 0; e < EE; e++) p[e] /= s;
        int i1 = 0;
        #pragma unroll
        for (int e = 1; e < EE; e++) if (p[e] > p[i1]) i1 = e;
        int i2 = -1;
        #pragma unroll
        for (int e = 0; e < EE; e++) if (e != i1 && (i2 < 0 || p[e] > p[i2])) i2 = e;
        float ssum = p[i1] + p[i2];
        if (ssum < 1e-9f) ssum = 1e-9f;
        g_top2e[2*t] = i1; g_top2e[2*t+1] = i2;
        g_top2w[2*t] = p[i1] / ssum; g_top2w[2*t+1] = p[i2] / ssum;
    }
}

// ---------------- sequential capacity assignment ----------------
__global__ void assign_kernel() {
    int tid = threadIdx.x, lane = tid & 31, wid = tid >> 5;
    __shared__ int wsum[32];
    int e0[8], e1[8];
    bool fb[8];
    #pragma unroll
    for (int i = 0; i < 8; i++) {
        int t = tid * 8 + i;
        e0[i] = g_top2e[2*t]; e1[i] = g_top2e[2*t+1];
        fb[i] = false;
    }
    for (int e = 0; e < EE; e++) {
        bool elig[8]; int cnt = 0;
        #pragma unroll
        for (int i = 0; i < 8; i++) {
            elig[i] = (!fb[i]) && (e0[i] == e || e1[i] == e);
            cnt += elig[i] ? 1 : 0;
        }
        int inc = cnt;
        #pragma unroll
        for (int o = 1; o < 32; o <<= 1) { int v = __shfl_up_sync(0xffffffffu, inc, o); if (lane >= o) inc += v; }
        if (lane == 31) wsum[wid] = inc;
        __syncthreads();
        if (wid == 0) {
            int v = wsum[lane];
            int inc2 = v;
            #pragma unroll
            for (int o = 1; o < 32; o <<= 1) { int u = __shfl_up_sync(0xffffffffu, inc2, o); if (lane >= o) inc2 += u; }
            wsum[lane] = inc2;
        }
        __syncthreads();
        int pos = inc - cnt + (wid ? wsum[wid-1] : 0);
        int total = wsum[31];
        if (tid == 0) g_counts[e] = (total < CAPACITY) ? total : CAPACITY;
        #pragma unroll
        for (int i = 0; i < 8; i++) {
            if (elig[i]) {
                int t = tid * 8 + i;
                if (pos < CAPACITY) {
                    int k = (e0[i] == e) ? 0 : 1;
                    g_slot[2*t + k] = pos;
                    g_idx[e*CAPACITY + pos] = t;
                } else {
                    fb[i] = true;
                }
                pos++;
            }
        }
        __syncthreads();
    }
    int cnt = 0;
    #pragma unroll
    for (int i = 0; i < 8; i++) cnt += fb[i] ? 1 : 0;
    int inc = cnt;
    #pragma unroll
    for (int o = 1; o < 32; o <<= 1) { int v = __shfl_up_sync(0xffffffffu, inc, o); if (lane >= o) inc += v; }
    if (lane == 31) wsum[wid] = inc;
    __syncthreads();
    if (wid == 0) {
        int v = wsum[lane];
        int inc2 = v;
        #pragma unroll
        for (int o = 1; o < 32; o <<= 1) { int u = __shfl_up_sync(0xffffffffu, inc2, o); if (lane >= o) inc2 += u; }
        wsum[lane] = inc2;
    }
    __syncthreads();
    int pos = inc - cnt + (wid ? wsum[wid-1] : 0);
    #pragma unroll
    for (int i = 0; i < 8; i++) {
        int t = tid * 8 + i;
        g_fbflag[t] = fb[i] ? 1 : 0;
        if (fb[i]) { g_fbidx[pos] = t; g_fbslot[t] = pos; pos++; }
    }
    if (tid == 0) g_fbcount = wsum[31];
}

// ---------------- gather body ----------------
__device__ __forceinline__ void gather_body(const float* __restrict__ x, int r, int i) {
    int t;
    __half* dstrow;
    if (r < RR) {
        int e = r / CAPACITY;
        if (r - e*CAPACITY >= g_counts[e]) return;
        t = g_idx[r];
        dstrow = g_Xg + (size_t)r * DD;
    } else {
        int rr = r - RR;
        if (rr >= g_fbcount) return;
        t = g_fbidx[rr];
        dstrow = g_Xfb + (size_t)rr * DD;
    }
    const float4* src = reinterpret_cast<const float4*>(x + (size_t)t * DD);
    __half2* dst = reinterpret_cast<__half2*>(dstrow);
    float4 v = src[i];
    dst[2*i]   = __floats2half2_rn(v.x, v.y);
    dst[2*i+1] = __floats2half2_rn(v.z, v.w);
}

__global__ void gather_all(const float* __restrict__ x) {
    gather_body(x, blockIdx.x, threadIdx.x);
}

// ---------------- mega-prep: gather + all 4 transpose-converts in ONE launch ----------------
#define MP_GATHER (RR + TT)                  // 28672
#define MP_W1     (16*64*EE)                 // 8192
#define MP_W2     (64*16*EE)                 // 8192
#define MP_FW1    (16*64)                    // 1024
#define MP_FW2    (64*16)                    // 1024
#define MP_TOTAL  (MP_GATHER + MP_W1 + MP_W2 + MP_FW1 + MP_FW2)

__global__ void megaprep(const float* __restrict__ x,
                         const float* __restrict__ W1, const float* __restrict__ W2,
                         const float* __restrict__ fw1, const float* __restrict__ fw2) {
    __shared__ float tile[64][65];
    int b = blockIdx.x, tid = threadIdx.x;
    if (b < MP_GATHER) { gather_body(x, b, tid); return; }
    b -= MP_GATHER;
    if (b < MP_W1) {     // W1 [E][DD,II] -> [E][II,DD]  (Kdim=DD, Ndim=II)
        int kb = (b & 15) * 64;
        int t2 = b >> 4;
        int nb = (t2 & 63) * 64;
        int z  = t2 >> 6;
        tconv_tile(W1 + (size_t)z*DD*II, g_W1f + (size_t)z*DD*II, DD, II, kb, nb, tile, tid);
        return;
    }
    b -= MP_W1;
    if (b < MP_W2) {     // W2 [E][II,DD] -> [E][DD,II]  (Kdim=II, Ndim=DD)
        int kb = (b & 63) * 64;
        int t2 = b >> 6;
        int nb = (t2 & 15) * 64;
        int z  = t2 >> 4;
        tconv_tile(W2 + (size_t)z*II*DD, g_W2f + (size_t)z*II*DD, II, DD, kb, nb, tile, tid);
        return;
    }
    b -= MP_W2;
    if (b < MP_FW1) {    // fw1 [DD,II] -> [II,DD]
        int kb = (b & 15) * 64;
        int nb = (b >> 4) * 64;
        tconv_tile(fw1, g_fw1f, DD, II, kb, nb, tile, tid);
        return;
    }
    b -= MP_FW1;
    {                    // fw2 [II,DD] -> [DD,II]
        int kb = (b & 63) * 64;
        int nb = (b >> 6) * 64;
        tconv_tile(fw2, g_fw2f, II, DD, kb, nb, tile, tid);
    }
}

// ============================================================================
// Path A: tcgen05 GEMM, M=256 per CTA, experts + fallback fused via blockIdx.z
// PHASE 1: X@W1 + b -> gelu -> H (fp16);  PHASE 2: H@W2 + b -> Y (fp16)
// z in [0,EE): expert z; z == EE: fallback FFN
// ============================================================================
#define TCBM 256
#define TCBN 256
#define BKH 64
#define NSTG 3
#define TC_A2 32768
#define TC_STGB 65536
#define SM_TILE0 1024
#define TC_SMEM (SM_TILE0 + NSTG*TC_STGB)   // 197632

#define IDESC_F16_128x256 ((1u<<4) | (32u<<17) | (8u<<24))

#if TC_PATH
static __device__ __forceinline__ uint64_t make_desc(uint32_t addr) {
    const uint64_t base =
        (uint64_t(2)  << 61) | (uint64_t(1) << 46) | (uint64_t(64) << 32) | (uint64_t(1) << 16);
    return base | ((uint64_t)(addr >> 4) & 0x3FFF);
}
__device__ __forceinline__ void mma_f16_ss(uint32_t d_tmem, uint64_t adesc, uint64_t bdesc,
                                           uint32_t idesc, bool accum) {
    uint32_t en = accum ? 1u : 0u;
    asm volatile(
        "{\n\t"
        ".reg .pred p;\n\t"
        "setp.ne.u32 p, %5, 0;\n\t"
        "tcgen05.mma.cta_group::1.kind::f16 [%0], %1, %2, %3, {%4, %4, %4, %4}, p;\n\t"
        "}"
        :: "r"(d_tmem), "l"(adesc), "l"(bdesc), "r"(idesc), "r"(0u), "r"(en)
        : "memory");
}
#define TC_LD32(r, addr) \
    asm volatile( \
        "tcgen05.ld.sync.aligned.32x32b.x32.b32 " \
        "{%0, %1, %2, %3, %4, %5, %6, %7, " \
        " %8, %9, %10, %11, %12, %13, %14, %15, " \
        " %16, %17, %18, %19, %20, %21, %22, %23, " \
        " %24, %25, %26, %27, %28, %29, %30, %31}, [%32];" \
        : "=r"((r)[0]),  "=r"((r)[1]),  "=r"((r)[2]),  "=r"((r)[3]), \
          "=r"((r)[4]),  "=r"((r)[5]),  "=r"((r)[6]),  "=r"((r)[7]), \
          "=r"((r)[8]),  "=r"((r)[9]),  "=r"((r)[10]), "=r"((r)[11]), \
          "=r"((r)[12]), "=r"((r)[13]), "=r"((r)[14]), "=r"((r)[15]), \
          "=r"((r)[16]), "=r"((r)[17]), "=r"((r)[18]), "=r"((r)[19]), \
          "=r"((r)[20]), "=r"((r)[21]), "=r"((r)[22]), "=r"((r)[23]), \
          "=r"((r)[24]), "=r"((r)[25]), "=r"((r)[26]), "=r"((r)[27]), \
          "=r"((r)[28]), "=r"((r)[29]), "=r"((r)[30]), "=r"((r)[31]) \
        : "r"(addr))
#endif

template<int PHASE>
__global__ void __launch_bounds__(256, 1) gemm_tc5(const float* __restrict__ bias_e,
                                                   const float* __restrict__ bias_f) {
#if TC_PATH
    constexpr bool G1 = (PHASE == 1);
    constexpr int K = G1 ? DD : II;
    constexpr int N = G1 ? II : DD;
    constexpr int KT = K / BKH;

    const int z = blockIdx.z;
    const bool FB = (z == EE);
    const int count = FB ? g_fbcount : g_counts[z];
    const int m0 = blockIdx.y * TCBM;
    if (m0 >= count) return;
    const int n0 = blockIdx.x * TCBN;

    const __half* __restrict__ A;
    const __half* __restrict__ B;
    if constexpr (G1) {
        A = FB ? g_Xfb : g_Xg + (size_t)z*CAPACITY*DD;
        B = FB ? g_fw1f : g_W1f + (size_t)z*DD*II;
    } else {
        A = FB ? g_Hfb : g_H + (size_t)z*CAPACITY*II;
        B = FB ? g_fw2f : g_W2f + (size_t)z*II*DD;
    }
    const float* biasp = FB ? bias_f : bias_e + (size_t)z*N;

    extern __shared__ char smem[];
    const uint32_t sb = smem_u32(smem);
    const int tid = threadIdx.x, lane = tid & 31, wid = tid >> 5;

    const uint32_t mb_full0 = sb + 64, mb_empty0 = sb + 96, mb_done = sb + 120;
    if (tid == 0) {
        #pragma unroll
        for (int s = 0; s < NSTG; s++) {
            mbar_init(mb_full0 + 8*s, 224);
            mbar_init(mb_empty0 + 8*s, 1);
        }
        mbar_init(mb_done, 1);
    }
    if (wid == 0) {
        asm volatile("tcgen05.alloc.cta_group::1.sync.aligned.shared::cta.b32 [%0], %1;"
                     :: "r"(sb), "r"(512) : "memory");
    }
    __syncthreads();
    uint32_t tb;
    asm volatile("ld.shared.b32 %0, [%1];" : "=r"(tb) : "r"(sb));

    if (wid == 0) {
        if (lane == 0) {
            uint64_t ad0[NSTG], ad1[NSTG], bd[NSTG];
            #pragma unroll
            for (int s = 0; s < NSTG; s++) {
                uint32_t base = sb + SM_TILE0 + s*TC_STGB;
                ad0[s] = make_desc(base);
                ad1[s] = make_desc(base + 16384);
                bd[s]  = make_desc(base + TC_A2);
            }
            #pragma unroll 1
            for (int kt = 0; kt < KT; kt++) {
                int st = kt % NSTG;
                uint32_t ph = (kt / NSTG) & 1;
                mbar_wait(mb_full0 + 8*st, ph);
                asm volatile("tcgen05.fence::after_thread_sync;" ::: "memory");
                #pragma unroll
                for (int k = 0; k < 4; k++) {
                    bool acc = (kt > 0) || (k > 0);
                    mma_f16_ss(tb,       ad0[st] + k*2, bd[st] + k*2, IDESC_F16_128x256, acc);
                    mma_f16_ss(tb + 256, ad1[st] + k*2, bd[st] + k*2, IDESC_F16_128x256, acc);
                }
                asm volatile("tcgen05.commit.cta_group::1.mbarrier::arrive::one.shared::cluster.b64 [%0];"
                             :: "r"(mb_empty0 + 8*st) : "memory");
            }
            asm volatile("tcgen05.commit.cta_group::1.mbarrier::arrive::one.shared::cluster.b64 [%0];"
                         :: "r"(mb_done) : "memory");
        }
    } else {
        const int ptid = tid - 32;
        #pragma unroll 1
        for (int kt = 0; kt < KT; kt++) {
            int st = kt % NSTG;
            uint32_t eph = ((kt / NSTG) & 1) ^ 1u;
            mbar_wait(mb_empty0 + 8*st, eph);
            uint32_t aB = sb + SM_TILE0 + st*TC_STGB;
            uint32_t bB = aB + TC_A2;
            const __half* Ak = A + (size_t)m0 * K + kt * BKH;
            const __half* Bk = B + (size_t)n0 * K + kt * BKH;
            #pragma unroll 1
            for (int i = ptid; i < 4096; i += 224) {
                if (i < 2048) {
                    int r = i >> 3, c = i & 7;
                    cpasync16(aB + (uint32_t)(r*128 + ((c ^ (r & 7)) << 4)), Ak + (size_t)r*K + c*8);
                } else {
                    int j = i - 2048;
                    int r = j >> 3, c = j & 7;
                    cpasync16(bB + (uint32_t)(r*128 + ((c ^ (r & 7)) << 4)), Bk + (size_t)r*K + c*8);
                }
            }
            cpasync_commit();
            if (kt > 0) {
                cpasync_wait1();
                fence_proxy_async_shared();
                mbar_arrive(mb_full0 + 8*((kt-1) % NSTG));
            }
        }
        cpasync_wait0();
        fence_proxy_async_shared();
        mbar_arrive(mb_full0 + 8*((KT-1) % NSTG));
    }

    mbar_wait(mb_done, 0);
    asm volatile("tcgen05.fence::after_thread_sync;" ::: "memory");

    // epilogue: warps 0-3 -> m-tile 0 (TMEM cols 0-255), warps 4-7 -> m-tile 1 (256-511)
    {
        const int mtile = wid >> 2;
        const int lw = wid & 3;
        const int row = m0 + mtile*128 + lw*32 + lane;
        const uint32_t coff = (uint32_t)mtile * 256;
        __half* outp;
        if constexpr (G1)
            outp = (FB ? g_Hfb : g_H + (size_t)z*CAPACITY*II) + (size_t)row * II;
        else
            outp = (FB ? g_Yfbh : g_Yeh + (size_t)z*CAPACITY*DD) + (size_t)row * DD;
        #pragma unroll 1
        for (int cb = 0; cb < 8; cb++) {
            uint32_t r[32];
            TC_LD32(r, tb + coff + cb*32);
            asm volatile("tcgen05.wait::ld.sync.aligned;" ::: "memory");
            int c0 = n0 + cb*32;
            union { __half2 h[16]; uint4 u[4]; } o;
            #pragma unroll
            for (int j = 0; j < 16; j++) {
                float v0 = __uint_as_float(r[2*j])   + __ldg(biasp + c0 + 2*j);
                float v1 = __uint_as_float(r[2*j+1]) + __ldg(biasp + c0 + 2*j + 1);
                if constexpr (G1) { v0 = gelu_exact(v0); v1 = gelu_exact(v1); }
                o.h[j] = __floats2half2_rn(v0, v1);
            }
            uint4* dst = reinterpret_cast<uint4*>(outp + c0);
            dst[0] = o.u[0]; dst[1] = o.u[1]; dst[2] = o.u[2]; dst[3] = o.u[3];
        }
    }
    __syncthreads();
    if (wid == 0) {
        asm volatile("tcgen05.relinquish_alloc_permit.cta_group::1.sync.aligned;");
        asm volatile("tcgen05.dealloc.cta_group::1.sync.aligned.b32 %0, %1;" :: "r"(tb), "r"(512));
    }
#endif
}

// ============================================================================
// Path B: HMMA GEMM fallback ([K,N] weights), 128x128 tiles, 3-stage
// ============================================================================
#define BM 128
#define BN 128
#define HM_STGB 32768
#define HM_SMEM (3*HM_STGB)

template<int MODE>
__global__ void gemm_hmma(const float* __restrict__ bias) {
    constexpr bool G1 = (MODE < 2);
    constexpr bool FB = (MODE & 1);
    constexpr int K = G1 ? DD : II;
    constexpr int N = G1 ? II : DD;
    constexpr int KT = K / BKH;

    const int e = blockIdx.z;
    const int count = FB ? g_fbcount : g_counts[e];
    const int m0 = blockIdx.y * BM;
    if (m0 >= count) return;
    const int n0 = blockIdx.x * BN;

    const __half* __restrict__ Aexp;
    const __half* __restrict__ Bexp;
    if constexpr (MODE == 0) { Aexp = g_Xg  + (size_t)e*CAPACITY*K; Bexp = g_W1f + (size_t)e*K*II; }
    if constexpr (MODE == 1) { Aexp = g_Xfb;                        Bexp = g_fw1f; }
    if constexpr (MODE == 2) { Aexp = g_H   + (size_t)e*CAPACITY*K; Bexp = g_W2f + (size_t)e*K*DD; }
    if constexpr (MODE == 3) { Aexp = g_Hfb;                        Bexp = g_fw2f; }
    const float* biasp = bias + (FB ? 0 : (size_t)e*N);

    extern __shared__ __half smemh[];
    const uint32_t sbase = smem_u32(smemh);
    const int tid = threadIdx.x, lane = tid & 31, wid = tid >> 5;
    const int wm = wid & 1, wn = wid >> 1;
    const int g = lane >> 3, rin = lane & 7;

    float acc[4][4][4];
    #pragma unroll
    for (int a = 0; a < 4; a++)
        #pragma unroll
        for (int b = 0; b < 4; b++)
            #pragma unroll
            for (int c = 0; c < 4; c++) acc[a][b][c] = 0.f;

    auto loadStage = [&](int kt, int st) {
        if (kt < KT) {
            uint32_t aB = sbase + st * HM_STGB;
            uint32_t bB = aB + 16384;
            #pragma unroll
            for (int j = 0; j < 4; j++) {
                int id = j * 256 + tid;
                int r = id >> 3, c = id & 7;
                const __half* src = Aexp + (size_t)(m0 + r) * K + kt * BKH + c * 8;
                uint32_t dst = aB + (uint32_t)(r * 64 + ((c ^ (r & 7)) << 3)) * 2;
                cpasync16(dst, src);
            }
            #pragma unroll
            for (int j = 0; j < 4; j++) {
                int id = j * 256 + tid;
                int r = id >> 4, c = id & 15;
                const __half* src = Bexp + (size_t)(kt * BKH + r) * N + n0 + c * 8;
                uint32_t dst = bB + (uint32_t)(r * 128 + (((c & 8) | ((c ^ r) & 7)) << 3)) * 2;
                cpasync16(dst, src);
            }
        }
        cpasync_commit();
    };

    loadStage(0, 0);
    loadStage(1, 1);
    int st = 0;
    #pragma unroll 1
    for (int kt = 0; kt < KT; kt++) {
        cpasync_wait1();
        __syncthreads();
        loadStage(kt + 2, (st + 2) % 3);
        uint32_t aB = sbase + st * HM_STGB;
        uint32_t bB = aB + 16384;
        #pragma unroll
        for (int ks = 0; ks < 4; ks++) {
            uint32_t afr[4][4];
            #pragma unroll
            for (int mt = 0; mt < 4; mt++) {
                int row = wm * 64 + mt * 16 + (g & 1) * 8 + rin;
                int ch = (ks * 2 + (g >> 1)) ^ rin;
                ldmatrix_x4(afr[mt], aB + (uint32_t)(row * 64 + ch * 8) * 2);
            }
            uint32_t bfr[4][2];
            #pragma unroll
            for (int ht = 0; ht < 2; ht++) {
                int row = ks * 16 + (g & 1) * 8 + rin;
                int c = wn * 4 + ht * 2 + (g >> 1);
                int ph = (c & 8) | ((c & 7) ^ rin);
                uint32_t r4[4];
                ldmatrix_x4_trans(r4, bB + (uint32_t)(row * 128 + ph * 8) * 2);
                bfr[ht*2][0] = r4[0]; bfr[ht*2][1] = r4[1];
                bfr[ht*2+1][0] = r4[2]; bfr[ht*2+1][1] = r4[3];
            }
            #pragma unroll
            for (int mt = 0; mt < 4; mt++)
                #pragma unroll
                for (int nt = 0; nt < 4; nt++)
                    mma16816(acc[mt][nt], afr[mt], bfr[nt]);
        }
        st = (st + 1) % 3;
    }

    const int growb = m0 + wm * 64;
    const int gcolb = n0 + wn * 32;
    #pragma unroll
    for (int mt = 0; mt < 4; mt++) {
        #pragma unroll
        for (int nt = 0; nt < 4; nt++) {
            int r0 = growb + mt * 16 + (lane >> 2);
            int c0 = gcolb + nt * 8 + (lane & 3) * 2;
            float b0f = biasp[c0], b1f = biasp[c0 + 1];
            float x0 = acc[mt][nt][0] + b0f, x1 = acc[mt][nt][1] + b1f;
            float x2 = acc[mt][nt][2] + b0f, x3 = acc[mt][nt][3] + b1f;
            if constexpr (G1) {
                __half* Hout = FB ? g_Hfb : (g_H + (size_t)e*CAPACITY*N);
                *reinterpret_cast<__half2*>(Hout + (size_t)r0 * N + c0) =
                    __floats2half2_rn(gelu_exact(x0), gelu_exact(x1));
                *reinterpret_cast<__half2*>(Hout + (size_t)(r0 + 8) * N + c0) =
                    __floats2half2_rn(gelu_exact(x2), gelu_exact(x3));
            } else {
                __half* Yout = FB ? g_Yfbh : (g_Yeh + (size_t)e*CAPACITY*N);
                *reinterpret_cast<__half2*>(Yout + (size_t)r0 * N + c0) =
                    __floats2half2_rn(x0, x1);
                *reinterpret_cast<__half2*>(Yout + (size_t)(r0 + 8) * N + c0) =
                    __floats2half2_rn(x2, x3);
            }
        }
    }
}

// ---------------- final combine (fp16 expert outputs) ----------------
__global__ void combine_kernel(float* __restrict__ out) {
    int t = blockIdx.x;
    int i = threadIdx.x;   // 256 threads * 4 elements
    float4* o = reinterpret_cast<float4*>(out + (size_t)t * DD);
    if (g_fbflag[t]) {
        const uint2 hv = reinterpret_cast<const uint2*>(g_Yfbh + (size_t)g_fbslot[t] * DD)[i];
        float2 a0 = __half22float2(*reinterpret_cast<const __half2*>(&hv.x));
        float2 a1 = __half22float2(*reinterpret_cast<const __half2*>(&hv.y));
        float4 v; v.x = a0.x; v.y = a0.y; v.z = a1.x; v.w = a1.y;
        o[i] = v;
    } else {
        int e0 = g_top2e[2*t], e1 = g_top2e[2*t+1];
        float w0 = g_top2w[2*t], w1 = g_top2w[2*t+1];
        size_t r0 = (size_t)(e0 * CAPACITY + g_slot[2*t]) * DD;
        size_t r1 = (size_t)(e1 * CAPACITY + g_slot[2*t+1]) * DD;
        uint2 av = reinterpret_cast<const uint2*>(g_Yeh + r0)[i];
        uint2 bv = reinterpret_cast<const uint2*>(g_Yeh + r1)[i];
        float2 a0 = __half22float2(*reinterpret_cast<const __half2*>(&av.x));
        float2 a1 = __half22float2(*reinterpret_cast<const __half2*>(&av.y));
        float2 b0 = __half22float2(*reinterpret_cast<const __half2*>(&bv.x));
        float2 b1 = __half22float2(*reinterpret_cast<const __half2*>(&bv.y));
        float4 v;
        v.x = w0 * a0.x + w1 * b0.x;
        v.y = w0 * a0.y + w1 * b0.y;
        v.z = w0 * a1.x + w1 * b1.x;
        v.w = w0 * a1.y + w1 * b1.y;
        o[i] = v;
    }
}

// ---------------- launch ----------------
extern "C" void kernel_launch(void* const* d_in, const int* in_sizes, int n_in,
                              void* d_out, int out_size) {
    const float* x   = (const float*)d_in[0];
    const float* Wr  = (const float*)d_in[1];
    const float* W1  = (const float*)d_in[2];
    const float* b1  = (const float*)d_in[3];
    const float* W2  = (const float*)d_in[4];
    const float* b2  = (const float*)d_in[5];
    const float* fw1 = (const float*)d_in[6];
    const float* fb1 = (const float*)d_in[7];
    const float* fw2 = (const float*)d_in[8];
    const float* fb2 = (const float*)d_in[9];
    float* out = (float*)d_out;

    __half* dW1;  cudaGetSymbolAddress((void**)&dW1,  g_W1f);
    __half* dW2;  cudaGetSymbolAddress((void**)&dW2,  g_W2f);
    __half* dfw1; cudaGetSymbolAddress((void**)&dfw1, g_fw1f);
    __half* dfw2; cudaGetSymbolAddress((void**)&dfw2, g_fw2f);

    cudaFuncAttributes fa{};
    cudaFuncGetAttributes(&fa, (const void*)gemm_tc5<1>);
    const bool use_tc = (fa.numRegs >= 24);

    if (use_tc) {
        cudaFuncSetAttribute(gemm_tc5<1>, cudaFuncAttributeMaxDynamicSharedMemorySize, TC_SMEM);
        cudaFuncSetAttribute(gemm_tc5<2>, cudaFuncAttributeMaxDynamicSharedMemorySize, TC_SMEM);
        router_kernel<<<TT/8, 256>>>(x, Wr);                               // 0
        assign_kernel<<<1, 1024>>>();                                      // 1
        megaprep<<<MP_TOTAL, 256>>>(x, W1, W2, fw1, fw2);                  // 2
        gemm_tc5<1><<<dim3(II/TCBN, TT/TCBM, EE+1), 256, TC_SMEM>>>(b1, fb1); // 3
        gemm_tc5<2><<<dim3(DD/TCBN, TT/TCBM, EE+1), 256, TC_SMEM>>>(b2, fb2); // 4
        combine_kernel<<<TT, 256>>>(out);                                  // 5
    } else {
        cudaFuncSetAttribute(gemm_hmma<0>, cudaFuncAttributeMaxDynamicSharedMemorySize, HM_SMEM);
        cudaFuncSetAttribute(gemm_hmma<1>, cudaFuncAttributeMaxDynamicSharedMemorySize, HM_SMEM);
        cudaFuncSetAttribute(gemm_hmma<2>, cudaFuncAttributeMaxDynamicSharedMemorySize, HM_SMEM);
        cudaFuncSetAttribute(gemm_hmma<3>, cudaFuncAttributeMaxDynamicSharedMemorySize, HM_SMEM);
        router_kernel<<<TT/8, 256>>>(x, Wr);
        convert_kernel<<<(EE*DD*II/8 + 255)/256, 256>>>(W1, dW1, EE*DD*II/8);
        convert_kernel<<<(EE*II*DD/8 + 255)/256, 256>>>(W2, dW2, EE*II*DD/8);
        assign_kernel<<<1, 1024>>>();
        gather_all<<<RR + TT, 256>>>(x);
        gemm_hmma<0><<<dim3(II/BN, CAPACITY/BM, EE), 256, HM_SMEM>>>(b1);
        gemm_hmma<2><<<dim3(DD/BN, CAPACITY/BM, EE), 256, HM_SMEM>>>(b2);
        convert_kernel<<<(DD*II/8 + 255)/256, 256>>>(fw1, dfw1, DD*II/8);
        gemm_hmma<1><<<dim3(II/BN, TT/BM, 1), 256, HM_SMEM>>>(fb1);
        convert_kernel<<<(II*DD/8 + 255)/256, 256>>>(fw2, dfw2, II*DD/8);
        gemm_hmma<3><<<dim3(DD/BN, TT/BM, 1), 256, HM_SMEM>>>(fb2);
    }

    combine_kernel<<<TT, 256>>>(out);
}

// round 12
// speedup vs baseline: 2.0106x; 1.3598x over previous
#include <cuda_runtime.h>
#include <cuda_fp16.h>
#include <cstdint>

// ---------------- problem constants ----------------
#define TT   8192
#define DD   1024
#define II   4096
#define EE   8
#define CAPACITY 2560
#define RR   (EE*CAPACITY)

// arch-specific (sm_103a/sm_100a) feature gate for tcgen05
#if defined(__CUDA_ARCH__) && (defined(__CUDA_ARCH_FEAT_SM103_ALL) || defined(__CUDA_ARCH_FEAT_SM100_ALL) || defined(__CUDA_ARCH_SPECIFIC__) || defined(__CUDA_ARCH_FAMILY_SPECIFIC__))
#define TC_PATH 1
#else
#define TC_PATH 0
#endif

// ---------------- device scratch ----------------
__device__ __half g_W1f[(size_t)EE*DD*II];
__device__ __half g_W2f[(size_t)EE*II*DD];
__device__ __half g_fw1f[(size_t)DD*II];
__device__ __half g_fw2f[(size_t)II*DD];
__device__ __half g_Xg [(size_t)RR*DD];
__device__ __half g_Xfb[(size_t)TT*DD];
__device__ __half g_H  [(size_t)RR*II];
__device__ __half g_Hfb[(size_t)TT*II];
__device__ __half g_Yeh [(size_t)RR*DD];
__device__ __half g_Yfbh[(size_t)TT*DD];
__device__ int    g_top2e[TT*2];
__device__ float  g_top2w[TT*2];
__device__ int    g_slot [TT*2];
__device__ int    g_fbslot[TT];
__device__ int    g_fbidx [TT];
__device__ unsigned char g_fbflag[TT];
__device__ int    g_counts[EE];
__device__ int    g_fbcount;
__device__ int    g_idx[RR];

// ---------------- generic helpers ----------------
__device__ __forceinline__ float gelu_exact(float v) {
    return 0.5f * v * (1.0f + erff(v * 0.7071067811865475f));
}
__device__ __forceinline__ void cpasync16(uint32_t dst, const void* src) {
    asm volatile("cp.async.cg.shared.global [%0], [%1], 16;\n" :: "r"(dst), "l"(src));
}
__device__ __forceinline__ void cpasync_commit() { asm volatile("cp.async.commit_group;\n"); }
__device__ __forceinline__ void cpasync_wait0() { asm volatile("cp.async.wait_group 0;\n"); }
__device__ __forceinline__ void cpasync_wait1() { asm volatile("cp.async.wait_group 1;\n"); }

__device__ __forceinline__ uint32_t smem_u32(const void* p) {
    uint32_t a;
    asm("{ .reg .u64 t; cvta.to.shared.u64 t, %1; cvt.u32.u64 %0, t; }" : "=r"(a) : "l"(p));
    return a;
}
__device__ __forceinline__ void ldmatrix_x4(uint32_t* r, uint32_t addr) {
    asm volatile("ldmatrix.sync.aligned.m8n8.x4.shared.b16 {%0,%1,%2,%3}, [%4];"
                 : "=r"(r[0]), "=r"(r[1]), "=r"(r[2]), "=r"(r[3]) : "r"(addr));
}
__device__ __forceinline__ void ldmatrix_x4_trans(uint32_t* r, uint32_t addr) {
    asm volatile("ldmatrix.sync.aligned.m8n8.x4.trans.shared.b16 {%0,%1,%2,%3}, [%4];"
                 : "=r"(r[0]), "=r"(r[1]), "=r"(r[2]), "=r"(r[3]) : "r"(addr));
}
__device__ __forceinline__ void mma16816(float* c, const uint32_t* a, const uint32_t* b) {
    asm volatile("mma.sync.aligned.m16n8k16.row.col.f32.f16.f16.f32 "
                 "{%0,%1,%2,%3},{%4,%5,%6,%7},{%8,%9},{%0,%1,%2,%3};"
                 : "+f"(c[0]), "+f"(c[1]), "+f"(c[2]), "+f"(c[3])
                 : "r"(a[0]), "r"(a[1]), "r"(a[2]), "r"(a[3]), "r"(b[0]), "r"(b[1]));
}

// ---------------- mbarrier helpers ----------------
__device__ __forceinline__ void mbar_init(uint32_t a, uint32_t cnt) {
    asm volatile("mbarrier.init.shared.b64 [%0], %1;" :: "r"(a), "r"(cnt) : "memory");
}
__device__ __forceinline__ void mbar_arrive(uint32_t a) {
    asm volatile("mbarrier.arrive.shared.b64 _, [%0];" :: "r"(a) : "memory");
}
__device__ __forceinline__ void mbar_wait(uint32_t a, uint32_t parity) {
    asm volatile(
        "{\n\t"
        ".reg .pred P1;\n\t"
        "WAIT_LOOP_%=:\n\t"
        "mbarrier.try_wait.parity.acquire.cta.shared::cta.b64 P1, [%0], %1, 0x989680;\n\t"
        "@P1 bra.uni WAIT_DONE_%=;\n\t"
        "bra.uni WAIT_LOOP_%=;\n\t"
        "WAIT_DONE_%=:\n\t"
        "}"
        :: "r"(a), "r"(parity) : "memory");
}
__device__ __forceinline__ void fence_proxy_async_shared() {
    asm volatile("fence.proxy.async.shared::cta;" ::: "memory");
}

// ---------------- fp32 -> fp16 plain convert (HMMA layout [K,N]) ----------------
__global__ void convert_kernel(const float* __restrict__ src, __half* __restrict__ dst, int n8) {
    int i = blockIdx.x * blockDim.x + threadIdx.x;
    if (i < n8) {
        float4 a = reinterpret_cast<const float4*>(src)[2*i];
        float4 b = reinterpret_cast<const float4*>(src)[2*i+1];
        union { __half2 h[4]; uint4 u; } o;
        o.h[0] = __floats2half2_rn(a.x, a.y);
        o.h[1] = __floats2half2_rn(a.z, a.w);
        o.h[2] = __floats2half2_rn(b.x, b.y);
        o.h[3] = __floats2half2_rn(b.z, b.w);
        reinterpret_cast<uint4*>(dst)[i] = o.u;
    }
}

// ---------------- transpose-convert tile body (TC layout [N,K]) ----------------
__device__ __forceinline__ void tconv_tile(const float* __restrict__ src, __half* __restrict__ dst,
                                           int Kdim, int Ndim, int kb, int nb,
                                           float (*tile)[65], int tid) {
    #pragma unroll
    for (int p = 0; p < 4; p++) {
        int i = p * 256 + tid;
        int r = i >> 4, c4 = i & 15;
        float4 v = *reinterpret_cast<const float4*>(src + (size_t)(kb + r) * Ndim + nb + c4 * 4);
        tile[r][c4*4+0] = v.x; tile[r][c4*4+1] = v.y;
        tile[r][c4*4+2] = v.z; tile[r][c4*4+3] = v.w;
    }
    __syncthreads();
    #pragma unroll
    for (int p = 0; p < 2; p++) {
        int i = p * 256 + tid;
        int r = i >> 3, c = i & 7;
        union { __half2 h[4]; uint4 u; } o;
        #pragma unroll
        for (int j = 0; j < 4; j++)
            o.h[j] = __floats2half2_rn(tile[c*8 + 2*j][r], tile[c*8 + 2*j + 1][r]);
        *reinterpret_cast<uint4*>(dst + (size_t)(nb + r) * Kdim + kb + c * 8) = o.u;
    }
}

__global__ void transpose_convert(const float* __restrict__ src, __half* __restrict__ dst,
                                  int Kdim, int Ndim) {
    __shared__ float tile[64][65];
    const size_t zoff = (size_t)blockIdx.z * Kdim * Ndim;
    tconv_tile(src + zoff, dst + zoff, Kdim, Ndim, blockIdx.x * 64, blockIdx.y * 64,
               tile, threadIdx.x);
}

// ---------------- router ----------------
__global__ void router_kernel(const float* __restrict__ x, const float* __restrict__ Wr) {
    __shared__ float sWr[EE*DD];
    int tid = threadIdx.x;
    for (int i = tid; i < EE*DD; i += 256) sWr[i] = Wr[i];
    __syncthreads();
    int w = tid >> 5, lane = tid & 31;
    int t = blockIdx.x * 8 + w;
    const float* xr = x + (size_t)t * DD;
    float acc[EE];
    #pragma unroll
    for (int e = 0; e < EE; e++) acc[e] = 0.f;
    for (int d = lane; d < DD; d += 32) {
        float xv = xr[d];
        #pragma unroll
        for (int e = 0; e < EE; e++) acc[e] += xv * sWr[e*DD + d];
    }
    #pragma unroll
    for (int e = 0; e < EE; e++)
        #pragma unroll
        for (int o = 16; o > 0; o >>= 1) acc[e] += __shfl_xor_sync(0xffffffffu, acc[e], o);
    if (lane == 0) {
        float m = acc[0];
        #pragma unroll
        for (int e = 1; e < EE; e++) m = fmaxf(m, acc[e]);
        float p[EE], s = 0.f;
        #pragma unroll
        for (int e = 0; e < EE; e++) { p[e] = expf(acc[e] - m); s += p[e]; }
        #pragma unroll
        for (int e = 0; e < EE; e++) p[e] /= s;
        int i1 = 0;
        #pragma unroll
        for (int e = 1; e < EE; e++) if (p[e] > p[i1]) i1 = e;
        int i2 = -1;
        #pragma unroll
        for (int e = 0; e < EE; e++) if (e != i1 && (i2 < 0 || p[e] > p[i2])) i2 = e;
        float ssum = p[i1] + p[i2];
        if (ssum < 1e-9f) ssum = 1e-9f;
        g_top2e[2*t] = i1; g_top2e[2*t+1] = i2;
        g_top2w[2*t] = p[i1] / ssum; g_top2w[2*t+1] = p[i2] / ssum;
    }
}

// ---------------- sequential capacity assignment ----------------
__global__ void assign_kernel() {
    int tid = threadIdx.x, lane = tid & 31, wid = tid >> 5;
    __shared__ int wsum[32];
    int e0[8], e1[8];
    bool fb[8];
    #pragma unroll
    for (int i = 0; i < 8; i++) {
        int t = tid * 8 + i;
        e0[i] = g_top2e[2*t]; e1[i] = g_top2e[2*t+1];
        fb[i] = false;
    }
    for (int e = 0; e < EE; e++) {
        bool elig[8]; int cnt = 0;
        #pragma unroll
        for (int i = 0; i < 8; i++) {
            elig[i] = (!fb[i]) && (e0[i] == e || e1[i] == e);
            cnt += elig[i] ? 1 : 0;
        }
        int inc = cnt;
        #pragma unroll
        for (int o = 1; o < 32; o <<= 1) { int v = __shfl_up_sync(0xffffffffu, inc, o); if (lane >= o) inc += v; }
        if (lane == 31) wsum[wid] = inc;
        __syncthreads();
        if (wid == 0) {
            int v = wsum[lane];
            int inc2 = v;
            #pragma unroll
            for (int o = 1; o < 32; o <<= 1) { int u = __shfl_up_sync(0xffffffffu, inc2, o); if (lane >= o) inc2 += u; }
            wsum[lane] = inc2;
        }
        __syncthreads();
        int pos = inc - cnt + (wid ? wsum[wid-1] : 0);
        int total = wsum[31];
        if (tid == 0) g_counts[e] = (total < CAPACITY) ? total : CAPACITY;
        #pragma unroll
        for (int i = 0; i < 8; i++) {
            if (elig[i]) {
                int t = tid * 8 + i;
                if (pos < CAPACITY) {
                    int k = (e0[i] == e) ? 0 : 1;
                    g_slot[2*t + k] = pos;
                    g_idx[e*CAPACITY + pos] = t;
                } else {
                    fb[i] = true;
                }
                pos++;
            }
        }
        __syncthreads();
    }
    int cnt = 0;
    #pragma unroll
    for (int i = 0; i < 8; i++) cnt += fb[i] ? 1 : 0;
    int inc = cnt;
    #pragma unroll
    for (int o = 1; o < 32; o <<= 1) { int v = __shfl_up_sync(0xffffffffu, inc, o); if (lane >= o) inc += v; }
    if (lane == 31) wsum[wid] = inc;
    __syncthreads();
    if (wid == 0) {
        int v = wsum[lane];
        int inc2 = v;
        #pragma unroll
        for (int o = 1; o < 32; o <<= 1) { int u = __shfl_up_sync(0xffffffffu, inc2, o); if (lane >= o) inc2 += u; }
        wsum[lane] = inc2;
    }
    __syncthreads();
    int pos = inc - cnt + (wid ? wsum[wid-1] : 0);
    #pragma unroll
    for (int i = 0; i < 8; i++) {
        int t = tid * 8 + i;
        g_fbflag[t] = fb[i] ? 1 : 0;
        if (fb[i]) { g_fbidx[pos] = t; g_fbslot[t] = pos; pos++; }
    }
    if (tid == 0) g_fbcount = wsum[31];
}

// ---------------- gather body ----------------
__device__ __forceinline__ void gather_body(const float* __restrict__ x, int r, int i) {
    int t;
    __half* dstrow;
    if (r < RR) {
        int e = r / CAPACITY;
        if (r - e*CAPACITY >= g_counts[e]) return;
        t = g_idx[r];
        dstrow = g_Xg + (size_t)r * DD;
    } else {
        int rr = r - RR;
        if (rr >= g_fbcount) return;
        t = g_fbidx[rr];
        dstrow = g_Xfb + (size_t)rr * DD;
    }
    const float4* src = reinterpret_cast<const float4*>(x + (size_t)t * DD);
    __half2* dst = reinterpret_cast<__half2*>(dstrow);
    float4 v = src[i];
    dst[2*i]   = __floats2half2_rn(v.x, v.y);
    dst[2*i+1] = __floats2half2_rn(v.z, v.w);
}

__global__ void gather_all(const float* __restrict__ x) {
    gather_body(x, blockIdx.x, threadIdx.x);
}

// ---------------- mega-prep ----------------
#define MP_GATHER (RR + TT)
#define MP_W1     (16*64*EE)
#define MP_W2     (64*16*EE)
#define MP_FW1    (16*64)
#define MP_FW2    (64*16)
#define MP_TOTAL  (MP_GATHER + MP_W1 + MP_W2 + MP_FW1 + MP_FW2)

__global__ void megaprep(const float* __restrict__ x,
                         const float* __restrict__ W1, const float* __restrict__ W2,
                         const float* __restrict__ fw1, const float* __restrict__ fw2) {
    __shared__ float tile[64][65];
    int b = blockIdx.x, tid = threadIdx.x;
    if (b < MP_GATHER) { gather_body(x, b, tid); return; }
    b -= MP_GATHER;
    if (b < MP_W1) {
        int kb = (b & 15) * 64;
        int t2 = b >> 4;
        int nb = (t2 & 63) * 64;
        int z  = t2 >> 6;
        tconv_tile(W1 + (size_t)z*DD*II, g_W1f + (size_t)z*DD*II, DD, II, kb, nb, tile, tid);
        return;
    }
    b -= MP_W1;
    if (b < MP_W2) {
        int kb = (b & 63) * 64;
        int t2 = b >> 6;
        int nb = (t2 & 15) * 64;
        int z  = t2 >> 4;
        tconv_tile(W2 + (size_t)z*II*DD, g_W2f + (size_t)z*II*DD, II, DD, kb, nb, tile, tid);
        return;
    }
    b -= MP_W2;
    if (b < MP_FW1) {
        int kb = (b & 15) * 64;
        int nb = (b >> 4) * 64;
        tconv_tile(fw1, g_fw1f, DD, II, kb, nb, tile, tid);
        return;
    }
    b -= MP_FW1;
    {
        int kb = (b & 63) * 64;
        int nb = (b >> 6) * 64;
        tconv_tile(fw2, g_fw2f, II, DD, kb, nb, tile, tid);
    }
}

// ============================================================================
// Path A: tcgen05 GEMM, M=256 per CTA, experts + fallback fused via blockIdx.z
// ============================================================================
#define TCBM 256
#define TCBN 256
#define BKH 64
#define NSTG 3
#define TC_A2 32768
#define TC_STGB 65536
#define SM_TILE0 2048
#define TC_SMEM (SM_TILE0 + NSTG*TC_STGB)   // 198656

#define IDESC_F16_128x256 ((1u<<4) | (32u<<17) | (8u<<24))

#if TC_PATH
static __device__ __forceinline__ uint64_t make_desc(uint32_t addr) {
    const uint64_t base =
        (uint64_t(2)  << 61) | (uint64_t(1) << 46) | (uint64_t(64) << 32) | (uint64_t(1) << 16);
    return base | ((uint64_t)(addr >> 4) & 0x3FFF);
}
__device__ __forceinline__ void mma_f16_ss(uint32_t d_tmem, uint64_t adesc, uint64_t bdesc,
                                           uint32_t idesc, bool accum) {
    uint32_t en = accum ? 1u : 0u;
    asm volatile(
        "{\n\t"
        ".reg .pred p;\n\t"
        "setp.ne.u32 p, %5, 0;\n\t"
        "tcgen05.mma.cta_group::1.kind::f16 [%0], %1, %2, %3, {%4, %4, %4, %4}, p;\n\t"
        "}"
        :: "r"(d_tmem), "l"(adesc), "l"(bdesc), "r"(idesc), "r"(0u), "r"(en)
        : "memory");
}
#define TC_LD32(r, addr) \
    asm volatile( \
        "tcgen05.ld.sync.aligned.32x32b.x32.b32 " \
        "{%0, %1, %2, %3, %4, %5, %6, %7, " \
        " %8, %9, %10, %11, %12, %13, %14, %15, " \
        " %16, %17, %18, %19, %20, %21, %22, %23, " \
        " %24, %25, %26, %27, %28, %29, %30, %31}, [%32];" \
        : "=r"((r)[0]),  "=r"((r)[1]),  "=r"((r)[2]),  "=r"((r)[3]), \
          "=r"((r)[4]),  "=r"((r)[5]),  "=r"((r)[6]),  "=r"((r)[7]), \
          "=r"((r)[8]),  "=r"((r)[9]),  "=r"((r)[10]), "=r"((r)[11]), \
          "=r"((r)[12]), "=r"((r)[13]), "=r"((r)[14]), "=r"((r)[15]), \
          "=r"((r)[16]), "=r"((r)[17]), "=r"((r)[18]), "=r"((r)[19]), \
          "=r"((r)[20]), "=r"((r)[21]), "=r"((r)[22]), "=r"((r)[23]), \
          "=r"((r)[24]), "=r"((r)[25]), "=r"((r)[26]), "=r"((r)[27]), \
          "=r"((r)[28]), "=r"((r)[29]), "=r"((r)[30]), "=r"((r)[31]) \
        : "r"(addr))
#endif

template<int PHASE>
__global__ void __launch_bounds__(256, 1) gemm_tc5(const float* __restrict__ bias_e,
                                                   const float* __restrict__ bias_f) {
#if TC_PATH
    constexpr bool G1 = (PHASE == 1);
    constexpr int K = G1 ? DD : II;
    constexpr int N = G1 ? II : DD;
    constexpr int KT = K / BKH;

    const int z = blockIdx.z;
    const bool FB = (z == EE);
    const int count = FB ? g_fbcount : g_counts[z];
    const int m0 = blockIdx.y * TCBM;
    if (m0 >= count) return;
    const int n0 = blockIdx.x * TCBN;

    const __half* __restrict__ A;
    const __half* __restrict__ B;
    if constexpr (G1) {
        A = FB ? g_Xfb : g_Xg + (size_t)z*CAPACITY*DD;
        B = FB ? g_fw1f : g_W1f + (size_t)z*DD*II;
    } else {
        A = FB ? g_Hfb : g_H + (size_t)z*CAPACITY*II;
        B = FB ? g_fw2f : g_W2f + (size_t)z*II*DD;
    }
    const float* biasp = FB ? bias_f : bias_e + (size_t)z*N;

    extern __shared__ char smem[];
    const uint32_t sb = smem_u32(smem);
    const int tid = threadIdx.x, lane = tid & 31, wid = tid >> 5;

    const uint32_t mb_full0 = sb + 64, mb_empty0 = sb + 96, mb_done = sb + 120;
    float* bias_sm = reinterpret_cast<float*>(smem + 1024);   // 256 floats
    if (tid == 0) {
        #pragma unroll
        for (int s = 0; s < NSTG; s++) {
            mbar_init(mb_full0 + 8*s, 224);
            mbar_init(mb_empty0 + 8*s, 1);
        }
        mbar_init(mb_done, 1);
    }
    bias_sm[tid] = biasp[n0 + tid];       // bias tile -> smem (visible after syncthreads)
    if (wid == 0) {
        asm volatile("tcgen05.alloc.cta_group::1.sync.aligned.shared::cta.b32 [%0], %1;"
                     :: "r"(sb), "r"(512) : "memory");
    }
    __syncthreads();
    uint32_t tb;
    asm volatile("ld.shared.b32 %0, [%1];" : "=r"(tb) : "r"(sb));

    if (wid == 0) {
        if (lane == 0) {
            uint64_t ad0[NSTG], ad1[NSTG], bd[NSTG];
            #pragma unroll
            for (int s = 0; s < NSTG; s++) {
                uint32_t base = sb + SM_TILE0 + s*TC_STGB;
                ad0[s] = make_desc(base);
                ad1[s] = make_desc(base + 16384);
                bd[s]  = make_desc(base + TC_A2);
            }
            #pragma unroll 1
            for (int kt = 0; kt < KT; kt++) {
                int st = kt % NSTG;
                uint32_t ph = (kt / NSTG) & 1;
                mbar_wait(mb_full0 + 8*st, ph);
                asm volatile("tcgen05.fence::after_thread_sync;" ::: "memory");
                #pragma unroll
                for (int k = 0; k < 4; k++) {
                    bool acc = (kt > 0) || (k > 0);
                    mma_f16_ss(tb,       ad0[st] + k*2, bd[st] + k*2, IDESC_F16_128x256, acc);
                    mma_f16_ss(tb + 256, ad1[st] + k*2, bd[st] + k*2, IDESC_F16_128x256, acc);
                }
                asm volatile("tcgen05.commit.cta_group::1.mbarrier::arrive::one.shared::cluster.b64 [%0];"
                             :: "r"(mb_empty0 + 8*st) : "memory");
            }
            asm volatile("tcgen05.commit.cta_group::1.mbarrier::arrive::one.shared::cluster.b64 [%0];"
                         :: "r"(mb_done) : "memory");
        }
    } else {
        // producers: warps 1..7 (224 threads). All addressing hoisted out of k-loop.
        const int ptid = tid - 32;
        uint32_t dstoff[19];
        const __half* srcp[19];
        #pragma unroll
        for (int j = 0; j < 19; j++) {
            int i = ptid + 224*j;
            bool isA = (i < 2048);
            int ii = isA ? i : (i - 2048);
            int r = ii >> 3, c = ii & 7;
            dstoff[j] = (isA ? 0u : (uint32_t)TC_A2)
                      + (uint32_t)(r*128 + ((c ^ (r & 7)) << 4));
            const __half* base = isA ? (A + (size_t)(m0 + r) * K)
                                     : (B + (size_t)(n0 + (r & 255)) * K);
            srcp[j] = base + c*8;
        }
        const bool has19 = (ptid < 64);
        #pragma unroll 1
        for (int kt = 0; kt < KT; kt++) {
            int st = kt % NSTG;
            uint32_t eph = ((kt / NSTG) & 1) ^ 1u;
            mbar_wait(mb_empty0 + 8*st, eph);
            uint32_t stgB = sb + SM_TILE0 + st*TC_STGB;
            #pragma unroll
            for (int j = 0; j < 18; j++)
                cpasync16(stgB + dstoff[j], srcp[j]);
            if (has19) cpasync16(stgB + dstoff[18], srcp[18]);
            cpasync_commit();
            #pragma unroll
            for (int j = 0; j < 19; j++) srcp[j] += BKH;
            if (kt > 0) {
                cpasync_wait1();
                fence_proxy_async_shared();
                mbar_arrive(mb_full0 + 8*((kt-1) % NSTG));
            }
        }
        cpasync_wait0();
        fence_proxy_async_shared();
        mbar_arrive(mb_full0 + 8*((KT-1) % NSTG));
    }

    mbar_wait(mb_done, 0);
    asm volatile("tcgen05.fence::after_thread_sync;" ::: "memory");

    // epilogue: warps 0-3 -> m-tile 0 (TMEM cols 0-255), warps 4-7 -> m-tile 1 (256-511)
    {
        const int mtile = wid >> 2;
        const int lw = wid & 3;
        const int row = m0 + mtile*128 + lw*32 + lane;
        const uint32_t coff = (uint32_t)mtile * 256;
        __half* outp;
        if constexpr (G1)
            outp = (FB ? g_Hfb : g_H + (size_t)z*CAPACITY*II) + (size_t)row * II;
        else
            outp = (FB ? g_Yfbh : g_Yeh + (size_t)z*CAPACITY*DD) + (size_t)row * DD;
        uint32_t ra[32], rb[32];
        #pragma unroll 1
        for (int cc = 0; cc < 4; cc++) {
            TC_LD32(ra, tb + coff + (2*cc)*32);
            TC_LD32(rb, tb + coff + (2*cc+1)*32);
            asm volatile("tcgen05.wait::ld.sync.aligned;" ::: "memory");
            #pragma unroll
            for (int half = 0; half < 2; half++) {
                const uint32_t* r = half ? rb : ra;
                int cb = 2*cc + half;
                int cl = cb*32;                 // tile-local column base
                union { __half2 h[16]; uint4 u[4]; } o;
                #pragma unroll
                for (int j = 0; j < 16; j++) {
                    float v0 = __uint_as_float(r[2*j])   + bias_sm[cl + 2*j];
                    float v1 = __uint_as_float(r[2*j+1]) + bias_sm[cl + 2*j + 1];
                    if constexpr (G1) { v0 = gelu_exact(v0); v1 = gelu_exact(v1); }
                    o.h[j] = __floats2half2_rn(v0, v1);
                }
                uint4* dst = reinterpret_cast<uint4*>(outp + n0 + cl);
                dst[0] = o.u[0]; dst[1] = o.u[1]; dst[2] = o.u[2]; dst[3] = o.u[3];
            }
        }
    }
    __syncthreads();
    if (wid == 0) {
        asm volatile("tcgen05.relinquish_alloc_permit.cta_group::1.sync.aligned;");
        asm volatile("tcgen05.dealloc.cta_group::1.sync.aligned.b32 %0, %1;" :: "r"(tb), "r"(512));
    }
#endif
}

// ============================================================================
// Path B: HMMA GEMM fallback ([K,N] weights), 128x128 tiles, 3-stage
// ============================================================================
#define BM 128
#define BN 128
#define HM_STGB 32768
#define HM_SMEM (3*HM_STGB)

template<int MODE>
__global__ void gemm_hmma(const float* __restrict__ bias) {
    constexpr bool G1 = (MODE < 2);
    constexpr bool FB = (MODE & 1);
    constexpr int K = G1 ? DD : II;
    constexpr int N = G1 ? II : DD;
    constexpr int KT = K / BKH;

    const int e = blockIdx.z;
    const int count = FB ? g_fbcount : g_counts[e];
    const int m0 = blockIdx.y * BM;
    if (m0 >= count) return;
    const int n0 = blockIdx.x * BN;

    const __half* __restrict__ Aexp;
    const __half* __restrict__ Bexp;
    if constexpr (MODE == 0) { Aexp = g_Xg  + (size_t)e*CAPACITY*K; Bexp = g_W1f + (size_t)e*K*II; }
    if constexpr (MODE == 1) { Aexp = g_Xfb;                        Bexp = g_fw1f; }
    if constexpr (MODE == 2) { Aexp = g_H   + (size_t)e*CAPACITY*K; Bexp = g_W2f + (size_t)e*K*DD; }
    if constexpr (MODE == 3) { Aexp = g_Hfb;                        Bexp = g_fw2f; }
    const float* biasp = bias + (FB ? 0 : (size_t)e*N);

    extern __shared__ __half smemh[];
    const uint32_t sbase = smem_u32(smemh);
    const int tid = threadIdx.x, lane = tid & 31, wid = tid >> 5;
    const int wm = wid & 1, wn = wid >> 1;
    const int g = lane >> 3, rin = lane & 7;

    float acc[4][4][4];
    #pragma unroll
    for (int a = 0; a < 4; a++)
        #pragma unroll
        for (int b = 0; b < 4; b++)
            #pragma unroll
            for (int c = 0; c < 4; c++) acc[a][b][c] = 0.f;

    auto loadStage = [&](int kt, int st) {
        if (kt < KT) {
            uint32_t aB = sbase + st * HM_STGB;
            uint32_t bB = aB + 16384;
            #pragma unroll
            for (int j = 0; j < 4; j++) {
                int id = j * 256 + tid;
                int r = id >> 3, c = id & 7;
                const __half* src = Aexp + (size_t)(m0 + r) * K + kt * BKH + c * 8;
                uint32_t dst = aB + (uint32_t)(r * 64 + ((c ^ (r & 7)) << 3)) * 2;
                cpasync16(dst, src);
            }
            #pragma unroll
            for (int j = 0; j < 4; j++) {
                int id = j * 256 + tid;
                int r = id >> 4, c = id & 15;
                const __half* src = Bexp + (size_t)(kt * BKH + r) * N + n0 + c * 8;
                uint32_t dst = bB + (uint32_t)(r * 128 + (((c & 8) | ((c ^ r) & 7)) << 3)) * 2;
                cpasync16(dst, src);
            }
        }
        cpasync_commit();
    };

    loadStage(0, 0);
    loadStage(1, 1);
    int st = 0;
    #pragma unroll 1
    for (int kt = 0; kt < KT; kt++) {
        cpasync_wait1();
        __syncthreads();
        loadStage(kt + 2, (st + 2) % 3);
        uint32_t aB = sbase + st * HM_STGB;
        uint32_t bB = aB + 16384;
        #pragma unroll
        for (int ks = 0; ks < 4; ks++) {
            uint32_t afr[4][4];
            #pragma unroll
            for (int mt = 0; mt < 4; mt++) {
                int row = wm * 64 + mt * 16 + (g & 1) * 8 + rin;
                int ch = (ks * 2 + (g >> 1)) ^ rin;
                ldmatrix_x4(afr[mt], aB + (uint32_t)(row * 64 + ch * 8) * 2);
            }
            uint32_t bfr[4][2];
            #pragma unroll
            for (int ht = 0; ht < 2; ht++) {
                int row = ks * 16 + (g & 1) * 8 + rin;
                int c = wn * 4 + ht * 2 + (g >> 1);
                int ph = (c & 8) | ((c & 7) ^ rin);
                uint32_t r4[4];
                ldmatrix_x4_trans(r4, bB + (uint32_t)(row * 128 + ph * 8) * 2);
                bfr[ht*2][0] = r4[0]; bfr[ht*2][1] = r4[1];
                bfr[ht*2+1][0] = r4[2]; bfr[ht*2+1][1] = r4[3];
            }
            #pragma unroll
            for (int mt = 0; mt < 4; mt++)
                #pragma unroll
                for (int nt = 0; nt < 4; nt++)
                    mma16816(acc[mt][nt], afr[mt], bfr[nt]);
        }
        st = (st + 1) % 3;
    }

    const int growb = m0 + wm * 64;
    const int gcolb = n0 + wn * 32;
    #pragma unroll
    for (int mt = 0; mt < 4; mt++) {
        #pragma unroll
        for (int nt = 0; nt < 4; nt++) {
            int r0 = growb + mt * 16 + (lane >> 2);
            int c0 = gcolb + nt * 8 + (lane & 3) * 2;
            float b0f = biasp[c0], b1f = biasp[c0 + 1];
            float x0 = acc[mt][nt][0] + b0f, x1 = acc[mt][nt][1] + b1f;
            float x2 = acc[mt][nt][2] + b0f, x3 = acc[mt][nt][3] + b1f;
            if constexpr (G1) {
                __half* Hout = FB ? g_Hfb : (g_H + (size_t)e*CAPACITY*N);
                *reinterpret_cast<__half2*>(Hout + (size_t)r0 * N + c0) =
                    __floats2half2_rn(gelu_exact(x0), gelu_exact(x1));
                *reinterpret_cast<__half2*>(Hout + (size_t)(r0 + 8) * N + c0) =
                    __floats2half2_rn(gelu_exact(x2), gelu_exact(x3));
            } else {
                __half* Yout = FB ? g_Yfbh : (g_Yeh + (size_t)e*CAPACITY*N);
                *reinterpret_cast<__half2*>(Yout + (size_t)r0 * N + c0) =
                    __floats2half2_rn(x0, x1);
                *reinterpret_cast<__half2*>(Yout + (size_t)(r0 + 8) * N + c0) =
                    __floats2half2_rn(x2, x3);
            }
        }
    }
}

// ---------------- final combine (fp16 expert outputs) ----------------
__global__ void combine_kernel(float* __restrict__ out) {
    int t = blockIdx.x;
    int i = threadIdx.x;
    float4* o = reinterpret_cast<float4*>(out + (size_t)t * DD);
    if (g_fbflag[t]) {
        const uint2 hv = reinterpret_cast<const uint2*>(g_Yfbh + (size_t)g_fbslot[t] * DD)[i];
        float2 a0 = __half22float2(*reinterpret_cast<const __half2*>(&hv.x));
        float2 a1 = __half22float2(*reinterpret_cast<const __half2*>(&hv.y));
        float4 v; v.x = a0.x; v.y = a0.y; v.z = a1.x; v.w = a1.y;
        o[i] = v;
    } else {
        int e0 = g_top2e[2*t], e1 = g_top2e[2*t+1];
        float w0 = g_top2w[2*t], w1 = g_top2w[2*t+1];
        size_t r0 = (size_t)(e0 * CAPACITY + g_slot[2*t]) * DD;
        size_t r1 = (size_t)(e1 * CAPACITY + g_slot[2*t+1]) * DD;
        uint2 av = reinterpret_cast<const uint2*>(g_Yeh + r0)[i];
        uint2 bv = reinterpret_cast<const uint2*>(g_Yeh + r1)[i];
        float2 a0 = __half22float2(*reinterpret_cast<const __half2*>(&av.x));
        float2 a1 = __half22float2(*reinterpret_cast<const __half2*>(&av.y));
        float2 b0 = __half22float2(*reinterpret_cast<const __half2*>(&bv.x));
        float2 b1 = __half22float2(*reinterpret_cast<const __half2*>(&bv.y));
        float4 v;
        v.x = w0 * a0.x + w1 * b0.x;
        v.y = w0 * a0.y + w1 * b0.y;
        v.z = w0 * a1.x + w1 * b1.x;
        v.w = w0 * a1.y + w1 * b1.y;
        o[i] = v;
    }
}

// ---------------- launch ----------------
extern "C" void kernel_launch(void* const* d_in, const int* in_sizes, int n_in,
                              void* d_out, int out_size) {
    const float* x   = (const float*)d_in[0];
    const float* Wr  = (const float*)d_in[1];
    const float* W1  = (const float*)d_in[2];
    const float* b1  = (const float*)d_in[3];
    const float* W2  = (const float*)d_in[4];
    const float* b2  = (const float*)d_in[5];
    const float* fw1 = (const float*)d_in[6];
    const float* fb1 = (const float*)d_in[7];
    const float* fw2 = (const float*)d_in[8];
    const float* fb2 = (const float*)d_in[9];
    float* out = (float*)d_out;

    __half* dW1;  cudaGetSymbolAddress((void**)&dW1,  g_W1f);
    __half* dW2;  cudaGetSymbolAddress((void**)&dW2,  g_W2f);
    __half* dfw1; cudaGetSymbolAddress((void**)&dfw1, g_fw1f);
    __half* dfw2; cudaGetSymbolAddress((void**)&dfw2, g_fw2f);

    cudaFuncAttributes fa{};
    cudaFuncGetAttributes(&fa, (const void*)gemm_tc5<1>);
    const bool use_tc = (fa.numRegs >= 24);

    if (use_tc) {
        cudaFuncSetAttribute(gemm_tc5<1>, cudaFuncAttributeMaxDynamicSharedMemorySize, TC_SMEM);
        cudaFuncSetAttribute(gemm_tc5<2>, cudaFuncAttributeMaxDynamicSharedMemorySize, TC_SMEM);
        router_kernel<<<TT/8, 256>>>(x, Wr);                               // 0
        assign_kernel<<<1, 1024>>>();                                      // 1
        megaprep<<<MP_TOTAL, 256>>>(x, W1, W2, fw1, fw2);                  // 2
        gemm_tc5<1><<<dim3(II/TCBN, TT/TCBM, EE+1), 256, TC_SMEM>>>(b1, fb1); // 3 <- profiled
        gemm_tc5<2><<<dim3(DD/TCBN, TT/TCBM, EE+1), 256, TC_SMEM>>>(b2, fb2); // 4
        combine_kernel<<<TT, 256>>>(out);                                  // 5
    } else {
        cudaFuncSetAttribute(gemm_hmma<0>, cudaFuncAttributeMaxDynamicSharedMemorySize, HM_SMEM);
        cudaFuncSetAttribute(gemm_hmma<1>, cudaFuncAttributeMaxDynamicSharedMemorySize, HM_SMEM);
        cudaFuncSetAttribute(gemm_hmma<2>, cudaFuncAttributeMaxDynamicSharedMemorySize, HM_SMEM);
        cudaFuncSetAttribute(gemm_hmma<3>, cudaFuncAttributeMaxDynamicSharedMemorySize, HM_SMEM);
        router_kernel<<<TT/8, 256>>>(x, Wr);
        convert_kernel<<<(EE*DD*II/8 + 255)/256, 256>>>(W1, dW1, EE*DD*II/8);
        convert_kernel<<<(EE*II*DD/8 + 255)/256, 256>>>(W2, dW2, EE*II*DD/8);
        assign_kernel<<<1, 1024>>>();
        gather_all<<<RR + TT, 256>>>(x);
        gemm_hmma<0><<<dim3(II/BN, CAPACITY/BM, EE), 256, HM_SMEM>>>(b1);
        gemm_hmma<2><<<dim3(DD/BN, CAPACITY/BM, EE), 256, HM_SMEM>>>(b2);
        convert_kernel<<<(DD*II/8 + 255)/256, 256>>>(fw1, dfw1, DD*II/8);
        gemm_hmma<1><<<dim3(II/BN, TT/BM, 1), 256, HM_SMEM>>>(fb1);
        convert_kernel<<<(II*DD/8 + 255)/256, 256>>>(fw2, dfw2, II*DD/8);
        gemm_hmma<3><<<dim3(DD/BN, TT/BM, 1), 256, HM_SMEM>>>(fb2);
    }

    combine_kernel<<<TT, 256>>>(out);
}

// round 13
// speedup vs baseline: 2.0189x; 1.0042x over previous
#include <cuda_runtime.h>
#include <cuda.h>
#include <cuda_fp16.h>
#include <cstdint>

// ---------------- problem constants ----------------
#define TT   8192
#define DD   1024
#define II   4096
#define EE   8
#define CAPACITY 2560
#define RR   (EE*CAPACITY)

// arch-specific (sm_103a/sm_100a) feature gate for tcgen05
#if defined(__CUDA_ARCH__) && (defined(__CUDA_ARCH_FEAT_SM103_ALL) || defined(__CUDA_ARCH_FEAT_SM100_ALL) || defined(__CUDA_ARCH_SPECIFIC__) || defined(__CUDA_ARCH_FAMILY_SPECIFIC__))
#define TC_PATH 1
#else
#define TC_PATH 0
#endif

// ---------------- device scratch ----------------
__device__ __half g_W1f[(size_t)EE*DD*II];
__device__ __half g_W2f[(size_t)EE*II*DD];
__device__ __half g_fw1f[(size_t)DD*II];
__device__ __half g_fw2f[(size_t)II*DD];
__device__ __half g_Xg [(size_t)RR*DD];
__device__ __half g_Xfb[(size_t)TT*DD];
__device__ __half g_H  [(size_t)RR*II];
__device__ __half g_Hfb[(size_t)TT*II];
__device__ __half g_Yeh [(size_t)RR*DD];
__device__ __half g_Yfbh[(size_t)TT*DD];
__device__ int    g_top2e[TT*2];
__device__ float  g_top2w[TT*2];
__device__ int    g_slot [TT*2];
__device__ int    g_fbslot[TT];
__device__ int    g_fbidx [TT];
__device__ unsigned char g_fbflag[TT];
__device__ int    g_counts[EE];
__device__ int    g_fbcount;
__device__ int    g_idx[RR];

// ---------------- generic helpers ----------------
__device__ __forceinline__ float gelu_exact(float v) {
    return 0.5f * v * (1.0f + erff(v * 0.7071067811865475f));
}
__device__ __forceinline__ void cpasync16(uint32_t dst, const void* src) {
    asm volatile("cp.async.cg.shared.global [%0], [%1], 16;\n" :: "r"(dst), "l"(src));
}
__device__ __forceinline__ void cpasync_commit() { asm volatile("cp.async.commit_group;\n"); }
__device__ __forceinline__ void cpasync_wait0() { asm volatile("cp.async.wait_group 0;\n"); }
__device__ __forceinline__ void cpasync_wait1() { asm volatile("cp.async.wait_group 1;\n"); }

__device__ __forceinline__ uint32_t smem_u32(const void* p) {
    uint32_t a;
    asm("{ .reg .u64 t; cvta.to.shared.u64 t, %1; cvt.u32.u64 %0, t; }" : "=r"(a) : "l"(p));
    return a;
}
__device__ __forceinline__ void ldmatrix_x4(uint32_t* r, uint32_t addr) {
    asm volatile("ldmatrix.sync.aligned.m8n8.x4.shared.b16 {%0,%1,%2,%3}, [%4];"
                 : "=r"(r[0]), "=r"(r[1]), "=r"(r[2]), "=r"(r[3]) : "r"(addr));
}
__device__ __forceinline__ void ldmatrix_x4_trans(uint32_t* r, uint32_t addr) {
    asm volatile("ldmatrix.sync.aligned.m8n8.x4.trans.shared.b16 {%0,%1,%2,%3}, [%4];"
                 : "=r"(r[0]), "=r"(r[1]), "=r"(r[2]), "=r"(r[3]) : "r"(addr));
}
__device__ __forceinline__ void mma16816(float* c, const uint32_t* a, const uint32_t* b) {
    asm volatile("mma.sync.aligned.m16n8k16.row.col.f32.f16.f16.f32 "
                 "{%0,%1,%2,%3},{%4,%5,%6,%7},{%8,%9},{%0,%1,%2,%3};"
                 : "+f"(c[0]), "+f"(c[1]), "+f"(c[2]), "+f"(c[3])
                 : "r"(a[0]), "r"(a[1]), "r"(a[2]), "r"(a[3]), "r"(b[0]), "r"(b[1]));
}

// ---------------- mbarrier helpers ----------------
__device__ __forceinline__ void mbar_init(uint32_t a, uint32_t cnt) {
    asm volatile("mbarrier.init.shared.b64 [%0], %1;" :: "r"(a), "r"(cnt) : "memory");
}
__device__ __forceinline__ void mbar_arrive(uint32_t a) {
    asm volatile("mbarrier.arrive.shared.b64 _, [%0];" :: "r"(a) : "memory");
}
__device__ __forceinline__ void mbar_expect_tx(uint32_t a, uint32_t bytes) {
    asm volatile("mbarrier.arrive.expect_tx.shared.b64 _, [%0], %1;" :: "r"(a), "r"(bytes) : "memory");
}
__device__ __forceinline__ void mbar_wait(uint32_t a, uint32_t parity) {
    asm volatile(
        "{\n\t"
        ".reg .pred P1;\n\t"
        "WAIT_LOOP_%=:\n\t"
        "mbarrier.try_wait.parity.acquire.cta.shared::cta.b64 P1, [%0], %1, 0x989680;\n\t"
        "@P1 bra.uni WAIT_DONE_%=;\n\t"
        "bra.uni WAIT_LOOP_%=;\n\t"
        "WAIT_DONE_%=:\n\t"
        "}"
        :: "r"(a), "r"(parity) : "memory");
}
__device__ __forceinline__ void fence_proxy_async_shared() {
    asm volatile("fence.proxy.async.shared::cta;" ::: "memory");
}
// 2D TMA load global->shared::cta, mbarrier complete_tx
__device__ __forceinline__ void tma2d(uint32_t smemaddr, const CUtensorMap* tm,
                                      int cx, int cy, uint32_t mbar) {
    asm volatile("cp.async.bulk.tensor.2d.shared::cta.global.tile.mbarrier::complete_tx::bytes "
                 "[%0], [%1, {%2, %3}], [%4];"
                 :: "r"(smemaddr), "l"(tm), "r"(cx), "r"(cy), "r"(mbar) : "memory");
}

// ---------------- fp32 -> fp16 plain convert (HMMA layout [K,N]) ----------------
__global__ void convert_kernel(const float* __restrict__ src, __half* __restrict__ dst, int n8) {
    int i = blockIdx.x * blockDim.x + threadIdx.x;
    if (i < n8) {
        float4 a = reinterpret_cast<const float4*>(src)[2*i];
        float4 b = reinterpret_cast<const float4*>(src)[2*i+1];
        union { __half2 h[4]; uint4 u; } o;
        o.h[0] = __floats2half2_rn(a.x, a.y);
        o.h[1] = __floats2half2_rn(a.z, a.w);
        o.h[2] = __floats2half2_rn(b.x, b.y);
        o.h[3] = __floats2half2_rn(b.z, b.w);
        reinterpret_cast<uint4*>(dst)[i] = o.u;
    }
}

// ---------------- transpose-convert tile body (TC layout [N,K]) ----------------
__device__ __forceinline__ void tconv_tile(const float* __restrict__ src, __half* __restrict__ dst,
                                           int Kdim, int Ndim, int kb, int nb,
                                           float (*tile)[65], int tid) {
    #pragma unroll
    for (int p = 0; p < 4; p++) {
        int i = p * 256 + tid;
        int r = i >> 4, c4 = i & 15;
        float4 v = *reinterpret_cast<const float4*>(src + (size_t)(kb + r) * Ndim + nb + c4 * 4);
        tile[r][c4*4+0] = v.x; tile[r][c4*4+1] = v.y;
        tile[r][c4*4+2] = v.z; tile[r][c4*4+3] = v.w;
    }
    __syncthreads();
    #pragma unroll
    for (int p = 0; p < 2; p++) {
        int i = p * 256 + tid;
        int r = i >> 3, c = i & 7;
        union { __half2 h[4]; uint4 u; } o;
        #pragma unroll
        for (int j = 0; j < 4; j++)
            o.h[j] = __floats2half2_rn(tile[c*8 + 2*j][r], tile[c*8 + 2*j + 1][r]);
        *reinterpret_cast<uint4*>(dst + (size_t)(nb + r) * Kdim + kb + c * 8) = o.u;
    }
}

// ---------------- router ----------------
__global__ void router_kernel(const float* __restrict__ x, const float* __restrict__ Wr) {
    __shared__ float sWr[EE*DD];
    int tid = threadIdx.x;
    for (int i = tid; i < EE*DD; i += 256) sWr[i] = Wr[i];
    __syncthreads();
    int w = tid >> 5, lane = tid & 31;
    int t = blockIdx.x * 8 + w;
    const float* xr = x + (size_t)t * DD;
    float acc[EE];
    #pragma unroll
    for (int e = 0; e < EE; e++) acc[e] = 0.f;
    for (int d = lane; d < DD; d += 32) {
        float xv = xr[d];
        #pragma unroll
        for (int e = 0; e < EE; e++) acc[e] += xv * sWr[e*DD + d];
    }
    #pragma unroll
    for (int e = 0; e < EE; e++)
        #pragma unroll
        for (int o = 16; o > 0; o >>= 1) acc[e] += __shfl_xor_sync(0xffffffffu, acc[e], o);
    if (lane == 0) {
        float m = acc[0];
        #pragma unroll
        for (int e = 1; e < EE; e++) m = fmaxf(m, acc[e]);
        float p[EE], s = 0.f;
        #pragma unroll
        for (int e = 0; e < EE; e++) { p[e] = expf(acc[e] - m); s += p[e]; }
        #pragma unroll
        for (int e = 0; e < EE; e++) p[e] /= s;
        int i1 = 0;
        #pragma unroll
        for (int e = 1; e < EE; e++) if (p[e] > p[i1]) i1 = e;
        int i2 = -1;
        #pragma unroll
        for (int e = 0; e < EE; e++) if (e != i1 && (i2 < 0 || p[e] > p[i2])) i2 = e;
        float ssum = p[i1] + p[i2];
        if (ssum < 1e-9f) ssum = 1e-9f;
        g_top2e[2*t] = i1; g_top2e[2*t+1] = i2;
        g_top2w[2*t] = p[i1] / ssum; g_top2w[2*t+1] = p[i2] / ssum;
    }
}

// ---------------- sequential capacity assignment ----------------
__global__ void assign_kernel() {
    int tid = threadIdx.x, lane = tid & 31, wid = tid >> 5;
    __shared__ int wsum[32];
    int e0[8], e1[8];
    bool fb[8];
    #pragma unroll
    for (int i = 0; i < 8; i++) {
        int t = tid * 8 + i;
        e0[i] = g_top2e[2*t]; e1[i] = g_top2e[2*t+1];
        fb[i] = false;
    }
    for (int e = 0; e < EE; e++) {
        bool elig[8]; int cnt = 0;
        #pragma unroll
        for (int i = 0; i < 8; i++) {
            elig[i] = (!fb[i]) && (e0[i] == e || e1[i] == e);
            cnt += elig[i] ? 1 : 0;
        }
        int inc = cnt;
        #pragma unroll
        for (int o = 1; o < 32; o <<= 1) { int v = __shfl_up_sync(0xffffffffu, inc, o); if (lane >= o) inc += v; }
        if (lane == 31) wsum[wid] = inc;
        __syncthreads();
        if (wid == 0) {
            int v = wsum[lane];
            int inc2 = v;
            #pragma unroll
            for (int o = 1; o < 32; o <<= 1) { int u = __shfl_up_sync(0xffffffffu, inc2, o); if (lane >= o) inc2 += u; }
            wsum[lane] = inc2;
        }
        __syncthreads();
        int pos = inc - cnt + (wid ? wsum[wid-1] : 0);
        int total = wsum[31];
        if (tid == 0) g_counts[e] = (total < CAPACITY) ? total : CAPACITY;
        #pragma unroll
        for (int i = 0; i < 8; i++) {
            if (elig[i]) {
                int t = tid * 8 + i;
                if (pos < CAPACITY) {
                    int k = (e0[i] == e) ? 0 : 1;
                    g_slot[2*t + k] = pos;
                    g_idx[e*CAPACITY + pos] = t;
                } else {
                    fb[i] = true;
                }
                pos++;
            }
        }
        __syncthreads();
    }
    int cnt = 0;
    #pragma unroll
    for (int i = 0; i < 8; i++) cnt += fb[i] ? 1 : 0;
    int inc = cnt;
    #pragma unroll
    for (int o = 1; o < 32; o <<= 1) { int v = __shfl_up_sync(0xffffffffu, inc, o); if (lane >= o) inc += v; }
    if (lane == 31) wsum[wid] = inc;
    __syncthreads();
    if (wid == 0) {
        int v = wsum[lane];
        int inc2 = v;
        #pragma unroll
        for (int o = 1; o < 32; o <<= 1) { int u = __shfl_up_sync(0xffffffffu, inc2, o); if (lane >= o) inc2 += u; }
        wsum[lane] = inc2;
    }
    __syncthreads();
    int pos = inc - cnt + (wid ? wsum[wid-1] : 0);
    #pragma unroll
    for (int i = 0; i < 8; i++) {
        int t = tid * 8 + i;
        g_fbflag[t] = fb[i] ? 1 : 0;
        if (fb[i]) { g_fbidx[pos] = t; g_fbslot[t] = pos; pos++; }
    }
    if (tid == 0) g_fbcount = wsum[31];
}

// ---------------- gather body ----------------
__device__ __forceinline__ void gather_body(const float* __restrict__ x, int r, int i) {
    int t;
    __half* dstrow;
    if (r < RR) {
        int e = r / CAPACITY;
        if (r - e*CAPACITY >= g_counts[e]) return;
        t = g_idx[r];
        dstrow = g_Xg + (size_t)r * DD;
    } else {
        int rr = r - RR;
        if (rr >= g_fbcount) return;
        t = g_fbidx[rr];
        dstrow = g_Xfb + (size_t)rr * DD;
    }
    const float4* src = reinterpret_cast<const float4*>(x + (size_t)t * DD);
    __half2* dst = reinterpret_cast<__half2*>(dstrow);
    float4 v = src[i];
    dst[2*i]   = __floats2half2_rn(v.x, v.y);
    dst[2*i+1] = __floats2half2_rn(v.z, v.w);
}

__global__ void gather_all(const float* __restrict__ x) {
    gather_body(x, blockIdx.x, threadIdx.x);
}

// ---------------- mega-prep ----------------
#define MP_GATHER (RR + TT)
#define MP_W1     (16*64*EE)
#define MP_W2     (64*16*EE)
#define MP_FW1    (16*64)
#define MP_FW2    (64*16)
#define MP_TOTAL  (MP_GATHER + MP_W1 + MP_W2 + MP_FW1 + MP_FW2)

__global__ void megaprep(const float* __restrict__ x,
                         const float* __restrict__ W1, const float* __restrict__ W2,
                         const float* __restrict__ fw1, const float* __restrict__ fw2) {
    __shared__ float tile[64][65];
    int b = blockIdx.x, tid = threadIdx.x;
    if (b < MP_GATHER) { gather_body(x, b, tid); return; }
    b -= MP_GATHER;
    if (b < MP_W1) {
        int kb = (b & 15) * 64;
        int t2 = b >> 4;
        int nb = (t2 & 63) * 64;
        int z  = t2 >> 6;
        tconv_tile(W1 + (size_t)z*DD*II, g_W1f + (size_t)z*DD*II, DD, II, kb, nb, tile, tid);
        return;
    }
    b -= MP_W1;
    if (b < MP_W2) {
        int kb = (b & 63) * 64;
        int t2 = b >> 6;
        int nb = (t2 & 15) * 64;
        int z  = t2 >> 4;
        tconv_tile(W2 + (size_t)z*II*DD, g_W2f + (size_t)z*II*DD, II, DD, kb, nb, tile, tid);
        return;
    }
    b -= MP_W2;
    if (b < MP_FW1) {
        int kb = (b & 15) * 64;
        int nb = (b >> 4) * 64;
        tconv_tile(fw1, g_fw1f, DD, II, kb, nb, tile, tid);
        return;
    }
    b -= MP_FW1;
    {
        int kb = (b & 63) * 64;
        int nb = (b >> 6) * 64;
        tconv_tile(fw2, g_fw2f, II, DD, kb, nb, tile, tid);
    }
}

// ============================================================================
// Path A: tcgen05 GEMM with TMA producers. M=256 per CTA, z: experts + fb
// ============================================================================
#define TCBM 256
#define TCBN 256
#define BKH 64
#define NSTG 3
#define TC_A2 32768
#define TC_STGB 65536
#define SM_TILE0 2048
#define TC_SMEM (SM_TILE0 + NSTG*TC_STGB)   // 198656

#define IDESC_F16_128x256 ((1u<<4) | (32u<<17) | (8u<<24))

#if TC_PATH
static __device__ __forceinline__ uint64_t make_desc(uint32_t addr) {
    const uint64_t base =
        (uint64_t(2)  << 61) | (uint64_t(1) << 46) | (uint64_t(64) << 32) | (uint64_t(1) << 16);
    return base | ((uint64_t)(addr >> 4) & 0x3FFF);
}
__device__ __forceinline__ void mma_f16_ss(uint32_t d_tmem, uint64_t adesc, uint64_t bdesc,
                                           uint32_t idesc, bool accum) {
    uint32_t en = accum ? 1u : 0u;
    asm volatile(
        "{\n\t"
        ".reg .pred p;\n\t"
        "setp.ne.u32 p, %5, 0;\n\t"
        "tcgen05.mma.cta_group::1.kind::f16 [%0], %1, %2, %3, {%4, %4, %4, %4}, p;\n\t"
        "}"
        :: "r"(d_tmem), "l"(adesc), "l"(bdesc), "r"(idesc), "r"(0u), "r"(en)
        : "memory");
}
#define TC_LD32(r, addr) \
    asm volatile( \
        "tcgen05.ld.sync.aligned.32x32b.x32.b32 " \
        "{%0, %1, %2, %3, %4, %5, %6, %7, " \
        " %8, %9, %10, %11, %12, %13, %14, %15, " \
        " %16, %17, %18, %19, %20, %21, %22, %23, " \
        " %24, %25, %26, %27, %28, %29, %30, %31}, [%32];" \
        : "=r"((r)[0]),  "=r"((r)[1]),  "=r"((r)[2]),  "=r"((r)[3]), \
          "=r"((r)[4]),  "=r"((r)[5]),  "=r"((r)[6]),  "=r"((r)[7]), \
          "=r"((r)[8]),  "=r"((r)[9]),  "=r"((r)[10]), "=r"((r)[11]), \
          "=r"((r)[12]), "=r"((r)[13]), "=r"((r)[14]), "=r"((r)[15]), \
          "=r"((r)[16]), "=r"((r)[17]), "=r"((r)[18]), "=r"((r)[19]), \
          "=r"((r)[20]), "=r"((r)[21]), "=r"((r)[22]), "=r"((r)[23]), \
          "=r"((r)[24]), "=r"((r)[25]), "=r"((r)[26]), "=r"((r)[27]), \
          "=r"((r)[28]), "=r"((r)[29]), "=r"((r)[30]), "=r"((r)[31]) \
        : "r"(addr))
#endif

template<int PHASE>
__global__ void __launch_bounds__(256, 1) gemm_tc5(
    const __grid_constant__ CUtensorMap tmAe,
    const __grid_constant__ CUtensorMap tmAf,
    const __grid_constant__ CUtensorMap tmBe,
    const __grid_constant__ CUtensorMap tmBf,
    const float* __restrict__ bias_e,
    const float* __restrict__ bias_f) {
#if TC_PATH
    constexpr bool G1 = (PHASE == 1);
    constexpr int N = G1 ? II : DD;
    constexpr int KT = (G1 ? DD : II) / BKH;

    const int z = blockIdx.z;
    const bool FB = (z == EE);
    const int count = FB ? g_fbcount : g_counts[z];
    const int m0 = blockIdx.y * TCBM;
    if (m0 >= count) return;
    const int n0 = blockIdx.x * TCBN;

    const CUtensorMap* tmA = FB ? &tmAf : &tmAe;
    const CUtensorMap* tmB = FB ? &tmBf : &tmBe;
    const int rowA = FB ? m0 : z*CAPACITY + m0;
    const int rowB = FB ? n0 : z*N + n0;
    const float* biasp = FB ? bias_f : bias_e + (size_t)z*N;

    extern __shared__ char smem[];
    const uint32_t sb = smem_u32(smem);
    const int tid = threadIdx.x, lane = tid & 31, wid = tid >> 5;

    const uint32_t mb_full0 = sb + 64, mb_empty0 = sb + 96, mb_done = sb + 120;
    float* bias_sm = reinterpret_cast<float*>(smem + 1024);   // 256 floats
    if (tid == 0) {
        #pragma unroll
        for (int s = 0; s < NSTG; s++) {
            mbar_init(mb_full0 + 8*s, 1);    // completed via expect_tx + TMA complete_tx
            mbar_init(mb_empty0 + 8*s, 1);   // armed by tcgen05.commit
        }
        mbar_init(mb_done, 1);
    }
    bias_sm[tid] = biasp[n0 + tid];
    if (wid == 0) {
        asm volatile("tcgen05.alloc.cta_group::1.sync.aligned.shared::cta.b32 [%0], %1;"
                     :: "r"(sb), "r"(512) : "memory");
    }
    __syncthreads();
    uint32_t tb;
    asm volatile("ld.shared.b32 %0, [%1];" : "=r"(tb) : "r"(sb));

    if (wid == 0 && lane == 0) {
        // MMA issuer
        uint64_t ad0[NSTG], ad1[NSTG], bd[NSTG];
        #pragma unroll
        for (int s = 0; s < NSTG; s++) {
            uint32_t base = sb + SM_TILE0 + s*TC_STGB;
            ad0[s] = make_desc(base);
            ad1[s] = make_desc(base + 16384);
            bd[s]  = make_desc(base + TC_A2);
        }
        #pragma unroll 1
        for (int kt = 0; kt < KT; kt++) {
            int st = kt % NSTG;
            uint32_t ph = (kt / NSTG) & 1;
            mbar_wait(mb_full0 + 8*st, ph);
            asm volatile("tcgen05.fence::after_thread_sync;" ::: "memory");
            #pragma unroll
            for (int k = 0; k < 4; k++) {
                bool acc = (kt > 0) || (k > 0);
                mma_f16_ss(tb,       ad0[st] + k*2, bd[st] + k*2, IDESC_F16_128x256, acc);
                mma_f16_ss(tb + 256, ad1[st] + k*2, bd[st] + k*2, IDESC_F16_128x256, acc);
            }
            asm volatile("tcgen05.commit.cta_group::1.mbarrier::arrive::one.shared::cluster.b64 [%0];"
                         :: "r"(mb_empty0 + 8*st) : "memory");
        }
        asm volatile("tcgen05.commit.cta_group::1.mbarrier::arrive::one.shared::cluster.b64 [%0];"
                     :: "r"(mb_done) : "memory");
    } else if (tid == 32) {
        // TMA producer: one thread, 2 bulk loads + expect_tx per k-chunk
        #pragma unroll 1
        for (int kt = 0; kt < KT; kt++) {
            int st = kt % NSTG;
            uint32_t eph = ((kt / NSTG) & 1) ^ 1u;
            mbar_wait(mb_empty0 + 8*st, eph);
            uint32_t stgB = sb + SM_TILE0 + st*TC_STGB;
            uint32_t fullb = mb_full0 + 8*st;
            mbar_expect_tx(fullb, (uint32_t)TC_STGB);
            tma2d(stgB,         tmA, kt*BKH, rowA, fullb);
            tma2d(stgB + TC_A2, tmB, kt*BKH, rowB, fullb);
        }
    }

    mbar_wait(mb_done, 0);
    asm volatile("tcgen05.fence::after_thread_sync;" ::: "memory");

    // epilogue: warps 0-3 -> m-tile 0 (TMEM cols 0-255), warps 4-7 -> m-tile 1 (256-511)
    {
        const int mtile = wid >> 2;
        const int lw = wid & 3;
        const int row = m0 + mtile*128 + lw*32 + lane;
        const uint32_t coff = (uint32_t)mtile * 256;
        __half* outp;
        if constexpr (G1)
            outp = (FB ? g_Hfb : g_H + (size_t)z*CAPACITY*II) + (size_t)row * II;
        else
            outp = (FB ? g_Yfbh : g_Yeh + (size_t)z*CAPACITY*DD) + (size_t)row * DD;
        uint32_t ra[32], rb[32];
        #pragma unroll 1
        for (int cc = 0; cc < 4; cc++) {
            TC_LD32(ra, tb + coff + (2*cc)*32);
            TC_LD32(rb, tb + coff + (2*cc+1)*32);
            asm volatile("tcgen05.wait::ld.sync.aligned;" ::: "memory");
            #pragma unroll
            for (int half = 0; half < 2; half++) {
                const uint32_t* r = half ? rb : ra;
                int cl = (2*cc + half)*32;
                union { __half2 h[16]; uint4 u[4]; } o;
                #pragma unroll
                for (int j = 0; j < 16; j++) {
                    float v0 = __uint_as_float(r[2*j])   + bias_sm[cl + 2*j];
                    float v1 = __uint_as_float(r[2*j+1]) + bias_sm[cl + 2*j + 1];
                    if constexpr (G1) { v0 = gelu_exact(v0); v1 = gelu_exact(v1); }
                    o.h[j] = __floats2half2_rn(v0, v1);
                }
                uint4* dst = reinterpret_cast<uint4*>(outp + n0 + cl);
                dst[0] = o.u[0]; dst[1] = o.u[1]; dst[2] = o.u[2]; dst[3] = o.u[3];
            }
        }
    }
    __syncthreads();
    if (wid == 0) {
        asm volatile("tcgen05.relinquish_alloc_permit.cta_group::1.sync.aligned;");
        asm volatile("tcgen05.dealloc.cta_group::1.sync.aligned.b32 %0, %1;" :: "r"(tb), "r"(512));
    }
#endif
}

// ============================================================================
// Path B: HMMA GEMM fallback ([K,N] weights), 128x128 tiles, 3-stage
// ============================================================================
#define BM 128
#define BN 128
#define HM_STGB 32768
#define HM_SMEM (3*HM_STGB)

template<int MODE>
__global__ void gemm_hmma(const float* __restrict__ bias) {
    constexpr bool G1 = (MODE < 2);
    constexpr bool FB = (MODE & 1);
    constexpr int K = G1 ? DD : II;
    constexpr int N = G1 ? II : DD;
    constexpr int KT = K / BKH;

    const int e = blockIdx.z;
    const int count = FB ? g_fbcount : g_counts[e];
    const int m0 = blockIdx.y * BM;
    if (m0 >= count) return;
    const int n0 = blockIdx.x * BN;

    const __half* __restrict__ Aexp;
    const __half* __restrict__ Bexp;
    if constexpr (MODE == 0) { Aexp = g_Xg  + (size_t)e*CAPACITY*K; Bexp = g_W1f + (size_t)e*K*II; }
    if constexpr (MODE == 1) { Aexp = g_Xfb;                        Bexp = g_fw1f; }
    if constexpr (MODE == 2) { Aexp = g_H   + (size_t)e*CAPACITY*K; Bexp = g_W2f + (size_t)e*K*DD; }
    if constexpr (MODE == 3) { Aexp = g_Hfb;                        Bexp = g_fw2f; }
    const float* biasp = bias + (FB ? 0 : (size_t)e*N);

    extern __shared__ __half smemh[];
    const uint32_t sbase = smem_u32(smemh);
    const int tid = threadIdx.x, lane = tid & 31, wid = tid >> 5;
    const int wm = wid & 1, wn = wid >> 1;
    const int g = lane >> 3, rin = lane & 7;

    float acc[4][4][4];
    #pragma unroll
    for (int a = 0; a < 4; a++)
        #pragma unroll
        for (int b = 0; b < 4; b++)
            #pragma unroll
            for (int c = 0; c < 4; c++) acc[a][b][c] = 0.f;

    auto loadStage = [&](int kt, int st) {
        if (kt < KT) {
            uint32_t aB = sbase + st * HM_STGB;
            uint32_t bB = aB + 16384;
            #pragma unroll
            for (int j = 0; j < 4; j++) {
                int id = j * 256 + tid;
                int r = id >> 3, c = id & 7;
                const __half* src = Aexp + (size_t)(m0 + r) * K + kt * BKH + c * 8;
                uint32_t dst = aB + (uint32_t)(r * 64 + ((c ^ (r & 7)) << 3)) * 2;
                cpasync16(dst, src);
            }
            #pragma unroll
            for (int j = 0; j < 4; j++) {
                int id = j * 256 + tid;
                int r = id >> 4, c = id & 15;
                const __half* src = Bexp + (size_t)(kt * BKH + r) * N + n0 + c * 8;
                uint32_t dst = bB + (uint32_t)(r * 128 + (((c & 8) | ((c ^ r) & 7)) << 3)) * 2;
                cpasync16(dst, src);
            }
        }
        cpasync_commit();
    };

    loadStage(0, 0);
    loadStage(1, 1);
    int st = 0;
    #pragma unroll 1
    for (int kt = 0; kt < KT; kt++) {
        cpasync_wait1();
        __syncthreads();
        loadStage(kt + 2, (st + 2) % 3);
        uint32_t aB = sbase + st * HM_STGB;
        uint32_t bB = aB + 16384;
        #pragma unroll
        for (int ks = 0; ks < 4; ks++) {
            uint32_t afr[4][4];
            #pragma unroll
            for (int mt = 0; mt < 4; mt++) {
                int row = wm * 64 + mt * 16 + (g & 1) * 8 + rin;
                int ch = (ks * 2 + (g >> 1)) ^ rin;
                ldmatrix_x4(afr[mt], aB + (uint32_t)(row * 64 + ch * 8) * 2);
            }
            uint32_t bfr[4][2];
            #pragma unroll
            for (int ht = 0; ht < 2; ht++) {
                int row = ks * 16 + (g & 1) * 8 + rin;
                int c = wn * 4 + ht * 2 + (g >> 1);
                int ph = (c & 8) | ((c & 7) ^ rin);
                uint32_t r4[4];
                ldmatrix_x4_trans(r4, bB + (uint32_t)(row * 128 + ph * 8) * 2);
                bfr[ht*2][0] = r4[0]; bfr[ht*2][1] = r4[1];
                bfr[ht*2+1][0] = r4[2]; bfr[ht*2+1][1] = r4[3];
            }
            #pragma unroll
            for (int mt = 0; mt < 4; mt++)
                #pragma unroll
                for (int nt = 0; nt < 4; nt++)
                    mma16816(acc[mt][nt], afr[mt], bfr[nt]);
        }
        st = (st + 1) % 3;
    }

    const int growb = m0 + wm * 64;
    const int gcolb = n0 + wn * 32;
    #pragma unroll
    for (int mt = 0; mt < 4; mt++) {
        #pragma unroll
        for (int nt = 0; nt < 4; nt++) {
            int r0 = growb + mt * 16 + (lane >> 2);
            int c0 = gcolb + nt * 8 + (lane & 3) * 2;
            float b0f = biasp[c0], b1f = biasp[c0 + 1];
            float x0 = acc[mt][nt][0] + b0f, x1 = acc[mt][nt][1] + b1f;
            float x2 = acc[mt][nt][2] + b0f, x3 = acc[mt][nt][3] + b1f;
            if constexpr (G1) {
                __half* Hout = FB ? g_Hfb : (g_H + (size_t)e*CAPACITY*N);
                *reinterpret_cast<__half2*>(Hout + (size_t)r0 * N + c0) =
                    __floats2half2_rn(gelu_exact(x0), gelu_exact(x1));
                *reinterpret_cast<__half2*>(Hout + (size_t)(r0 + 8) * N + c0) =
                    __floats2half2_rn(gelu_exact(x2), gelu_exact(x3));
            } else {
                __half* Yout = FB ? g_Yfbh : (g_Yeh + (size_t)e*CAPACITY*N);
                *reinterpret_cast<__half2*>(Yout + (size_t)r0 * N + c0) =
                    __floats2half2_rn(x0, x1);
                *reinterpret_cast<__half2*>(Yout + (size_t)(r0 + 8) * N + c0) =
                    __floats2half2_rn(x2, x3);
            }
        }
    }
}

// ---------------- final combine (fp16 expert outputs) ----------------
__global__ void combine_kernel(float* __restrict__ out) {
    int t = blockIdx.x;
    int i = threadIdx.x;
    float4* o = reinterpret_cast<float4*>(out + (size_t)t * DD);
    if (g_fbflag[t]) {
        const uint2 hv = reinterpret_cast<const uint2*>(g_Yfbh + (size_t)g_fbslot[t] * DD)[i];
        float2 a0 = __half22float2(*reinterpret_cast<const __half2*>(&hv.x));
        float2 a1 = __half22float2(*reinterpret_cast<const __half2*>(&hv.y));
        float4 v; v.x = a0.x; v.y = a0.y; v.z = a1.x; v.w = a1.y;
        o[i] = v;
    } else {
        int e0 = g_top2e[2*t], e1 = g_top2e[2*t+1];
        float w0 = g_top2w[2*t], w1 = g_top2w[2*t+1];
        size_t r0 = (size_t)(e0 * CAPACITY + g_slot[2*t]) * DD;
        size_t r1 = (size_t)(e1 * CAPACITY + g_slot[2*t+1]) * DD;
        uint2 av = reinterpret_cast<const uint2*>(g_Yeh + r0)[i];
        uint2 bv = reinterpret_cast<const uint2*>(g_Yeh + r1)[i];
        float2 a0 = __half22float2(*reinterpret_cast<const __half2*>(&av.x));
        float2 a1 = __half22float2(*reinterpret_cast<const __half2*>(&av.y));
        float2 b0 = __half22float2(*reinterpret_cast<const __half2*>(&bv.x));
        float2 b1 = __half22float2(*reinterpret_cast<const __half2*>(&bv.y));
        float4 v;
        v.x = w0 * a0.x + w1 * b0.x;
        v.y = w0 * a0.y + w1 * b0.y;
        v.z = w0 * a1.x + w1 * b1.x;
        v.w = w0 * a1.y + w1 * b1.y;
        o[i] = v;
    }
}

// ---------------- host: tensormap encode via driver entry point ----------------
typedef CUresult (*PFN_tmEncode)(CUtensorMap*, CUtensorMapDataType, cuuint32_t, void*,
                                 const cuuint64_t*, const cuuint64_t*, const cuuint32_t*,
                                 const cuuint32_t*, CUtensorMapInterleave, CUtensorMapSwizzle,
                                 CUtensorMapL2promotion, CUtensorMapFloatOOBfill);

static bool encode_tm2d(PFN_tmEncode enc, CUtensorMap* tm, void* ptr,
                        uint64_t inner, uint64_t rows) {
    cuuint64_t dims[2]    = {inner, rows};
    cuuint64_t strides[1] = {inner * 2};   // fp16 row pitch in bytes
    cuuint32_t box[2]     = {64, 256};     // 128B x 256 rows
    cuuint32_t es[2]      = {1, 1};
    CUresult r = enc(tm, CU_TENSOR_MAP_DATA_TYPE_FLOAT16, 2, ptr, dims, strides, box, es,
                     CU_TENSOR_MAP_INTERLEAVE_NONE, CU_TENSOR_MAP_SWIZZLE_128B,
                     CU_TENSOR_MAP_L2_PROMOTION_L2_128B, CU_TENSOR_MAP_FLOAT_OOB_FILL_NONE);
    return r == CUDA_SUCCESS;
}

// ---------------- launch ----------------
extern "C" void kernel_launch(void* const* d_in, const int* in_sizes, int n_in,
                              void* d_out, int out_size) {
    const float* x   = (const float*)d_in[0];
    const float* Wr  = (const float*)d_in[1];
    const float* W1  = (const float*)d_in[2];
    const float* b1  = (const float*)d_in[3];
    const float* W2  = (const float*)d_in[4];
    const float* b2  = (const float*)d_in[5];
    const float* fw1 = (const float*)d_in[6];
    const float* fb1 = (const float*)d_in[7];
    const float* fw2 = (const float*)d_in[8];
    const float* fb2 = (const float*)d_in[9];
    float* out = (float*)d_out;

    __half *dW1, *dW2, *dfw1, *dfw2, *dXg, *dXfb, *dH, *dHfb;
    cudaGetSymbolAddress((void**)&dW1,  g_W1f);
    cudaGetSymbolAddress((void**)&dW2,  g_W2f);
    cudaGetSymbolAddress((void**)&dfw1, g_fw1f);
    cudaGetSymbolAddress((void**)&dfw2, g_fw2f);
    cudaGetSymbolAddress((void**)&dXg,  g_Xg);
    cudaGetSymbolAddress((void**)&dXfb, g_Xfb);
    cudaGetSymbolAddress((void**)&dH,   g_H);
    cudaGetSymbolAddress((void**)&dHfb, g_Hfb);

    // TC-path probe: real body => many regs; generic pass => empty body
    cudaFuncAttributes fa{};
    cudaFuncGetAttributes(&fa, (const void*)gemm_tc5<1>);
    bool use_tc = (fa.numRegs >= 24);

    // tensormap encode (driver entry point via runtime; no -lcuda link needed)
    CUtensorMap tmXg{}, tmXfb{}, tmW1{}, tmFw1{}, tmH{}, tmHfb{}, tmW2{}, tmFw2{};
    if (use_tc) {
        void* fn = nullptr;
        cudaDriverEntryPointQueryResult qr;
        cudaGetDriverEntryPoint("cuTensorMapEncodeTiled", &fn, cudaEnableDefault, &qr);
        if (fn == nullptr) {
            use_tc = false;
        } else {
            PFN_tmEncode enc = (PFN_tmEncode)fn;
            bool ok = true;
            ok &= encode_tm2d(enc, &tmXg,  dXg,  DD, RR);
            ok &= encode_tm2d(enc, &tmXfb, dXfb, DD, TT);
            ok &= encode_tm2d(enc, &tmW1,  dW1,  DD, (uint64_t)II*EE);
            ok &= encode_tm2d(enc, &tmFw1, dfw1, DD, II);
            ok &= encode_tm2d(enc, &tmH,   dH,   II, RR);
            ok &= encode_tm2d(enc, &tmHfb, dHfb, II, TT);
            ok &= encode_tm2d(enc, &tmW2,  dW2,  II, (uint64_t)DD*EE);
            ok &= encode_tm2d(enc, &tmFw2, dfw2, II, DD);
            if (!ok) use_tc = false;
        }
    }

    if (use_tc) {
        cudaFuncSetAttribute(gemm_tc5<1>, cudaFuncAttributeMaxDynamicSharedMemorySize, TC_SMEM);
        cudaFuncSetAttribute(gemm_tc5<2>, cudaFuncAttributeMaxDynamicSharedMemorySize, TC_SMEM);
        router_kernel<<<TT/8, 256>>>(x, Wr);                               // 0
        assign_kernel<<<1, 1024>>>();                                      // 1
        megaprep<<<MP_TOTAL, 256>>>(x, W1, W2, fw1, fw2);                  // 2
        gemm_tc5<1><<<dim3(II/TCBN, TT/TCBM, EE+1), 256, TC_SMEM>>>(
            tmXg, tmXfb, tmW1, tmFw1, b1, fb1);                            // 3 <- profiled
        gemm_tc5<2><<<dim3(DD/TCBN, TT/TCBM, EE+1), 256, TC_SMEM>>>(
            tmH, tmHfb, tmW2, tmFw2, b2, fb2);                             // 4
        combine_kernel<<<TT, 256>>>(out);                                  // 5
    } else {
        cudaFuncSetAttribute(gemm_hmma<0>, cudaFuncAttributeMaxDynamicSharedMemorySize, HM_SMEM);
        cudaFuncSetAttribute(gemm_hmma<1>, cudaFuncAttributeMaxDynamicSharedMemorySize, HM_SMEM);
        cudaFuncSetAttribute(gemm_hmma<2>, cudaFuncAttributeMaxDynamicSharedMemorySize, HM_SMEM);
        cudaFuncSetAttribute(gemm_hmma<3>, cudaFuncAttributeMaxDynamicSharedMemorySize, HM_SMEM);
        router_kernel<<<TT/8, 256>>>(x, Wr);
        convert_kernel<<<(EE*DD*II/8 + 255)/256, 256>>>(W1, dW1, EE*DD*II/8);
        convert_kernel<<<(EE*II*DD/8 + 255)/256, 256>>>(W2, dW2, EE*II*DD/8);
        assign_kernel<<<1, 1024>>>();
        gather_all<<<RR + TT, 256>>>(x);
        gemm_hmma<0><<<dim3(II/BN, CAPACITY/BM, EE), 256, HM_SMEM>>>(b1);
        gemm_hmma<2><<<dim3(DD/BN, CAPACITY/BM, EE), 256, HM_SMEM>>>(b2);
        convert_kernel<<<(DD*II/8 + 255)/256, 256>>>(fw1, dfw1, DD*II/8);
        gemm_hmma<1><<<dim3(II/BN, TT/BM, 1), 256, HM_SMEM>>>(fb1);
        convert_kernel<<<(II*DD/8 + 255)/256, 256>>>(fw2, dfw2, II*DD/8);
        gemm_hmma<3><<<dim3(DD/BN, TT/BM, 1), 256, HM_SMEM>>>(fb2);
    }

    combine_kernel<<<TT, 256>>>(out);
}